// round 6
// baseline (speedup 1.0000x reference)
#include <cuda_runtime.h>
#include <math.h>

#define MINN  1e-15f
#define PMAX  0.996f      // (1 - 4e-3)/sqrt(c), c=1
#define SLOPE 0.01f

constexpr int NMAX = 100000;
constexpr int EMAX = 800000;
constexpr int WPB  = 8;          // warps per block
constexpr int TPB  = WPB * 32;   // 256 threads

// ---------------- scratch (static device globals; no allocation) ----------------
__device__ float g_xcat[NMAX * 128];
__device__ float g_xt  [NMAX * 128];
__device__ float g_x2  [NMAX * 128];
__device__ float g_xtf [NMAX * 64];
__device__ float g_hatt[NMAX * 64];
__device__ float g_dis [NMAX];
__device__ int   g_cnt [NMAX];
__device__ int   g_cur [NMAX];
__device__ int   g_off [NMAX + 1];
__device__ int   g_bsum[128];
__device__ int   g_csr [EMAX];
__device__ float g_hb1 [128];
__device__ float g_hb2 [64];

typedef unsigned long long ull;

// ---------------- helpers ----------------
__device__ __forceinline__ float wred(float v) {
#pragma unroll
    for (int o = 16; o; o >>= 1) v += __shfl_xor_sync(0xffffffffu, v, o);
    return v;
}
// fast artanh: poly for |x|<0.25 (rel err <1e-7), MUFU log otherwise (rel err <5e-7)
__device__ __forceinline__ float artanhf_(float x) {
    x = fminf(fmaxf(x, -1.0f + 1e-7f), 1.0f - 1e-7f);
    float x2 = x * x;
    float ser = x * (1.0f + x2 * (0.33333334f + x2 * (0.2f + x2 * (0.14285715f + x2 * 0.11111111f))));
    float lg  = 0.5f * __logf(__fdividef(1.0f + x, 1.0f - x));
    return (x2 < 0.0625f) ? ser : lg;
}
// fast tanh via MUFU ex2 (~1e-6 rel)
__device__ __forceinline__ float tfast(float x) {
    float ax = fabsf(x);
    float t = __expf(-2.0f * ax);
    float r = __fdividef(1.0f - t, 1.0f + t);
    return copysignf(r, x);
}
__device__ __forceinline__ float sigf(float x) {
    return __fdividef(1.0f, 1.0f + __expf(-x));
}
// packed f32x2 ops (sm_103a FFMA2 path)
__device__ __forceinline__ ull fdup(float v) {
    ull d; asm("mov.b64 %0, {%1, %1};" : "=l"(d) : "f"(v)); return d;
}
__device__ __forceinline__ void ffma2(ull& d, ull a, ull b) {
    asm("fma.rn.f32x2 %0, %1, %2, %0;" : "+l"(d) : "l"(a), "l"(b));
}
__device__ __forceinline__ float2 funpack(ull d) {
    float2 r; asm("mov.b64 {%0, %1}, %2;" : "=f"(r.x), "=f"(r.y) : "l"(d)); return r;
}

// ---------------- hyperbolic bias precompute ----------------
__device__ __forceinline__ float blk_red128(float v, float* sh) {
    int t = threadIdx.x;
    sh[t] = v; __syncthreads();
    for (int s = 64; s > 0; s >>= 1) { if (t < s) sh[t] += sh[t + s]; __syncthreads(); }
    float r = sh[0]; __syncthreads();
    return r;
}

__global__ void k_bias(const float* __restrict__ b1, const float* __restrict__ b2) {
    __shared__ float sh[128];
    int t = threadIdx.x;
    float v = b1[t];
    float n2 = blk_red128(v * v, sh);
    float nn = fmaxf(sqrtf(n2), MINN);
    float u = tanhf(nn) / nn * v;
    float pu2 = blk_red128(u * u, sh);
    float pn = fmaxf(sqrtf(pu2), MINN);
    if (pn > PMAX) u *= PMAX / pn;
    g_hb1[t] = u;
    float v2 = (t < 64) ? b2[t] : 0.f;
    float m2 = blk_red128(v2 * v2, sh);
    float mn = fmaxf(sqrtf(m2), MINN);
    float u2 = tanhf(mn) / mn * v2;
    float q2 = blk_red128(u2 * u2, sh);
    float qn = fmaxf(sqrtf(q2), MINN);
    if (qn > PMAX) u2 *= PMAX / qn;
    if (t < 64) g_hb2[t] = u2;
}

// ---------------- init: x = feat@Wl.T + bl ; expmap0 ; proj ; concat hidden ; proj ----------------
// k-paired FFMA2, M=8 node blocking, no x duplication.
// wq[k2][lane] = float4{W[j,2k2], W[j,2k2+1], W[j+32,2k2], W[j+32,2k2+1]}, j=lane
__global__ __launch_bounds__(TPB) void k_init2(const float* __restrict__ feat, const float* __restrict__ Wl,
                                               const float* __restrict__ bl, const float* __restrict__ hidlast, int n) {
    extern __shared__ unsigned char smraw[];
    ulonglong2* wq2 = (ulonglong2*)smraw;                            // 64*32 entries, 32KB
    float4* sxf4 = (float4*)(smraw + 64 * 32 * 16);                  // WPB*8*32 float4, 32KB
    float* shb = (float*)(smraw + 64 * 32 * 16 + WPB * 8 * 32 * 16); // 64
    int t = threadIdx.x;
    for (int idx = t; idx < 64 * 32; idx += TPB) {
        int k2 = idx >> 5, j = idx & 31;
        float4 v;
        v.x = Wl[j * 128 + 2 * k2];
        v.y = Wl[j * 128 + 2 * k2 + 1];
        v.z = Wl[(j + 32) * 128 + 2 * k2];
        v.w = Wl[(j + 32) * 128 + 2 * k2 + 1];
        ((float4*)wq2)[idx] = v;
    }
    if (t < 64) shb[t] = bl[t];
    __syncthreads();
    int warp = t >> 5, lane = t & 31;
    float4* sxw = sxf4 + warp * 256;                    // 8 nodes * 32 float4
    const ulonglong2* sxu2 = (const ulonglong2*)sxw;    // [m*32 + k4]
    int ngrp = (n + 7) >> 3;
    for (int grp = blockIdx.x * WPB + warp; grp < ngrp; grp += gridDim.x * WPB) {
        int base = grp * 8;
#pragma unroll
        for (int m = 0; m < 8; m++) {
            int nm = min(base + m, n - 1);
            sxw[m * 32 + lane] = ((const float4*)feat)[nm * 32 + lane];
        }
        __syncwarp();
        ull accA[8], accB[8];
#pragma unroll
        for (int m = 0; m < 8; m++) { accA[m] = 0ull; accB[m] = 0ull; }
#pragma unroll 2
        for (int k4 = 0; k4 < 32; k4++) {
            ulonglong2 wwa = wq2[(2 * k4) * 32 + lane];
            ulonglong2 wwb = wq2[(2 * k4 + 1) * 32 + lane];
#pragma unroll
            for (int m = 0; m < 8; m++) {
                ulonglong2 xp = sxu2[m * 32 + k4];      // broadcast: (x[4k4],x[4k4+1]),(x[4k4+2],x[4k4+3])
                ffma2(accA[m], wwa.x, xp.x);
                ffma2(accB[m], wwa.y, xp.x);
                ffma2(accA[m], wwb.x, xp.y);
                ffma2(accB[m], wwb.y, xp.y);
            }
        }
#pragma unroll
        for (int m = 0; m < 8; m++) {
            int nm = base + m;
            float2 fa = funpack(accA[m]);
            float2 fb = funpack(accB[m]);
            float a0 = fa.x + fa.y + shb[lane];
            float a1 = fb.x + fb.y + shb[lane + 32];
            // expmap0
            float s = wred(a0 * a0 + a1 * a1);
            float nn = fmaxf(sqrtf(s), MINN);
            float sc = tfast(nn) / nn; a0 *= sc; a1 *= sc;
            // proj (64-dim)
            s = wred(a0 * a0 + a1 * a1);
            nn = fmaxf(sqrtf(s), MINN);
            if (nn > PMAX) { sc = PMAX / nn; a0 *= sc; a1 *= sc; }
            // concat hidden, proj over 128 dims
            int nmc = min(nm, n - 1);
            float h0 = hidlast[nmc * 64 + lane];
            float h1 = hidlast[nmc * 64 + lane + 32];
            s = wred(a0 * a0 + a1 * a1 + h0 * h0 + h1 * h1);
            nn = fmaxf(sqrtf(s), MINN);
            if (nn > PMAX) { sc = PMAX / nn; a0 *= sc; a1 *= sc; h0 *= sc; h1 *= sc; }
            if (nm < n) {
                g_xcat[nm * 128 + lane]      = a0;
                g_xcat[nm * 128 + lane + 32] = a1;
                g_xcat[nm * 128 + lane + 64] = h0;
                g_xcat[nm * 128 + lane + 96] = h1;
            }
        }
        __syncwarp();
    }
}

// ---------------- CSR build ----------------
__global__ void k_zero2(int n) {
    int i = blockIdx.x * blockDim.x + threadIdx.x;
    if (i < n) { g_cnt[i] = 0; g_cur[i] = 0; }
}
__global__ void k_count(const int* __restrict__ src, int e) {
    int i = blockIdx.x * blockDim.x + threadIdx.x;
    if (i < e) atomicAdd(&g_cnt[src[i]], 1);
}
__global__ void k_scan1(int n) {
    __shared__ int sh[1024];
    int t = threadIdx.x;
    int i = blockIdx.x * 1024 + t;
    int v = (i < n) ? g_cnt[i] : 0;
    sh[t] = v; __syncthreads();
    for (int d = 1; d < 1024; d <<= 1) {
        int x = (t >= d) ? sh[t - d] : 0;
        __syncthreads();
        sh[t] += x; __syncthreads();
    }
    if (i < n) g_off[i] = sh[t] - v;
    if (t == 1023) g_bsum[blockIdx.x] = sh[1023];
}
__global__ void k_scan2(int nb) {
    __shared__ int sh[128];
    int t = threadIdx.x;
    int v = (t < nb) ? g_bsum[t] : 0;
    sh[t] = v; __syncthreads();
    for (int d = 1; d < 128; d <<= 1) {
        int x = (t >= d) ? sh[t - d] : 0;
        __syncthreads();
        sh[t] += x; __syncthreads();
    }
    g_bsum[t] = sh[t] - v;
}
__global__ void k_scan3(int n, int e) {
    int i = blockIdx.x * blockDim.x + threadIdx.x;
    if (i < n) g_off[i] += g_bsum[i >> 10];
    if (i == 0) g_off[n] = e;
}
__global__ void k_dis(int n) {
    int i = blockIdx.x * blockDim.x + threadIdx.x;
    if (i < n) g_dis[i] = rsqrtf((float)(g_cnt[i] + 1));
}
__global__ void k_fill(const int* __restrict__ src, const int* __restrict__ dst, int e) {
    int i = blockIdx.x * blockDim.x + threadIdx.x;
    if (i < e) {
        int s = src[i];
        int p = g_off[s] + atomicAdd(&g_cur[s], 1);
        g_csr[p] = dst[i];
    }
}

// ---------------- hyp_linear (FFMA2 j-pairing, M=8 node blocking) ----------------
// wq[p][k2][lane] = ulonglong2{ (W[j,2k2],W[j+32,2k2]), (W[j,2k2+1],W[j+32,2k2+1]) }, j=p*64+lane
template <int P>
__global__ __launch_bounds__(TPB) void k_lin(const float* __restrict__ xin, const float* __restrict__ W,
                                             const float* __restrict__ hb, float* __restrict__ xtout, int n) {
    extern __shared__ unsigned char smraw[];
    ulonglong2* wq = (ulonglong2*)smraw;                                    // P*64*32
    float4* sxf4 = (float4*)(smraw + P * 64 * 32 * 16);                     // WPB*8*32
    float* shb = (float*)(smraw + P * 64 * 32 * 16 + WPB * 8 * 32 * 16);    // 64*P
    int t = threadIdx.x;
    for (int idx = t; idx < P * 64 * 32; idx += TPB) {
        int p = idx >> 11; int r = idx & 2047; int k2 = r >> 5; int j = r & 31;
        float4 v;
        v.x = W[(p * 64 + j) * 128 + 2 * k2];
        v.y = W[(p * 64 + j + 32) * 128 + 2 * k2];
        v.z = W[(p * 64 + j) * 128 + 2 * k2 + 1];
        v.w = W[(p * 64 + j + 32) * 128 + 2 * k2 + 1];
        ((float4*)wq)[idx] = v;
    }
    for (int idx = t; idx < 64 * P; idx += TPB) shb[idx] = hb[idx];
    __syncthreads();
    int warp = t >> 5, lane = t & 31;
    float4* sxw = sxf4 + warp * 256;
    constexpr int VO = 2 * P;
    int ngrp = (n + 7) >> 3;
    for (int grp = blockIdx.x * WPB + warp; grp < ngrp; grp += gridDim.x * WPB) {
        int base = grp * 8;
        float xn[8];
#pragma unroll
        for (int m = 0; m < 8; m++) {
            int nm = min(base + m, n - 1);
            float4 f = ((const float4*)xin)[nm * 32 + lane];
            sxw[m * 32 + lane] = f;
            float xs = f.x * f.x + f.y * f.y + f.z * f.z + f.w * f.w;
            xn[m] = fmaxf(sqrtf(wred(xs)), MINN);
        }
        __syncwarp();
        ull acc[8][P];
#pragma unroll
        for (int m = 0; m < 8; m++)
#pragma unroll
            for (int p = 0; p < P; p++) acc[m][p] = 0ull;
#pragma unroll 2
        for (int k4 = 0; k4 < 32; k4++) {
            ulonglong2 qa[P], qb[P];
#pragma unroll
            for (int p = 0; p < P; p++) {
                qa[p] = wq[p * 2048 + (2 * k4) * 32 + lane];
                qb[p] = wq[p * 2048 + (2 * k4 + 1) * 32 + lane];
            }
#pragma unroll
            for (int m = 0; m < 8; m++) {
                float4 xv = sxw[m * 32 + k4];               // broadcast
                ull d0 = fdup(xv.x), d1 = fdup(xv.y), d2 = fdup(xv.z), d3 = fdup(xv.w);
#pragma unroll
                for (int p = 0; p < P; p++) {
                    ffma2(acc[m][p], qa[p].x, d0);
                    ffma2(acc[m][p], qa[p].y, d1);
                    ffma2(acc[m][p], qb[p].x, d2);
                    ffma2(acc[m][p], qb[p].y, d3);
                }
            }
        }
#pragma unroll
        for (int m = 0; m < 8; m++) {
            int nm = base + m;
            float v[VO];
#pragma unroll
            for (int p = 0; p < P; p++) { float2 f = funpack(acc[m][p]); v[2 * p] = f.x; v[2 * p + 1] = f.y; }
            float ms = 0.f;
#pragma unroll
            for (int g = 0; g < VO; g++) ms += v[g] * v[g];
            float mxn2 = wred(ms);
            float mxn = fmaxf(sqrtf(mxn2), MINN);
            float xnn = xn[m];
            float r = tfast(mxn / xnn * artanhf_(xnn)) / mxn;
            if (mxn2 == 0.f) r = 0.f;
#pragma unroll
            for (int g = 0; g < VO; g++) v[g] *= r;
            // proj
            float s = 0.f;
#pragma unroll
            for (int g = 0; g < VO; g++) s += v[g] * v[g];
            s = wred(s);
            float pn = fmaxf(sqrtf(s), MINN);
            if (pn > PMAX) { float f = PMAX / pn;
#pragma unroll
                for (int g = 0; g < VO; g++) v[g] *= f; }
            // mobius_add(v, hb)
            float hx[VO];
            float xx = 0.f, xy = 0.f, yy = 0.f;
#pragma unroll
            for (int g = 0; g < VO; g++) {
                float hv = shb[lane + 32 * g];
                hx[g] = hv;
                xx += v[g] * v[g];
                xy += v[g] * hv;
                yy += hv * hv;
            }
            xx = wred(xx); xy = wred(xy); yy = wred(yy);
            float den = fmaxf(1.f + 2.f * xy + xx * yy, MINN);
            float ca = (1.f + 2.f * xy + yy) / den;
            float cb = (1.f - xx) / den;
#pragma unroll
            for (int g = 0; g < VO; g++) v[g] = ca * v[g] + cb * hx[g];
            // proj
            s = 0.f;
#pragma unroll
            for (int g = 0; g < VO; g++) s += v[g] * v[g];
            s = wred(s);
            pn = fmaxf(sqrtf(s), MINN);
            if (pn > PMAX) { float f = PMAX / pn;
#pragma unroll
                for (int g = 0; g < VO; g++) v[g] *= f; }
            // logmap0
            s = 0.f;
#pragma unroll
            for (int g = 0; g < VO; g++) s += v[g] * v[g];
            s = wred(s);
            pn = fmaxf(sqrtf(s), MINN);
            float a = artanhf_(pn) / pn;
            if (nm < n) {
#pragma unroll
                for (int g = 0; g < VO; g++) xtout[nm * (64 * P) + lane + 32 * g] = v[g] * a;
            }
        }
        __syncwarp();
    }
}

// ---------------- aggregation bodies ----------------
__device__ __forceinline__ float n2_4(float4 a) { return a.x * a.x + a.y * a.y + a.z * a.z + a.w * a.w; }
__device__ __forceinline__ void  mul4(float4& a, float s) { a.x *= s; a.y *= s; a.z *= s; a.w *= s; }

__device__ __forceinline__ void agg128_body(const float* __restrict__ xt, float* __restrict__ out,
                                            int n, int vb, int vgrid) {
    int t = threadIdx.x, warp = t >> 5, lane = t & 31;
    const float4* base = (const float4*)xt;
    for (int node = vb * WPB + warp; node < n; node += vgrid * WPB) {
        float dn = g_dis[node];
        float4 a = base[node * 32 + lane];
        mul4(a, dn * dn);
        int e1 = g_off[node + 1];
        for (int e = g_off[node]; e < e1; e++) {
            int c = g_csr[e];
            float w = dn * g_dis[c];
            float4 v = base[c * 32 + lane];
            a.x += w * v.x; a.y += w * v.y; a.z += w * v.z; a.w += w * v.w;
        }
        float s, nn, sc;
        s = wred(n2_4(a)); nn = fmaxf(sqrtf(s), MINN); sc = tfast(nn) / nn; mul4(a, sc);
        s = wred(n2_4(a)); nn = fmaxf(sqrtf(s), MINN); if (nn > PMAX) mul4(a, PMAX / nn);
        s = wred(n2_4(a)); nn = fmaxf(sqrtf(s), MINN); sc = artanhf_(nn) / nn; mul4(a, sc);
        a.x = (a.x >= 0.f) ? a.x : SLOPE * a.x;
        a.y = (a.y >= 0.f) ? a.y : SLOPE * a.y;
        a.z = (a.z >= 0.f) ? a.z : SLOPE * a.z;
        a.w = (a.w >= 0.f) ? a.w : SLOPE * a.w;
        s = wred(n2_4(a)); nn = fmaxf(sqrtf(s), MINN); sc = tfast(nn) / nn; mul4(a, sc);
        s = wred(n2_4(a)); nn = fmaxf(sqrtf(s), MINN); if (nn > PMAX) mul4(a, PMAX / nn);
        s = wred(n2_4(a)); nn = fmaxf(sqrtf(s), MINN); if (nn > PMAX) mul4(a, PMAX / nn);
        ((float4*)out)[node * 32 + lane] = a;
    }
}

__device__ __forceinline__ void att5_body(unsigned char* smraw,
                                          const float* __restrict__ hiddens, const float* __restrict__ Q,
                                          const float* __restrict__ ratt, int n, int vb, int vgrid) {
    ulonglong2* wq = (ulonglong2*)smraw;             // 1024 entries, 16KB
    ull* sxs = (ull*)(smraw + 16384);                // WPB*5*64, 20KB
    float* shr = (float*)(smraw + 36864);            // 64
    int t = threadIdx.x;
    for (int idx = t; idx < 32 * 32; idx += TPB) {
        int k2 = idx >> 5, j = idx & 31;
        float4 v;
        v.x = Q[(2 * k2) * 64 + j];
        v.y = Q[(2 * k2) * 64 + j + 32];
        v.z = Q[(2 * k2 + 1) * 64 + j];
        v.w = Q[(2 * k2 + 1) * 64 + j + 32];
        ((float4*)wq)[idx] = v;
    }
    if (t < 64) shr[t] = ratt[t];
    __syncthreads();
    int warp = t >> 5, lane = t & 31;
    ull* sxw = sxs + warp * 5 * 64;
    const ulonglong2* sxu = (const ulonglong2*)sxw;
    const float inv5 = 0.2f;
    for (int node = vb * WPB + warp; node < n; node += vgrid * WPB) {
        float hl0[5], hl1[5], ew[5];
#pragma unroll
        for (int w = 0; w < 5; w++) {
            size_t off = ((size_t)w * n + node) * 64;
            float v0 = hiddens[off + lane];
            float v1 = hiddens[off + lane + 32];
            float s = wred(v0 * v0 + v1 * v1);
            float pn = fmaxf(sqrtf(s), MINN);
            float sc = artanhf_(pn) / pn;
            v0 *= sc; v1 *= sc;
            hl0[w] = v0; hl1[w] = v1;
            sxw[w * 64 + lane] = fdup(v0);
            sxw[w * 64 + lane + 32] = fdup(v1);
        }
        __syncwarp();
        ull acc[5] = {0ull, 0ull, 0ull, 0ull, 0ull};
#pragma unroll 4
        for (int k2 = 0; k2 < 32; k2++) {
            ulonglong2 q = wq[k2 * 32 + lane];
#pragma unroll
            for (int w = 0; w < 5; w++) {
                ulonglong2 xd = sxu[w * 32 + k2];
                ffma2(acc[w], q.x, xd.x);
                ffma2(acc[w], q.y, xd.y);
            }
        }
#pragma unroll
        for (int w = 0; w < 5; w++) {
            float2 f = funpack(acc[w]);
            float ep = tfast(f.x) * shr[lane] + tfast(f.y) * shr[lane + 32];
            ew[w] = wred(ep);
        }
        float m = -1e30f;
#pragma unroll
        for (int w = 0; w < 5; w++) m = fmaxf(m, ew[w]);
        float ssum = 0.f;
#pragma unroll
        for (int w = 0; w < 5; w++) { ew[w] = __expf(ew[w] - m); ssum += ew[w]; }
        float inv = inv5 / ssum;
        float o0 = 0.f, o1 = 0.f;
#pragma unroll
        for (int w = 0; w < 5; w++) { o0 += ew[w] * hl0[w]; o1 += ew[w] * hl1[w]; }
        g_hatt[node * 64 + lane]      = o0 * inv;
        g_hatt[node * 64 + lane + 32] = o1 * inv;
        __syncwarp();
    }
}

// fused: even blocks -> agg128, odd blocks -> att5 (WIN==5 path)
__global__ __launch_bounds__(TPB) void k_aggatt(const float* __restrict__ xt, float* __restrict__ out,
                                                const float* __restrict__ hiddens, const float* __restrict__ Q,
                                                const float* __restrict__ ratt, int n) {
    extern __shared__ unsigned char smraw[];
    int vgrid = gridDim.x >> 1;
    int vb = blockIdx.x >> 1;
    if (blockIdx.x & 1) att5_body(smraw, hiddens, Q, ratt, n, vb, vgrid);
    else                agg128_body(xt, out, n, vb, vgrid);
}

// standalone agg128 (fallback path)
__global__ void k_agg128(const float* __restrict__ xt, float* __restrict__ out, int n) {
    agg128_body(xt, out, n, blockIdx.x, gridDim.x);
}

__global__ void k_agg64(const float* __restrict__ xt, float* __restrict__ out, int n) {
    int t = threadIdx.x, warp = t >> 5, lane = t & 31;
    const float2* base = (const float2*)xt;
    for (int node = blockIdx.x * WPB + warp; node < n; node += gridDim.x * WPB) {
        float dn = g_dis[node];
        float2 a = base[node * 32 + lane];
        float ws = dn * dn;
        a.x *= ws; a.y *= ws;
        int e1 = g_off[node + 1];
        for (int e = g_off[node]; e < e1; e++) {
            int c = g_csr[e];
            float w = dn * g_dis[c];
            float2 v = base[c * 32 + lane];
            a.x += w * v.x; a.y += w * v.y;
        }
        float s, nn, sc;
        s = wred(a.x * a.x + a.y * a.y); nn = fmaxf(sqrtf(s), MINN); sc = tfast(nn) / nn; a.x *= sc; a.y *= sc;
        s = wred(a.x * a.x + a.y * a.y); nn = fmaxf(sqrtf(s), MINN); if (nn > PMAX) { sc = PMAX / nn; a.x *= sc; a.y *= sc; }
        s = wred(a.x * a.x + a.y * a.y); nn = fmaxf(sqrtf(s), MINN); sc = artanhf_(nn) / nn; a.x *= sc; a.y *= sc;
        a.x = (a.x >= 0.f) ? a.x : SLOPE * a.x;
        a.y = (a.y >= 0.f) ? a.y : SLOPE * a.y;
        s = wred(a.x * a.x + a.y * a.y); nn = fmaxf(sqrtf(s), MINN); sc = tfast(nn) / nn; a.x *= sc; a.y *= sc;
        s = wred(a.x * a.x + a.y * a.y); nn = fmaxf(sqrtf(s), MINN); if (nn > PMAX) { sc = PMAX / nn; a.x *= sc; a.y *= sc; }
        s = wred(a.x * a.x + a.y * a.y); nn = fmaxf(sqrtf(s), MINN); sc = artanhf_(nn) / nn; a.x *= sc; a.y *= sc;
        ((float2*)out)[node * 32 + lane] = a;
    }
}

// generic attention fallback (win != 5)
__global__ void k_att(const float* __restrict__ hiddens, const float* __restrict__ Q,
                      const float* __restrict__ ratt, int n, int win) {
    __shared__ float shQ[64 * 64];
    __shared__ float shr[64];
    __shared__ float shh[WPB][64];
    int t = threadIdx.x;
    for (int idx = t; idx < 64 * 64; idx += TPB) shQ[idx] = Q[idx];
    if (t < 64) shr[t] = ratt[t];
    __syncthreads();
    int warp = t >> 5, lane = t & 31;
    float invwin = 1.0f / (float)win;
    for (int node = blockIdx.x * WPB + warp; node < n; node += gridDim.x * WPB) {
        float hl0[8], hl1[8], ew[8];
        for (int w = 0; w < win; w++) {
            size_t off = ((size_t)w * n + node) * 64;
            float v0 = hiddens[off + lane];
            float v1 = hiddens[off + lane + 32];
            float s = wred(v0 * v0 + v1 * v1);
            float pn = fmaxf(sqrtf(s), MINN);
            float sc = artanhf_(pn) / pn;
            v0 *= sc; v1 *= sc;
            hl0[w] = v0; hl1[w] = v1;
            shh[warp][lane] = v0; shh[warp][lane + 32] = v1;
            __syncwarp();
            float ep = 0.f;
#pragma unroll
            for (int g = 0; g < 2; g++) {
                int j = lane + 32 * g;
                float a = 0.f;
                for (int k = 0; k < 64; k++) a += shh[warp][k] * shQ[k * 64 + j];
                ep += tfast(a) * shr[j];
            }
            ew[w] = wred(ep);
            __syncwarp();
        }
        float m = -1e30f;
        for (int w = 0; w < win; w++) m = fmaxf(m, ew[w]);
        float ssum = 0.f;
        for (int w = 0; w < win; w++) { ew[w] = __expf(ew[w] - m); ssum += ew[w]; }
        float inv = invwin / ssum;
        float o0 = 0.f, o1 = 0.f;
        for (int w = 0; w < win; w++) { o0 += ew[w] * hl0[w]; o1 += ew[w] * hl1[w]; }
        g_hatt[node * 64 + lane]      = o0 * inv;
        g_hatt[node * 64 + lane + 32] = o1 * inv;
    }
}

// ---------------- GRU (FFMA2, 8-node blocking) + final expmap0/proj ----------------
__global__ __launch_bounds__(TPB) void k_gru2(const float* __restrict__ Wih, const float* __restrict__ Whh,
                                              const float* __restrict__ bih, const float* __restrict__ bhh,
                                              float* __restrict__ outp, int n) {
    extern __shared__ unsigned char smraw[];
    ulonglong2* wqi = (ulonglong2*)smraw;                      // 3*32*32
    ulonglong2* wqh = (ulonglong2*)(smraw + 49152);            // 3*32*32
    ull* sxx = (ull*)(smraw + 98304);                          // WPB*8*64
    ull* sxh = (ull*)(smraw + 131072);                         // WPB*8*64
    float* sbi = (float*)(smraw + 163840);                     // 192
    float* sbh = (float*)(smraw + 164608);                     // 192
    int t = threadIdx.x;
    for (int idx = t; idx < 3 * 32 * 32; idx += TPB) {
        int p = idx >> 10; int r = idx & 1023; int k2 = r >> 5; int j = r & 31;
        float4 vi, vh;
        vi.x = Wih[(p * 64 + j) * 64 + 2 * k2];
        vi.y = Wih[(p * 64 + j + 32) * 64 + 2 * k2];
        vi.z = Wih[(p * 64 + j) * 64 + 2 * k2 + 1];
        vi.w = Wih[(p * 64 + j + 32) * 64 + 2 * k2 + 1];
        vh.x = Whh[(p * 64 + j) * 64 + 2 * k2];
        vh.y = Whh[(p * 64 + j + 32) * 64 + 2 * k2];
        vh.z = Whh[(p * 64 + j) * 64 + 2 * k2 + 1];
        vh.w = Whh[(p * 64 + j + 32) * 64 + 2 * k2 + 1];
        ((float4*)wqi)[idx] = vi;
        ((float4*)wqh)[idx] = vh;
    }
    if (t < 192) { sbi[t] = bih[t]; sbh[t] = bhh[t]; }
    __syncthreads();
    int warp = t >> 5, lane = t & 31;
    ull* sxxw = sxx + warp * 512;
    ull* sxhw = sxh + warp * 512;
    const ulonglong2* sxxu = (const ulonglong2*)sxxw;
    const ulonglong2* sxhu = (const ulonglong2*)sxhw;
    int ngrp = (n + 7) >> 3;
    for (int grp = blockIdx.x * WPB + warp; grp < ngrp; grp += gridDim.x * WPB) {
        int base = grp * 8;
        float h0r[8], h1r[8];
#pragma unroll
        for (int m = 0; m < 8; m++) {
            int nm = min(base + m, n - 1);
            float x0 = g_xtf[nm * 64 + lane], x1 = g_xtf[nm * 64 + lane + 32];
            float h0 = g_hatt[nm * 64 + lane], h1 = g_hatt[nm * 64 + lane + 32];
            sxxw[m * 64 + lane] = fdup(x0);
            sxxw[m * 64 + lane + 32] = fdup(x1);
            sxhw[m * 64 + lane] = fdup(h0);
            sxhw[m * 64 + lane + 32] = fdup(h1);
            h0r[m] = h0; h1r[m] = h1;
        }
        __syncwarp();
        ull gi[8][3], gh[8][3];
#pragma unroll
        for (int m = 0; m < 8; m++)
#pragma unroll
            for (int p = 0; p < 3; p++) { gi[m][p] = 0ull; gh[m][p] = 0ull; }
#pragma unroll 1
        for (int k2 = 0; k2 < 32; k2++) {
            ulonglong2 qi[3], qh[3];
#pragma unroll
            for (int p = 0; p < 3; p++) {
                qi[p] = wqi[p * 1024 + k2 * 32 + lane];
                qh[p] = wqh[p * 1024 + k2 * 32 + lane];
            }
#pragma unroll
            for (int m = 0; m < 8; m++) {
                ulonglong2 xd = sxxu[m * 32 + k2];
                ulonglong2 hd = sxhu[m * 32 + k2];
#pragma unroll
                for (int p = 0; p < 3; p++) {
                    ffma2(gi[m][p], qi[p].x, xd.x);
                    ffma2(gi[m][p], qi[p].y, xd.y);
                    ffma2(gh[m][p], qh[p].x, hd.x);
                    ffma2(gh[m][p], qh[p].y, hd.y);
                }
            }
        }
#pragma unroll
        for (int m = 0; m < 8; m++) {
            int nm = base + m;
            float2 i0 = funpack(gi[m][0]), i1 = funpack(gi[m][1]), i2 = funpack(gi[m][2]);
            float2 hh0 = funpack(gh[m][0]), hh1 = funpack(gh[m][1]), hh2 = funpack(gh[m][2]);
            float ir0 = i0.x + sbi[lane],        ir1 = i0.y + sbi[lane + 32];
            float iz0 = i1.x + sbi[lane + 64],   iz1 = i1.y + sbi[lane + 96];
            float in0 = i2.x + sbi[lane + 128],  in1 = i2.y + sbi[lane + 160];
            float hr0 = hh0.x + sbh[lane],       hr1 = hh0.y + sbh[lane + 32];
            float hz0 = hh1.x + sbh[lane + 64],  hz1 = hh1.y + sbh[lane + 96];
            float hn0 = hh2.x + sbh[lane + 128], hn1 = hh2.y + sbh[lane + 160];
            float r0 = sigf(ir0 + hr0), r1 = sigf(ir1 + hr1);
            float z0 = sigf(iz0 + hz0), z1 = sigf(iz1 + hz1);
            float n0 = tfast(in0 + r0 * hn0), n1 = tfast(in1 + r1 * hn1);
            float o0 = (1.f - z0) * n0 + z0 * h0r[m];
            float o1 = (1.f - z1) * n1 + z1 * h1r[m];
            float s = wred(o0 * o0 + o1 * o1);
            float nn = fmaxf(sqrtf(s), MINN);
            float sc = tfast(nn) / nn; o0 *= sc; o1 *= sc;
            s = wred(o0 * o0 + o1 * o1);
            nn = fmaxf(sqrtf(s), MINN);
            if (nn > PMAX) { sc = PMAX / nn; o0 *= sc; o1 *= sc; }
            if (nm < n) {
                outp[nm * 64 + lane]      = o0;
                outp[nm * 64 + lane + 32] = o1;
            }
        }
        __syncwarp();
    }
}

// ---------------- launch ----------------
extern "C" void kernel_launch(void* const* d_in, const int* in_sizes, int n_in,
                              void* d_out, int out_size) {
    const int*   eidx = (const int*)  d_in[0];
    const float* feat = (const float*)d_in[1];
    const float* Wl   = (const float*)d_in[2];
    const float* bl   = (const float*)d_in[3];
    const float* W1   = (const float*)d_in[4];
    const float* b1   = (const float*)d_in[5];
    const float* W2   = (const float*)d_in[6];
    const float* b2   = (const float*)d_in[7];
    const float* Q    = (const float*)d_in[8];
    const float* ratt = (const float*)d_in[9];
    const float* Wih  = (const float*)d_in[10];
    const float* Whh  = (const float*)d_in[11];
    const float* bih  = (const float*)d_in[12];
    const float* bhh  = (const float*)d_in[13];
    const float* hidd = (const float*)d_in[14];
    float* outp = (float*)d_out;

    int E = in_sizes[0] / 2;
    int N = in_sizes[1] / 128;
    int WIN = in_sizes[14] / (N * 64);
    if (N > NMAX || E > EMAX) return;
    const int* src = eidx;
    const int* dst = eidx + E;

    float *p_xcat, *p_xt, *p_x2, *p_xtf, *p_hb1, *p_hb2;
    cudaGetSymbolAddress((void**)&p_xcat, g_xcat);
    cudaGetSymbolAddress((void**)&p_xt,   g_xt);
    cudaGetSymbolAddress((void**)&p_x2,   g_x2);
    cudaGetSymbolAddress((void**)&p_xtf,  g_xtf);
    cudaGetSymbolAddress((void**)&p_hb1,  g_hb1);
    cudaGetSymbolAddress((void**)&p_hb2,  g_hb2);

    const int SMI  = 64 * 32 * 16 + WPB * 8 * 32 * 16 + 64 * 4;             // 65792
    const int SML1 = 2 * 64 * 32 * 16 + WPB * 8 * 32 * 16 + 128 * 4;        // 98816
    const int SML2 = 64 * 32 * 16 + WPB * 8 * 32 * 16 + 64 * 4;             // 65792
    const int SMG  = 2 * 49152 + 2 * WPB * 8 * 64 * 8 + 2 * 192 * 4;        // 165376
    const int SMA  = 16384 + 20480 + 256;                                   // 37120
    cudaFuncSetAttribute(k_init2,   cudaFuncAttributeMaxDynamicSharedMemorySize, SMI);
    cudaFuncSetAttribute(k_lin<2>,  cudaFuncAttributeMaxDynamicSharedMemorySize, SML1);
    cudaFuncSetAttribute(k_lin<1>,  cudaFuncAttributeMaxDynamicSharedMemorySize, SML2);
    cudaFuncSetAttribute(k_gru2,    cudaFuncAttributeMaxDynamicSharedMemorySize, SMG);
    cudaFuncSetAttribute(k_aggatt,  cudaFuncAttributeMaxDynamicSharedMemorySize, SMA);

    int eb = (E + 255) / 256;
    int nb = (N + 255) / 256;
    int NB = (N + 1023) / 1024;

    k_bias<<<1, 128>>>(b1, b2);
    k_init2<<<444, TPB, SMI>>>(feat, Wl, bl, hidd + (size_t)(WIN - 1) * N * 64, N);
    k_zero2<<<nb, 256>>>(N);
    k_count<<<eb, 256>>>(src, E);
    k_scan1<<<NB, 1024>>>(N);
    k_scan2<<<1, 128>>>(NB);
    k_scan3<<<nb, 256>>>(N, E);
    k_dis<<<nb, 256>>>(N);
    k_fill<<<eb, 256>>>(src, dst, E);
    k_lin<2><<<296, TPB, SML1>>>(p_xcat, W1, p_hb1, p_xt, N);
    if (WIN == 5) {
        k_aggatt<<<1184, TPB, SMA>>>(p_xt, p_x2, hidd, Q, ratt, N);
    } else {
        k_agg128<<<1184, TPB>>>(p_xt, p_x2, N);
        k_att<<<1184, TPB>>>(hidd, Q, ratt, N, WIN);
    }
    k_lin<1><<<444, TPB, SML2>>>(p_x2, W2, p_hb2, p_xt, N);
    k_agg64<<<1184, TPB>>>(p_xt, p_xtf, N);
    k_gru2<<<148, TPB, SMG>>>(Wih, Whh, bih, bhh, outp, N);
}

// round 8
// speedup vs baseline: 1.5216x; 1.5216x over previous
#include <cuda_runtime.h>
#include <math.h>

#define MINN  1e-15f
#define PMAX  0.996f      // (1 - 4e-3)/sqrt(c), c=1
#define SLOPE 0.01f

constexpr int NMAX = 100000;
constexpr int EMAX = 800000;
constexpr int WPB  = 8;          // warps per block
constexpr int TPB  = WPB * 32;   // 256 threads

// ---------------- scratch (static device globals; no allocation) ----------------
__device__ float g_xcat[NMAX * 128];
__device__ float g_xt  [NMAX * 128];
__device__ float g_x2  [NMAX * 128];
__device__ float g_xtf [NMAX * 64];
__device__ float g_hatt[NMAX * 64];
__device__ float g_dis [NMAX];
__device__ int   g_cnt [NMAX];
__device__ int   g_cur [NMAX];
__device__ int   g_off [NMAX + 1];
__device__ int   g_bsum[128];
__device__ int   g_csr [EMAX];
__device__ float g_hb1 [128];
__device__ float g_hb2 [64];

typedef unsigned long long ull;

// ---------------- helpers ----------------
__device__ __forceinline__ float wred(float v) {
#pragma unroll
    for (int o = 16; o; o >>= 1) v += __shfl_xor_sync(0xffffffffu, v, o);
    return v;
}
// fast artanh: poly for |x|<0.25 (rel err <1e-7), MUFU log otherwise (rel err <5e-7)
__device__ __forceinline__ float artanhf_(float x) {
    x = fminf(fmaxf(x, -1.0f + 1e-7f), 1.0f - 1e-7f);
    float x2 = x * x;
    float ser = x * (1.0f + x2 * (0.33333334f + x2 * (0.2f + x2 * (0.14285715f + x2 * 0.11111111f))));
    float lg  = 0.5f * __logf(__fdividef(1.0f + x, 1.0f - x));
    return (x2 < 0.0625f) ? ser : lg;
}
// fast tanh via MUFU ex2 (~1e-6 rel): tanh(x) = sign(x) * (1-e^{-2|x|})/(1+e^{-2|x|})
__device__ __forceinline__ float tfast(float x) {
    float ax = fabsf(x);
    float t = __expf(-2.0f * ax);
    float r = __fdividef(1.0f - t, 1.0f + t);
    return copysignf(r, x);
}
__device__ __forceinline__ float sigf(float x) {
    return __fdividef(1.0f, 1.0f + __expf(-x));
}
// packed f32x2 ops (sm_103a FFMA2 path)
__device__ __forceinline__ ull fdup(float v) {
    ull d; asm("mov.b64 %0, {%1, %1};" : "=l"(d) : "f"(v)); return d;
}
__device__ __forceinline__ void ffma2(ull& d, ull a, ull b) {
    asm("fma.rn.f32x2 %0, %1, %2, %0;" : "+l"(d) : "l"(a), "l"(b));
}
__device__ __forceinline__ float2 funpack(ull d) {
    float2 r; asm("mov.b64 {%0, %1}, %2;" : "=f"(r.x), "=f"(r.y) : "l"(d)); return r;
}

// ---------------- hyperbolic bias precompute ----------------
__device__ __forceinline__ float blk_red128(float v, float* sh) {
    int t = threadIdx.x;
    sh[t] = v; __syncthreads();
    for (int s = 64; s > 0; s >>= 1) { if (t < s) sh[t] += sh[t + s]; __syncthreads(); }
    float r = sh[0]; __syncthreads();
    return r;
}

__global__ void k_bias(const float* __restrict__ b1, const float* __restrict__ b2) {
    __shared__ float sh[128];
    int t = threadIdx.x;
    float v = b1[t];
    float n2 = blk_red128(v * v, sh);
    float nn = fmaxf(sqrtf(n2), MINN);
    float u = tanhf(nn) / nn * v;
    float pu2 = blk_red128(u * u, sh);
    float pn = fmaxf(sqrtf(pu2), MINN);
    if (pn > PMAX) u *= PMAX / pn;
    g_hb1[t] = u;
    float v2 = (t < 64) ? b2[t] : 0.f;
    float m2 = blk_red128(v2 * v2, sh);
    float mn = fmaxf(sqrtf(m2), MINN);
    float u2 = tanhf(mn) / mn * v2;
    float q2 = blk_red128(u2 * u2, sh);
    float qn = fmaxf(sqrtf(q2), MINN);
    if (qn > PMAX) u2 *= PMAX / qn;
    if (t < 64) g_hb2[t] = u2;
}

// ---------------- init: x = feat@Wl.T + bl ; expmap0 ; proj ; concat hidden ; proj ----------------
// FFMA2 + 4-node blocking. IN=128, OUT=64 (1 f32x2 acc pair (lane, lane+32)).
__global__ __launch_bounds__(TPB) void k_init2(const float* __restrict__ feat, const float* __restrict__ Wl,
                                               const float* __restrict__ bl, const float* __restrict__ hidlast, int n) {
    extern __shared__ unsigned char smraw[];
    ulonglong2* wq = (ulonglong2*)smraw;                              // 64 k2 * 32 lanes
    ull* sx = (ull*)(smraw + 64 * 32 * 16);                           // WPB * 4 * 128
    float* shb = (float*)(smraw + 64 * 32 * 16 + WPB * 4 * 128 * 8);  // 64
    int t = threadIdx.x;
    for (int idx = t; idx < 64 * 32; idx += TPB) {
        int k2 = idx >> 5, j = idx & 31;
        float4 v;
        v.x = Wl[j * 128 + 2 * k2];
        v.y = Wl[(j + 32) * 128 + 2 * k2];
        v.z = Wl[j * 128 + 2 * k2 + 1];
        v.w = Wl[(j + 32) * 128 + 2 * k2 + 1];
        ((float4*)wq)[idx] = v;
    }
    if (t < 64) shb[t] = bl[t];
    __syncthreads();
    int warp = t >> 5, lane = t & 31;
    ull* sxw = sx + warp * 512;
    const ulonglong2* sxu = (const ulonglong2*)sxw;
    int ngrp = (n + 3) >> 2;
    for (int grp = blockIdx.x * WPB + warp; grp < ngrp; grp += gridDim.x * WPB) {
        int base = grp * 4;
#pragma unroll
        for (int m = 0; m < 4; m++) {
            int nm = min(base + m, n - 1);
            float4 f = ((const float4*)feat)[nm * 32 + lane];
            ulonglong2 d0, d1;
            d0.x = fdup(f.x); d0.y = fdup(f.y); d1.x = fdup(f.z); d1.y = fdup(f.w);
            ((ulonglong2*)(sxw + m * 128))[lane * 2] = d0;
            ((ulonglong2*)(sxw + m * 128))[lane * 2 + 1] = d1;
        }
        __syncwarp();
        ull acc[4] = {0ull, 0ull, 0ull, 0ull};
#pragma unroll 4
        for (int k2 = 0; k2 < 64; k2++) {
            ulonglong2 q = wq[k2 * 32 + lane];
#pragma unroll
            for (int m = 0; m < 4; m++) {
                ulonglong2 xd = sxu[m * 64 + k2];
                ffma2(acc[m], q.x, xd.x);
                ffma2(acc[m], q.y, xd.y);
            }
        }
#pragma unroll
        for (int m = 0; m < 4; m++) {
            int nm = base + m;
            float2 av = funpack(acc[m]);
            float a0 = av.x + shb[lane], a1 = av.y + shb[lane + 32];
            // expmap0
            float s = wred(a0 * a0 + a1 * a1);
            float nn = fmaxf(sqrtf(s), MINN);
            float sc = tfast(nn) / nn; a0 *= sc; a1 *= sc;
            // proj (64-dim)
            s = wred(a0 * a0 + a1 * a1);
            nn = fmaxf(sqrtf(s), MINN);
            if (nn > PMAX) { sc = PMAX / nn; a0 *= sc; a1 *= sc; }
            // concat hidden, proj over 128 dims
            int nmc = min(nm, n - 1);
            float h0 = hidlast[nmc * 64 + lane];
            float h1 = hidlast[nmc * 64 + lane + 32];
            s = wred(a0 * a0 + a1 * a1 + h0 * h0 + h1 * h1);
            nn = fmaxf(sqrtf(s), MINN);
            if (nn > PMAX) { sc = PMAX / nn; a0 *= sc; a1 *= sc; h0 *= sc; h1 *= sc; }
            if (nm < n) {
                g_xcat[nm * 128 + lane]      = a0;
                g_xcat[nm * 128 + lane + 32] = a1;
                g_xcat[nm * 128 + lane + 64] = h0;
                g_xcat[nm * 128 + lane + 96] = h1;
            }
        }
        __syncwarp();
    }
}

// ---------------- CSR build ----------------
__global__ void k_zero2(int n) {
    int i = blockIdx.x * blockDim.x + threadIdx.x;
    if (i < n) { g_cnt[i] = 0; g_cur[i] = 0; }
}
__global__ void k_count(const int* __restrict__ src, int e) {
    int i = blockIdx.x * blockDim.x + threadIdx.x;
    if (i < e) atomicAdd(&g_cnt[src[i]], 1);
}
__global__ void k_scan1(int n) {
    __shared__ int sh[1024];
    int t = threadIdx.x;
    int i = blockIdx.x * 1024 + t;
    int v = (i < n) ? g_cnt[i] : 0;
    sh[t] = v; __syncthreads();
    for (int d = 1; d < 1024; d <<= 1) {
        int x = (t >= d) ? sh[t - d] : 0;
        __syncthreads();
        sh[t] += x; __syncthreads();
    }
    if (i < n) g_off[i] = sh[t] - v;
    if (t == 1023) g_bsum[blockIdx.x] = sh[1023];
}
__global__ void k_scan2(int nb) {
    __shared__ int sh[128];
    int t = threadIdx.x;
    int v = (t < nb) ? g_bsum[t] : 0;
    sh[t] = v; __syncthreads();
    for (int d = 1; d < 128; d <<= 1) {
        int x = (t >= d) ? sh[t - d] : 0;
        __syncthreads();
        sh[t] += x; __syncthreads();
    }
    g_bsum[t] = sh[t] - v;
}
__global__ void k_scan3(int n, int e) {
    int i = blockIdx.x * blockDim.x + threadIdx.x;
    if (i < n) g_off[i] += g_bsum[i >> 10];
    if (i == 0) g_off[n] = e;
}
__global__ void k_dis(int n) {
    int i = blockIdx.x * blockDim.x + threadIdx.x;
    if (i < n) g_dis[i] = rsqrtf((float)(g_cnt[i] + 1));
}
__global__ void k_fill(const int* __restrict__ src, const int* __restrict__ dst, int e) {
    int i = blockIdx.x * blockDim.x + threadIdx.x;
    if (i < e) {
        int s = src[i];
        int p = g_off[s] + atomicAdd(&g_cur[s], 1);
        g_csr[p] = dst[i];
    }
}

// ---------------- hyp_linear (FFMA2, 4-node blocking): mobius_matvec -> proj -> mobius_add(hb) -> proj -> logmap0 ----------------
template <int P>
__global__ __launch_bounds__(TPB) void k_lin(const float* __restrict__ xin, const float* __restrict__ W,
                                             const float* __restrict__ hb, float* __restrict__ xtout, int n) {
    extern __shared__ unsigned char smraw[];
    ulonglong2* wq = (ulonglong2*)smraw;                                   // P*64*32
    ull* sx = (ull*)(smraw + P * 64 * 32 * 16);                            // WPB*4*128
    float* shb = (float*)(smraw + P * 64 * 32 * 16 + WPB * 4 * 128 * 8);   // 64*P
    int t = threadIdx.x;
    for (int idx = t; idx < P * 64 * 32; idx += TPB) {
        int p = idx >> 11; int r = idx & 2047; int k2 = r >> 5; int j = r & 31;
        float4 v;
        v.x = W[(p * 64 + j) * 128 + 2 * k2];
        v.y = W[(p * 64 + j + 32) * 128 + 2 * k2];
        v.z = W[(p * 64 + j) * 128 + 2 * k2 + 1];
        v.w = W[(p * 64 + j + 32) * 128 + 2 * k2 + 1];
        ((float4*)wq)[idx] = v;
    }
    for (int idx = t; idx < 64 * P; idx += TPB) shb[idx] = hb[idx];
    __syncthreads();
    int warp = t >> 5, lane = t & 31;
    ull* sxw = sx + warp * 512;
    const ulonglong2* sxu = (const ulonglong2*)sxw;
    constexpr int VO = 2 * P;
    int ngrp = (n + 3) >> 2;
    for (int grp = blockIdx.x * WPB + warp; grp < ngrp; grp += gridDim.x * WPB) {
        int base = grp * 4;
        float xn[4];
#pragma unroll
        for (int m = 0; m < 4; m++) {
            int nm = min(base + m, n - 1);
            float4 f = ((const float4*)xin)[nm * 32 + lane];
            ulonglong2 d0, d1;
            d0.x = fdup(f.x); d0.y = fdup(f.y); d1.x = fdup(f.z); d1.y = fdup(f.w);
            ((ulonglong2*)(sxw + m * 128))[lane * 2] = d0;
            ((ulonglong2*)(sxw + m * 128))[lane * 2 + 1] = d1;
            float xs = f.x * f.x + f.y * f.y + f.z * f.z + f.w * f.w;
            xn[m] = fmaxf(sqrtf(wred(xs)), MINN);
        }
        __syncwarp();
        ull acc[4][P];
#pragma unroll
        for (int m = 0; m < 4; m++)
#pragma unroll
            for (int p = 0; p < P; p++) acc[m][p] = 0ull;
#pragma unroll 4
        for (int k2 = 0; k2 < 64; k2++) {
            ulonglong2 q[P];
#pragma unroll
            for (int p = 0; p < P; p++) q[p] = wq[p * 2048 + k2 * 32 + lane];
#pragma unroll
            for (int m = 0; m < 4; m++) {
                ulonglong2 xd = sxu[m * 64 + k2];
#pragma unroll
                for (int p = 0; p < P; p++) { ffma2(acc[m][p], q[p].x, xd.x); ffma2(acc[m][p], q[p].y, xd.y); }
            }
        }
#pragma unroll
        for (int m = 0; m < 4; m++) {
            int nm = base + m;
            float v[VO];
#pragma unroll
            for (int p = 0; p < P; p++) { float2 f = funpack(acc[m][p]); v[2 * p] = f.x; v[2 * p + 1] = f.y; }
            float ms = 0.f;
#pragma unroll
            for (int g = 0; g < VO; g++) ms += v[g] * v[g];
            float mxn2 = wred(ms);
            float mxn = fmaxf(sqrtf(mxn2), MINN);
            float xnn = xn[m];
            float r = tfast(mxn / xnn * artanhf_(xnn)) / mxn;
            if (mxn2 == 0.f) r = 0.f;
#pragma unroll
            for (int g = 0; g < VO; g++) v[g] *= r;
            // proj
            float s = 0.f;
#pragma unroll
            for (int g = 0; g < VO; g++) s += v[g] * v[g];
            s = wred(s);
            float pn = fmaxf(sqrtf(s), MINN);
            if (pn > PMAX) { float f = PMAX / pn;
#pragma unroll
                for (int g = 0; g < VO; g++) v[g] *= f; }
            // mobius_add(v, hb)
            float hx[VO];
            float xx = 0.f, xy = 0.f, yy = 0.f;
#pragma unroll
            for (int g = 0; g < VO; g++) {
                float hv = shb[lane + 32 * g];
                hx[g] = hv;
                xx += v[g] * v[g];
                xy += v[g] * hv;
                yy += hv * hv;
            }
            xx = wred(xx); xy = wred(xy); yy = wred(yy);
            float den = fmaxf(1.f + 2.f * xy + xx * yy, MINN);
            float ca = (1.f + 2.f * xy + yy) / den;
            float cb = (1.f - xx) / den;
#pragma unroll
            for (int g = 0; g < VO; g++) v[g] = ca * v[g] + cb * hx[g];
            // proj
            s = 0.f;
#pragma unroll
            for (int g = 0; g < VO; g++) s += v[g] * v[g];
            s = wred(s);
            pn = fmaxf(sqrtf(s), MINN);
            if (pn > PMAX) { float f = PMAX / pn;
#pragma unroll
                for (int g = 0; g < VO; g++) v[g] *= f; }
            // logmap0
            s = 0.f;
#pragma unroll
            for (int g = 0; g < VO; g++) s += v[g] * v[g];
            s = wred(s);
            pn = fmaxf(sqrtf(s), MINN);
            float a = artanhf_(pn) / pn;
            if (nm < n) {
#pragma unroll
                for (int g = 0; g < VO; g++) xtout[nm * (64 * P) + lane + 32 * g] = v[g] * a;
            }
        }
        __syncwarp();
    }
}

// ---------------- aggregation (CSR gather) + activation chain ----------------
__device__ __forceinline__ float n2_4(float4 a) { return a.x * a.x + a.y * a.y + a.z * a.z + a.w * a.w; }
__device__ __forceinline__ void  mul4(float4& a, float s) { a.x *= s; a.y *= s; a.z *= s; a.w *= s; }

__global__ void k_agg128(const float* __restrict__ xt, float* __restrict__ out, int n) {
    int t = threadIdx.x, warp = t >> 5, lane = t & 31;
    const float4* base = (const float4*)xt;
    for (int node = blockIdx.x * WPB + warp; node < n; node += gridDim.x * WPB) {
        float dn = g_dis[node];
        float4 a = base[node * 32 + lane];
        mul4(a, dn * dn);
        int e1 = g_off[node + 1];
        for (int e = g_off[node]; e < e1; e++) {
            int c = g_csr[e];
            float w = dn * g_dis[c];
            float4 v = base[c * 32 + lane];
            a.x += w * v.x; a.y += w * v.y; a.z += w * v.z; a.w += w * v.w;
        }
        float s, nn, sc;
        s = wred(n2_4(a)); nn = fmaxf(sqrtf(s), MINN); sc = tfast(nn) / nn; mul4(a, sc);
        s = wred(n2_4(a)); nn = fmaxf(sqrtf(s), MINN); if (nn > PMAX) mul4(a, PMAX / nn);
        s = wred(n2_4(a)); nn = fmaxf(sqrtf(s), MINN); sc = artanhf_(nn) / nn; mul4(a, sc);
        a.x = (a.x >= 0.f) ? a.x : SLOPE * a.x;
        a.y = (a.y >= 0.f) ? a.y : SLOPE * a.y;
        a.z = (a.z >= 0.f) ? a.z : SLOPE * a.z;
        a.w = (a.w >= 0.f) ? a.w : SLOPE * a.w;
        s = wred(n2_4(a)); nn = fmaxf(sqrtf(s), MINN); sc = tfast(nn) / nn; mul4(a, sc);
        s = wred(n2_4(a)); nn = fmaxf(sqrtf(s), MINN); if (nn > PMAX) mul4(a, PMAX / nn);
        s = wred(n2_4(a)); nn = fmaxf(sqrtf(s), MINN); if (nn > PMAX) mul4(a, PMAX / nn);
        ((float4*)out)[node * 32 + lane] = a;
    }
}

__global__ void k_agg64(const float* __restrict__ xt, float* __restrict__ out, int n) {
    int t = threadIdx.x, warp = t >> 5, lane = t & 31;
    const float2* base = (const float2*)xt;
    for (int node = blockIdx.x * WPB + warp; node < n; node += gridDim.x * WPB) {
        float dn = g_dis[node];
        float2 a = base[node * 32 + lane];
        float ws = dn * dn;
        a.x *= ws; a.y *= ws;
        int e1 = g_off[node + 1];
        for (int e = g_off[node]; e < e1; e++) {
            int c = g_csr[e];
            float w = dn * g_dis[c];
            float2 v = base[c * 32 + lane];
            a.x += w * v.x; a.y += w * v.y;
        }
        float s, nn, sc;
        s = wred(a.x * a.x + a.y * a.y); nn = fmaxf(sqrtf(s), MINN); sc = tfast(nn) / nn; a.x *= sc; a.y *= sc;
        s = wred(a.x * a.x + a.y * a.y); nn = fmaxf(sqrtf(s), MINN); if (nn > PMAX) { sc = PMAX / nn; a.x *= sc; a.y *= sc; }
        s = wred(a.x * a.x + a.y * a.y); nn = fmaxf(sqrtf(s), MINN); sc = artanhf_(nn) / nn; a.x *= sc; a.y *= sc;
        a.x = (a.x >= 0.f) ? a.x : SLOPE * a.x;
        a.y = (a.y >= 0.f) ? a.y : SLOPE * a.y;
        s = wred(a.x * a.x + a.y * a.y); nn = fmaxf(sqrtf(s), MINN); sc = tfast(nn) / nn; a.x *= sc; a.y *= sc;
        s = wred(a.x * a.x + a.y * a.y); nn = fmaxf(sqrtf(s), MINN); if (nn > PMAX) { sc = PMAX / nn; a.x *= sc; a.y *= sc; }
        s = wred(a.x * a.x + a.y * a.y); nn = fmaxf(sqrtf(s), MINN); sc = artanhf_(nn) / nn; a.x *= sc; a.y *= sc;
        ((float2*)out)[node * 32 + lane] = a;
    }
}

// ---------------- HTA window attention (WIN=5 specialized, FFMA2) ----------------
__global__ __launch_bounds__(TPB) void k_att5(const float* __restrict__ hiddens, const float* __restrict__ Q,
                                              const float* __restrict__ ratt, int n) {
    __shared__ ulonglong2 wq[32 * 32];    // 16KB: k2-major, per-lane pair (j, j+32)
    __shared__ ull sxs[WPB * 5 * 64];     // 20KB dup hlog
    __shared__ float shr[64];
    int t = threadIdx.x;
    for (int idx = t; idx < 32 * 32; idx += TPB) {
        int k2 = idx >> 5, j = idx & 31;
        float4 v;
        v.x = Q[(2 * k2) * 64 + j];
        v.y = Q[(2 * k2) * 64 + j + 32];
        v.z = Q[(2 * k2 + 1) * 64 + j];
        v.w = Q[(2 * k2 + 1) * 64 + j + 32];
        ((float4*)wq)[idx] = v;
    }
    if (t < 64) shr[t] = ratt[t];
    __syncthreads();
    int warp = t >> 5, lane = t & 31;
    ull* sxw = sxs + warp * 5 * 64;
    const ulonglong2* sxu = (const ulonglong2*)sxw;
    const float inv5 = 0.2f;
    for (int node = blockIdx.x * WPB + warp; node < n; node += gridDim.x * WPB) {
        float hl0[5], hl1[5], ew[5];
#pragma unroll
        for (int w = 0; w < 5; w++) {
            size_t off = ((size_t)w * n + node) * 64;
            float v0 = hiddens[off + lane];
            float v1 = hiddens[off + lane + 32];
            float s = wred(v0 * v0 + v1 * v1);
            float pn = fmaxf(sqrtf(s), MINN);
            float sc = artanhf_(pn) / pn;
            v0 *= sc; v1 *= sc;
            hl0[w] = v0; hl1[w] = v1;
            sxw[w * 64 + lane] = fdup(v0);
            sxw[w * 64 + lane + 32] = fdup(v1);
        }
        __syncwarp();
        ull acc[5] = {0ull, 0ull, 0ull, 0ull, 0ull};
#pragma unroll 4
        for (int k2 = 0; k2 < 32; k2++) {
            ulonglong2 q = wq[k2 * 32 + lane];
#pragma unroll
            for (int w = 0; w < 5; w++) {
                ulonglong2 xd = sxu[w * 32 + k2];
                ffma2(acc[w], q.x, xd.x);
                ffma2(acc[w], q.y, xd.y);
            }
        }
#pragma unroll
        for (int w = 0; w < 5; w++) {
            float2 f = funpack(acc[w]);
            float ep = tfast(f.x) * shr[lane] + tfast(f.y) * shr[lane + 32];
            ew[w] = wred(ep);
        }
        float m = -1e30f;
#pragma unroll
        for (int w = 0; w < 5; w++) m = fmaxf(m, ew[w]);
        float ssum = 0.f;
#pragma unroll
        for (int w = 0; w < 5; w++) { ew[w] = __expf(ew[w] - m); ssum += ew[w]; }
        float inv = inv5 / ssum;
        float o0 = 0.f, o1 = 0.f;
#pragma unroll
        for (int w = 0; w < 5; w++) { o0 += ew[w] * hl0[w]; o1 += ew[w] * hl1[w]; }
        g_hatt[node * 64 + lane]      = o0 * inv;
        g_hatt[node * 64 + lane + 32] = o1 * inv;
        __syncwarp();
    }
}

// generic fallback (win != 5)
__global__ void k_att(const float* __restrict__ hiddens, const float* __restrict__ Q,
                      const float* __restrict__ ratt, int n, int win) {
    __shared__ float shQ[64 * 64];
    __shared__ float shr[64];
    __shared__ float shh[WPB][64];
    int t = threadIdx.x;
    for (int idx = t; idx < 64 * 64; idx += TPB) shQ[idx] = Q[idx];
    if (t < 64) shr[t] = ratt[t];
    __syncthreads();
    int warp = t >> 5, lane = t & 31;
    float invwin = 1.0f / (float)win;
    for (int node = blockIdx.x * WPB + warp; node < n; node += gridDim.x * WPB) {
        float hl0[8], hl1[8], ew[8];
        for (int w = 0; w < win; w++) {
            size_t off = ((size_t)w * n + node) * 64;
            float v0 = hiddens[off + lane];
            float v1 = hiddens[off + lane + 32];
            float s = wred(v0 * v0 + v1 * v1);
            float pn = fmaxf(sqrtf(s), MINN);
            float sc = artanhf_(pn) / pn;
            v0 *= sc; v1 *= sc;
            hl0[w] = v0; hl1[w] = v1;
            shh[warp][lane] = v0; shh[warp][lane + 32] = v1;
            __syncwarp();
            float ep = 0.f;
#pragma unroll
            for (int g = 0; g < 2; g++) {
                int j = lane + 32 * g;
                float a = 0.f;
                for (int k = 0; k < 64; k++) a += shh[warp][k] * shQ[k * 64 + j];
                ep += tfast(a) * shr[j];
            }
            ew[w] = wred(ep);
            __syncwarp();
        }
        float m = -1e30f;
        for (int w = 0; w < win; w++) m = fmaxf(m, ew[w]);
        float ssum = 0.f;
        for (int w = 0; w < win; w++) { ew[w] = __expf(ew[w] - m); ssum += ew[w]; }
        float inv = invwin / ssum;
        float o0 = 0.f, o1 = 0.f;
        for (int w = 0; w < win; w++) { o0 += ew[w] * hl0[w]; o1 += ew[w] * hl1[w]; }
        g_hatt[node * 64 + lane]      = o0 * inv;
        g_hatt[node * 64 + lane + 32] = o1 * inv;
    }
}

// ---------------- GRU (FFMA2, 8-node blocking) + final expmap0/proj ----------------
__global__ __launch_bounds__(TPB) void k_gru2(const float* __restrict__ Wih, const float* __restrict__ Whh,
                                              const float* __restrict__ bih, const float* __restrict__ bhh,
                                              float* __restrict__ outp, int n) {
    extern __shared__ unsigned char smraw[];
    ulonglong2* wqi = (ulonglong2*)smraw;                      // 3*32*32
    ulonglong2* wqh = (ulonglong2*)(smraw + 49152);            // 3*32*32
    ull* sxx = (ull*)(smraw + 98304);                          // WPB*8*64
    ull* sxh = (ull*)(smraw + 131072);                         // WPB*8*64
    float* sbi = (float*)(smraw + 163840);                     // 192
    float* sbh = (float*)(smraw + 164608);                     // 192
    int t = threadIdx.x;
    for (int idx = t; idx < 3 * 32 * 32; idx += TPB) {
        int p = idx >> 10; int r = idx & 1023; int k2 = r >> 5; int j = r & 31;
        float4 vi, vh;
        vi.x = Wih[(p * 64 + j) * 64 + 2 * k2];
        vi.y = Wih[(p * 64 + j + 32) * 64 + 2 * k2];
        vi.z = Wih[(p * 64 + j) * 64 + 2 * k2 + 1];
        vi.w = Wih[(p * 64 + j + 32) * 64 + 2 * k2 + 1];
        vh.x = Whh[(p * 64 + j) * 64 + 2 * k2];
        vh.y = Whh[(p * 64 + j + 32) * 64 + 2 * k2];
        vh.z = Whh[(p * 64 + j) * 64 + 2 * k2 + 1];
        vh.w = Whh[(p * 64 + j + 32) * 64 + 2 * k2 + 1];
        ((float4*)wqi)[idx] = vi;
        ((float4*)wqh)[idx] = vh;
    }
    if (t < 192) { sbi[t] = bih[t]; sbh[t] = bhh[t]; }
    __syncthreads();
    int warp = t >> 5, lane = t & 31;
    ull* sxxw = sxx + warp * 512;
    ull* sxhw = sxh + warp * 512;
    const ulonglong2* sxxu = (const ulonglong2*)sxxw;
    const ulonglong2* sxhu = (const ulonglong2*)sxhw;
    int ngrp = (n + 7) >> 3;
    for (int grp = blockIdx.x * WPB + warp; grp < ngrp; grp += gridDim.x * WPB) {
        int base = grp * 8;
        float h0r[8], h1r[8];
#pragma unroll
        for (int m = 0; m < 8; m++) {
            int nm = min(base + m, n - 1);
            float x0 = g_xtf[nm * 64 + lane], x1 = g_xtf[nm * 64 + lane + 32];
            float h0 = g_hatt[nm * 64 + lane], h1 = g_hatt[nm * 64 + lane + 32];
            sxxw[m * 64 + lane] = fdup(x0);
            sxxw[m * 64 + lane + 32] = fdup(x1);
            sxhw[m * 64 + lane] = fdup(h0);
            sxhw[m * 64 + lane + 32] = fdup(h1);
            h0r[m] = h0; h1r[m] = h1;
        }
        __syncwarp();
        ull gi[8][3], gh[8][3];
#pragma unroll
        for (int m = 0; m < 8; m++)
#pragma unroll
            for (int p = 0; p < 3; p++) { gi[m][p] = 0ull; gh[m][p] = 0ull; }
#pragma unroll 1
        for (int k2 = 0; k2 < 32; k2++) {
            ulonglong2 qi[3], qh[3];
#pragma unroll
            for (int p = 0; p < 3; p++) {
                qi[p] = wqi[p * 1024 + k2 * 32 + lane];
                qh[p] = wqh[p * 1024 + k2 * 32 + lane];
            }
#pragma unroll
            for (int m = 0; m < 8; m++) {
                ulonglong2 xd = sxxu[m * 32 + k2];
                ulonglong2 hd = sxhu[m * 32 + k2];
#pragma unroll
                for (int p = 0; p < 3; p++) {
                    ffma2(gi[m][p], qi[p].x, xd.x);
                    ffma2(gi[m][p], qi[p].y, xd.y);
                    ffma2(gh[m][p], qh[p].x, hd.x);
                    ffma2(gh[m][p], qh[p].y, hd.y);
                }
            }
        }
#pragma unroll
        for (int m = 0; m < 8; m++) {
            int nm = base + m;
            float2 i0 = funpack(gi[m][0]), i1 = funpack(gi[m][1]), i2 = funpack(gi[m][2]);
            float2 hh0 = funpack(gh[m][0]), hh1 = funpack(gh[m][1]), hh2 = funpack(gh[m][2]);
            float ir0 = i0.x + sbi[lane],        ir1 = i0.y + sbi[lane + 32];
            float iz0 = i1.x + sbi[lane + 64],   iz1 = i1.y + sbi[lane + 96];
            float in0 = i2.x + sbi[lane + 128],  in1 = i2.y + sbi[lane + 160];
            float hr0 = hh0.x + sbh[lane],       hr1 = hh0.y + sbh[lane + 32];
            float hz0 = hh1.x + sbh[lane + 64],  hz1 = hh1.y + sbh[lane + 96];
            float hn0 = hh2.x + sbh[lane + 128], hn1 = hh2.y + sbh[lane + 160];
            float r0 = sigf(ir0 + hr0), r1 = sigf(ir1 + hr1);
            float z0 = sigf(iz0 + hz0), z1 = sigf(iz1 + hz1);
            float n0 = tfast(in0 + r0 * hn0), n1 = tfast(in1 + r1 * hn1);
            float o0 = (1.f - z0) * n0 + z0 * h0r[m];
            float o1 = (1.f - z1) * n1 + z1 * h1r[m];
            float s = wred(o0 * o0 + o1 * o1);
            float nn = fmaxf(sqrtf(s), MINN);
            float sc = tfast(nn) / nn; o0 *= sc; o1 *= sc;
            s = wred(o0 * o0 + o1 * o1);
            nn = fmaxf(sqrtf(s), MINN);
            if (nn > PMAX) { sc = PMAX / nn; o0 *= sc; o1 *= sc; }
            if (nm < n) {
                outp[nm * 64 + lane]      = o0;
                outp[nm * 64 + lane + 32] = o1;
            }
        }
        __syncwarp();
    }
}

// ---------------- launch ----------------
extern "C" void kernel_launch(void* const* d_in, const int* in_sizes, int n_in,
                              void* d_out, int out_size) {
    const int*   eidx = (const int*)  d_in[0];
    const float* feat = (const float*)d_in[1];
    const float* Wl   = (const float*)d_in[2];
    const float* bl   = (const float*)d_in[3];
    const float* W1   = (const float*)d_in[4];
    const float* b1   = (const float*)d_in[5];
    const float* W2   = (const float*)d_in[6];
    const float* b2   = (const float*)d_in[7];
    const float* Q    = (const float*)d_in[8];
    const float* ratt = (const float*)d_in[9];
    const float* Wih  = (const float*)d_in[10];
    const float* Whh  = (const float*)d_in[11];
    const float* bih  = (const float*)d_in[12];
    const float* bhh  = (const float*)d_in[13];
    const float* hidd = (const float*)d_in[14];
    float* outp = (float*)d_out;

    int E = in_sizes[0] / 2;
    int N = in_sizes[1] / 128;
    int WIN = in_sizes[14] / (N * 64);
    if (N > NMAX || E > EMAX) return;
    const int* src = eidx;
    const int* dst = eidx + E;

    float *p_xcat, *p_xt, *p_x2, *p_xtf, *p_hb1, *p_hb2;
    cudaGetSymbolAddress((void**)&p_xcat, g_xcat);
    cudaGetSymbolAddress((void**)&p_xt,   g_xt);
    cudaGetSymbolAddress((void**)&p_x2,   g_x2);
    cudaGetSymbolAddress((void**)&p_xtf,  g_xtf);
    cudaGetSymbolAddress((void**)&p_hb1,  g_hb1);
    cudaGetSymbolAddress((void**)&p_hb2,  g_hb2);

    const int SMI  = 64 * 32 * 16 + WPB * 4 * 128 * 8 + 64 * 4;            // 65792
    const int SML1 = 2 * 64 * 32 * 16 + WPB * 4 * 128 * 8 + 128 * 4;       // 98816
    const int SML2 = 64 * 32 * 16 + WPB * 4 * 128 * 8 + 64 * 4;            // 65792
    const int SMG  = 2 * 49152 + 2 * WPB * 8 * 64 * 8 + 2 * 192 * 4;       // 165376
    cudaFuncSetAttribute(k_init2,   cudaFuncAttributeMaxDynamicSharedMemorySize, SMI);
    cudaFuncSetAttribute(k_lin<2>,  cudaFuncAttributeMaxDynamicSharedMemorySize, SML1);
    cudaFuncSetAttribute(k_lin<1>,  cudaFuncAttributeMaxDynamicSharedMemorySize, SML2);
    cudaFuncSetAttribute(k_gru2,    cudaFuncAttributeMaxDynamicSharedMemorySize, SMG);

    int eb = (E + 255) / 256;
    int nb = (N + 255) / 256;
    int NB = (N + 1023) / 1024;

    k_bias<<<1, 128>>>(b1, b2);
    k_init2<<<444, TPB, SMI>>>(feat, Wl, bl, hidd + (size_t)(WIN - 1) * N * 64, N);
    k_zero2<<<nb, 256>>>(N);
    k_count<<<eb, 256>>>(src, E);
    k_scan1<<<NB, 1024>>>(N);
    k_scan2<<<1, 128>>>(NB);
    k_scan3<<<nb, 256>>>(N, E);
    k_dis<<<nb, 256>>>(N);
    k_fill<<<eb, 256>>>(src, dst, E);
    k_lin<2><<<296, TPB, SML1>>>(p_xcat, W1, p_hb1, p_xt, N);
    k_agg128<<<1184, TPB>>>(p_xt, p_x2, N);
    k_lin<1><<<444, TPB, SML2>>>(p_x2, W2, p_hb2, p_xt, N);
    k_agg64<<<1184, TPB>>>(p_xt, p_xtf, N);
    if (WIN == 5) k_att5<<<592, TPB>>>(hidd, Q, ratt, N);
    else          k_att<<<1184, TPB>>>(hidd, Q, ratt, N, WIN);
    k_gru2<<<148, TPB, SMG>>>(Wih, Whh, bih, bhh, outp, N);
}

// round 9
// speedup vs baseline: 1.5293x; 1.0051x over previous
#include <cuda_runtime.h>
#include <math.h>

#define MINN  1e-15f
#define PMAX  0.996f      // (1 - 4e-3)/sqrt(c), c=1
#define SLOPE 0.01f

constexpr int NMAX = 100000;
constexpr int EMAX = 800000;
constexpr int WPB  = 8;          // warps per block
constexpr int TPB  = WPB * 32;   // 256 threads

// ---------------- scratch (static device globals; no allocation) ----------------
__device__ float g_xcat[NMAX * 128];
__device__ float g_xt  [NMAX * 128];
__device__ float g_x2  [NMAX * 128];
__device__ float g_xtf [NMAX * 64];
__device__ float g_hatt[NMAX * 64];
__device__ float g_dis [NMAX];
__device__ int   g_cnt [NMAX];
__device__ int   g_cur [NMAX];
__device__ int   g_off [NMAX + 1];
__device__ int   g_bsum[128];
__device__ int   g_csr [EMAX];
__device__ float g_hb1 [128];
__device__ float g_hb2 [64];

typedef unsigned long long ull;

// ---------------- helpers ----------------
__device__ __forceinline__ float wred(float v) {
#pragma unroll
    for (int o = 16; o; o >>= 1) v += __shfl_xor_sync(0xffffffffu, v, o);
    return v;
}
// fast artanh: poly for |x|<0.25 (rel err <1e-7), MUFU log otherwise (rel err <5e-7)
__device__ __forceinline__ float artanhf_(float x) {
    x = fminf(fmaxf(x, -1.0f + 1e-7f), 1.0f - 1e-7f);
    float x2 = x * x;
    float ser = x * (1.0f + x2 * (0.33333334f + x2 * (0.2f + x2 * (0.14285715f + x2 * 0.11111111f))));
    float lg  = 0.5f * __logf(__fdividef(1.0f + x, 1.0f - x));
    return (x2 < 0.0625f) ? ser : lg;
}
// fast tanh via MUFU ex2 (~1e-6 rel): tanh(x) = sign(x) * (1-e^{-2|x|})/(1+e^{-2|x|})
__device__ __forceinline__ float tfast(float x) {
    float ax = fabsf(x);
    float t = __expf(-2.0f * ax);
    float r = __fdividef(1.0f - t, 1.0f + t);
    return copysignf(r, x);
}
__device__ __forceinline__ float sigf(float x) {
    return __fdividef(1.0f, 1.0f + __expf(-x));
}
// packed f32x2 ops (sm_103a FFMA2 path)
__device__ __forceinline__ ull fdup(float v) {
    ull d; asm("mov.b64 %0, {%1, %1};" : "=l"(d) : "f"(v)); return d;
}
__device__ __forceinline__ void ffma2(ull& d, ull a, ull b) {
    asm("fma.rn.f32x2 %0, %1, %2, %0;" : "+l"(d) : "l"(a), "l"(b));
}
__device__ __forceinline__ float2 funpack(ull d) {
    float2 r; asm("mov.b64 {%0, %1}, %2;" : "=f"(r.x), "=f"(r.y) : "l"(d)); return r;
}

// ---------------- hyperbolic bias precompute ----------------
__device__ __forceinline__ float blk_red128(float v, float* sh) {
    int t = threadIdx.x;
    sh[t] = v; __syncthreads();
    for (int s = 64; s > 0; s >>= 1) { if (t < s) sh[t] += sh[t + s]; __syncthreads(); }
    float r = sh[0]; __syncthreads();
    return r;
}

__global__ void k_bias(const float* __restrict__ b1, const float* __restrict__ b2) {
    __shared__ float sh[128];
    int t = threadIdx.x;
    float v = b1[t];
    float n2 = blk_red128(v * v, sh);
    float nn = fmaxf(sqrtf(n2), MINN);
    float u = tanhf(nn) / nn * v;
    float pu2 = blk_red128(u * u, sh);
    float pn = fmaxf(sqrtf(pu2), MINN);
    if (pn > PMAX) u *= PMAX / pn;
    g_hb1[t] = u;
    float v2 = (t < 64) ? b2[t] : 0.f;
    float m2 = blk_red128(v2 * v2, sh);
    float mn = fmaxf(sqrtf(m2), MINN);
    float u2 = tanhf(mn) / mn * v2;
    float q2 = blk_red128(u2 * u2, sh);
    float qn = fmaxf(sqrtf(q2), MINN);
    if (qn > PMAX) u2 *= PMAX / qn;
    if (t < 64) g_hb2[t] = u2;
}

// ---------------- init: x = feat@Wl.T + bl ; expmap0 ; proj ; concat hidden ; proj ----------------
// FFMA2 + 4-node blocking. IN=128, OUT=64 (1 f32x2 acc pair (lane, lane+32)).
__global__ __launch_bounds__(TPB) void k_init2(const float* __restrict__ feat, const float* __restrict__ Wl,
                                               const float* __restrict__ bl, const float* __restrict__ hidlast, int n) {
    extern __shared__ unsigned char smraw[];
    ulonglong2* wq = (ulonglong2*)smraw;                              // 64 k2 * 32 lanes
    ull* sx = (ull*)(smraw + 64 * 32 * 16);                           // WPB * 4 * 128
    float* shb = (float*)(smraw + 64 * 32 * 16 + WPB * 4 * 128 * 8);  // 64
    int t = threadIdx.x;
    for (int idx = t; idx < 64 * 32; idx += TPB) {
        int k2 = idx >> 5, j = idx & 31;
        float4 v;
        v.x = Wl[j * 128 + 2 * k2];
        v.y = Wl[(j + 32) * 128 + 2 * k2];
        v.z = Wl[j * 128 + 2 * k2 + 1];
        v.w = Wl[(j + 32) * 128 + 2 * k2 + 1];
        ((float4*)wq)[idx] = v;
    }
    if (t < 64) shb[t] = bl[t];
    __syncthreads();
    int warp = t >> 5, lane = t & 31;
    ull* sxw = sx + warp * 512;
    const ulonglong2* sxu = (const ulonglong2*)sxw;
    int ngrp = (n + 3) >> 2;
    for (int grp = blockIdx.x * WPB + warp; grp < ngrp; grp += gridDim.x * WPB) {
        int base = grp * 4;
#pragma unroll
        for (int m = 0; m < 4; m++) {
            int nm = min(base + m, n - 1);
            float4 f = ((const float4*)feat)[nm * 32 + lane];
            ulonglong2 d0, d1;
            d0.x = fdup(f.x); d0.y = fdup(f.y); d1.x = fdup(f.z); d1.y = fdup(f.w);
            ((ulonglong2*)(sxw + m * 128))[lane * 2] = d0;
            ((ulonglong2*)(sxw + m * 128))[lane * 2 + 1] = d1;
        }
        __syncwarp();
        ull acc[4] = {0ull, 0ull, 0ull, 0ull};
#pragma unroll 4
        for (int k2 = 0; k2 < 64; k2++) {
            ulonglong2 q = wq[k2 * 32 + lane];
#pragma unroll
            for (int m = 0; m < 4; m++) {
                ulonglong2 xd = sxu[m * 64 + k2];
                ffma2(acc[m], q.x, xd.x);
                ffma2(acc[m], q.y, xd.y);
            }
        }
#pragma unroll
        for (int m = 0; m < 4; m++) {
            int nm = base + m;
            float2 av = funpack(acc[m]);
            float a0 = av.x + shb[lane], a1 = av.y + shb[lane + 32];
            // expmap0
            float s = wred(a0 * a0 + a1 * a1);
            float nn = fmaxf(sqrtf(s), MINN);
            float sc = tfast(nn) / nn; a0 *= sc; a1 *= sc;
            // proj (64-dim)
            s = wred(a0 * a0 + a1 * a1);
            nn = fmaxf(sqrtf(s), MINN);
            if (nn > PMAX) { sc = PMAX / nn; a0 *= sc; a1 *= sc; }
            // concat hidden, proj over 128 dims
            int nmc = min(nm, n - 1);
            float h0 = hidlast[nmc * 64 + lane];
            float h1 = hidlast[nmc * 64 + lane + 32];
            s = wred(a0 * a0 + a1 * a1 + h0 * h0 + h1 * h1);
            nn = fmaxf(sqrtf(s), MINN);
            if (nn > PMAX) { sc = PMAX / nn; a0 *= sc; a1 *= sc; h0 *= sc; h1 *= sc; }
            if (nm < n) {
                g_xcat[nm * 128 + lane]      = a0;
                g_xcat[nm * 128 + lane + 32] = a1;
                g_xcat[nm * 128 + lane + 64] = h0;
                g_xcat[nm * 128 + lane + 96] = h1;
            }
        }
        __syncwarp();
    }
}

// ---------------- CSR build ----------------
__global__ void k_zero2(int n) {
    int i = blockIdx.x * blockDim.x + threadIdx.x;
    if (i < n) { g_cnt[i] = 0; g_cur[i] = 0; }
}
__global__ void k_count(const int* __restrict__ src, int e) {
    int i = blockIdx.x * blockDim.x + threadIdx.x;
    if (i < e) atomicAdd(&g_cnt[src[i]], 1);
}
__global__ void k_scan1(int n) {
    __shared__ int sh[1024];
    int t = threadIdx.x;
    int i = blockIdx.x * 1024 + t;
    int v = (i < n) ? g_cnt[i] : 0;
    sh[t] = v; __syncthreads();
    for (int d = 1; d < 1024; d <<= 1) {
        int x = (t >= d) ? sh[t - d] : 0;
        __syncthreads();
        sh[t] += x; __syncthreads();
    }
    if (i < n) g_off[i] = sh[t] - v;
    if (t == 1023) g_bsum[blockIdx.x] = sh[1023];
}
__global__ void k_scan2(int nb) {
    __shared__ int sh[128];
    int t = threadIdx.x;
    int v = (t < nb) ? g_bsum[t] : 0;
    sh[t] = v; __syncthreads();
    for (int d = 1; d < 128; d <<= 1) {
        int x = (t >= d) ? sh[t - d] : 0;
        __syncthreads();
        sh[t] += x; __syncthreads();
    }
    g_bsum[t] = sh[t] - v;
}
__global__ void k_scan3(int n, int e) {
    int i = blockIdx.x * blockDim.x + threadIdx.x;
    if (i < n) g_off[i] += g_bsum[i >> 10];
    if (i == 0) g_off[n] = e;
}
__global__ void k_dis(int n) {
    int i = blockIdx.x * blockDim.x + threadIdx.x;
    if (i < n) g_dis[i] = rsqrtf((float)(g_cnt[i] + 1));
}
__global__ void k_fill(const int* __restrict__ src, const int* __restrict__ dst, int e) {
    int i = blockIdx.x * blockDim.x + threadIdx.x;
    if (i < e) {
        int s = src[i];
        int p = g_off[s] + atomicAdd(&g_cur[s], 1);
        g_csr[p] = dst[i];
    }
}

// ---------------- hyp_linear (FFMA2, 4-node blocking): mobius_matvec -> proj -> mobius_add(hb) -> proj -> logmap0 ----------------
template <int P>
__global__ __launch_bounds__(TPB) void k_lin(const float* __restrict__ xin, const float* __restrict__ W,
                                             const float* __restrict__ hb, float* __restrict__ xtout, int n) {
    extern __shared__ unsigned char smraw[];
    ulonglong2* wq = (ulonglong2*)smraw;                                   // P*64*32
    ull* sx = (ull*)(smraw + P * 64 * 32 * 16);                            // WPB*4*128
    float* shb = (float*)(smraw + P * 64 * 32 * 16 + WPB * 4 * 128 * 8);   // 64*P
    int t = threadIdx.x;
    for (int idx = t; idx < P * 64 * 32; idx += TPB) {
        int p = idx >> 11; int r = idx & 2047; int k2 = r >> 5; int j = r & 31;
        float4 v;
        v.x = W[(p * 64 + j) * 128 + 2 * k2];
        v.y = W[(p * 64 + j + 32) * 128 + 2 * k2];
        v.z = W[(p * 64 + j) * 128 + 2 * k2 + 1];
        v.w = W[(p * 64 + j + 32) * 128 + 2 * k2 + 1];
        ((float4*)wq)[idx] = v;
    }
    for (int idx = t; idx < 64 * P; idx += TPB) shb[idx] = hb[idx];
    __syncthreads();
    int warp = t >> 5, lane = t & 31;
    ull* sxw = sx + warp * 512;
    const ulonglong2* sxu = (const ulonglong2*)sxw;
    constexpr int VO = 2 * P;
    int ngrp = (n + 3) >> 2;
    for (int grp = blockIdx.x * WPB + warp; grp < ngrp; grp += gridDim.x * WPB) {
        int base = grp * 4;
        float xn[4];
#pragma unroll
        for (int m = 0; m < 4; m++) {
            int nm = min(base + m, n - 1);
            float4 f = ((const float4*)xin)[nm * 32 + lane];
            ulonglong2 d0, d1;
            d0.x = fdup(f.x); d0.y = fdup(f.y); d1.x = fdup(f.z); d1.y = fdup(f.w);
            ((ulonglong2*)(sxw + m * 128))[lane * 2] = d0;
            ((ulonglong2*)(sxw + m * 128))[lane * 2 + 1] = d1;
            float xs = f.x * f.x + f.y * f.y + f.z * f.z + f.w * f.w;
            xn[m] = fmaxf(sqrtf(wred(xs)), MINN);
        }
        __syncwarp();
        ull acc[4][P];
#pragma unroll
        for (int m = 0; m < 4; m++)
#pragma unroll
            for (int p = 0; p < P; p++) acc[m][p] = 0ull;
#pragma unroll 4
        for (int k2 = 0; k2 < 64; k2++) {
            ulonglong2 q[P];
#pragma unroll
            for (int p = 0; p < P; p++) q[p] = wq[p * 2048 + k2 * 32 + lane];
#pragma unroll
            for (int m = 0; m < 4; m++) {
                ulonglong2 xd = sxu[m * 64 + k2];
#pragma unroll
                for (int p = 0; p < P; p++) { ffma2(acc[m][p], q[p].x, xd.x); ffma2(acc[m][p], q[p].y, xd.y); }
            }
        }
#pragma unroll
        for (int m = 0; m < 4; m++) {
            int nm = base + m;
            float v[VO];
#pragma unroll
            for (int p = 0; p < P; p++) { float2 f = funpack(acc[m][p]); v[2 * p] = f.x; v[2 * p + 1] = f.y; }
            float ms = 0.f;
#pragma unroll
            for (int g = 0; g < VO; g++) ms += v[g] * v[g];
            float mxn2 = wred(ms);
            float mxn = fmaxf(sqrtf(mxn2), MINN);
            float xnn = xn[m];
            float r = tfast(mxn / xnn * artanhf_(xnn)) / mxn;
            if (mxn2 == 0.f) r = 0.f;
#pragma unroll
            for (int g = 0; g < VO; g++) v[g] *= r;
            // proj
            float s = 0.f;
#pragma unroll
            for (int g = 0; g < VO; g++) s += v[g] * v[g];
            s = wred(s);
            float pn = fmaxf(sqrtf(s), MINN);
            if (pn > PMAX) { float f = PMAX / pn;
#pragma unroll
                for (int g = 0; g < VO; g++) v[g] *= f; }
            // mobius_add(v, hb)
            float hx[VO];
            float xx = 0.f, xy = 0.f, yy = 0.f;
#pragma unroll
            for (int g = 0; g < VO; g++) {
                float hv = shb[lane + 32 * g];
                hx[g] = hv;
                xx += v[g] * v[g];
                xy += v[g] * hv;
                yy += hv * hv;
            }
            xx = wred(xx); xy = wred(xy); yy = wred(yy);
            float den = fmaxf(1.f + 2.f * xy + xx * yy, MINN);
            float ca = (1.f + 2.f * xy + yy) / den;
            float cb = (1.f - xx) / den;
#pragma unroll
            for (int g = 0; g < VO; g++) v[g] = ca * v[g] + cb * hx[g];
            // proj
            s = 0.f;
#pragma unroll
            for (int g = 0; g < VO; g++) s += v[g] * v[g];
            s = wred(s);
            pn = fmaxf(sqrtf(s), MINN);
            if (pn > PMAX) { float f = PMAX / pn;
#pragma unroll
                for (int g = 0; g < VO; g++) v[g] *= f; }
            // logmap0
            s = 0.f;
#pragma unroll
            for (int g = 0; g < VO; g++) s += v[g] * v[g];
            s = wred(s);
            pn = fmaxf(sqrtf(s), MINN);
            float a = artanhf_(pn) / pn;
            if (nm < n) {
#pragma unroll
                for (int g = 0; g < VO; g++) xtout[nm * (64 * P) + lane + 32 * g] = v[g] * a;
            }
        }
        __syncwarp();
    }
}

// ---------------- aggregation (CSR gather) + activation chain ----------------
__device__ __forceinline__ float n2_4(float4 a) { return a.x * a.x + a.y * a.y + a.z * a.z + a.w * a.w; }
__device__ __forceinline__ void  mul4(float4& a, float s) { a.x *= s; a.y *= s; a.z *= s; a.w *= s; }

__global__ void k_agg128(const float* __restrict__ xt, float* __restrict__ out, int n) {
    int t = threadIdx.x, warp = t >> 5, lane = t & 31;
    const float4* base = (const float4*)xt;
    for (int node = blockIdx.x * WPB + warp; node < n; node += gridDim.x * WPB) {
        float dn = g_dis[node];
        float4 a = base[node * 32 + lane];
        mul4(a, dn * dn);
        int e1 = g_off[node + 1];
        for (int e = g_off[node]; e < e1; e++) {
            int c = g_csr[e];
            float w = dn * g_dis[c];
            float4 v = base[c * 32 + lane];
            a.x += w * v.x; a.y += w * v.y; a.z += w * v.z; a.w += w * v.w;
        }
        float s, nn, sc;
        s = wred(n2_4(a)); nn = fmaxf(sqrtf(s), MINN); sc = tfast(nn) / nn; mul4(a, sc);
        s = wred(n2_4(a)); nn = fmaxf(sqrtf(s), MINN); if (nn > PMAX) mul4(a, PMAX / nn);
        s = wred(n2_4(a)); nn = fmaxf(sqrtf(s), MINN); sc = artanhf_(nn) / nn; mul4(a, sc);
        a.x = (a.x >= 0.f) ? a.x : SLOPE * a.x;
        a.y = (a.y >= 0.f) ? a.y : SLOPE * a.y;
        a.z = (a.z >= 0.f) ? a.z : SLOPE * a.z;
        a.w = (a.w >= 0.f) ? a.w : SLOPE * a.w;
        s = wred(n2_4(a)); nn = fmaxf(sqrtf(s), MINN); sc = tfast(nn) / nn; mul4(a, sc);
        s = wred(n2_4(a)); nn = fmaxf(sqrtf(s), MINN); if (nn > PMAX) mul4(a, PMAX / nn);
        s = wred(n2_4(a)); nn = fmaxf(sqrtf(s), MINN); if (nn > PMAX) mul4(a, PMAX / nn);
        ((float4*)out)[node * 32 + lane] = a;
    }
}

__global__ void k_agg64(const float* __restrict__ xt, float* __restrict__ out, int n) {
    int t = threadIdx.x, warp = t >> 5, lane = t & 31;
    const float2* base = (const float2*)xt;
    for (int node = blockIdx.x * WPB + warp; node < n; node += gridDim.x * WPB) {
        float dn = g_dis[node];
        float2 a = base[node * 32 + lane];
        float ws = dn * dn;
        a.x *= ws; a.y *= ws;
        int e1 = g_off[node + 1];
        for (int e = g_off[node]; e < e1; e++) {
            int c = g_csr[e];
            float w = dn * g_dis[c];
            float2 v = base[c * 32 + lane];
            a.x += w * v.x; a.y += w * v.y;
        }
        float s, nn, sc;
        s = wred(a.x * a.x + a.y * a.y); nn = fmaxf(sqrtf(s), MINN); sc = tfast(nn) / nn; a.x *= sc; a.y *= sc;
        s = wred(a.x * a.x + a.y * a.y); nn = fmaxf(sqrtf(s), MINN); if (nn > PMAX) { sc = PMAX / nn; a.x *= sc; a.y *= sc; }
        s = wred(a.x * a.x + a.y * a.y); nn = fmaxf(sqrtf(s), MINN); sc = artanhf_(nn) / nn; a.x *= sc; a.y *= sc;
        a.x = (a.x >= 0.f) ? a.x : SLOPE * a.x;
        a.y = (a.y >= 0.f) ? a.y : SLOPE * a.y;
        s = wred(a.x * a.x + a.y * a.y); nn = fmaxf(sqrtf(s), MINN); sc = tfast(nn) / nn; a.x *= sc; a.y *= sc;
        s = wred(a.x * a.x + a.y * a.y); nn = fmaxf(sqrtf(s), MINN); if (nn > PMAX) { sc = PMAX / nn; a.x *= sc; a.y *= sc; }
        s = wred(a.x * a.x + a.y * a.y); nn = fmaxf(sqrtf(s), MINN); sc = artanhf_(nn) / nn; a.x *= sc; a.y *= sc;
        ((float2*)out)[node * 32 + lane] = a;
    }
}

// ---------------- HTA window attention (WIN=5 specialized, FFMA2) ----------------
__global__ __launch_bounds__(TPB) void k_att5(const float* __restrict__ hiddens, const float* __restrict__ Q,
                                              const float* __restrict__ ratt, int n) {
    __shared__ ulonglong2 wq[32 * 32];    // 16KB: k2-major, per-lane pair (j, j+32)
    __shared__ ull sxs[WPB * 5 * 64];     // 20KB dup hlog
    __shared__ float shr[64];
    int t = threadIdx.x;
    for (int idx = t; idx < 32 * 32; idx += TPB) {
        int k2 = idx >> 5, j = idx & 31;
        float4 v;
        v.x = Q[(2 * k2) * 64 + j];
        v.y = Q[(2 * k2) * 64 + j + 32];
        v.z = Q[(2 * k2 + 1) * 64 + j];
        v.w = Q[(2 * k2 + 1) * 64 + j + 32];
        ((float4*)wq)[idx] = v;
    }
    if (t < 64) shr[t] = ratt[t];
    __syncthreads();
    int warp = t >> 5, lane = t & 31;
    ull* sxw = sxs + warp * 5 * 64;
    const ulonglong2* sxu = (const ulonglong2*)sxw;
    const float inv5 = 0.2f;
    for (int node = blockIdx.x * WPB + warp; node < n; node += gridDim.x * WPB) {
        float hl0[5], hl1[5], ew[5];
#pragma unroll
        for (int w = 0; w < 5; w++) {
            size_t off = ((size_t)w * n + node) * 64;
            float v0 = hiddens[off + lane];
            float v1 = hiddens[off + lane + 32];
            float s = wred(v0 * v0 + v1 * v1);
            float pn = fmaxf(sqrtf(s), MINN);
            float sc = artanhf_(pn) / pn;
            v0 *= sc; v1 *= sc;
            hl0[w] = v0; hl1[w] = v1;
            sxw[w * 64 + lane] = fdup(v0);
            sxw[w * 64 + lane + 32] = fdup(v1);
        }
        __syncwarp();
        ull acc[5] = {0ull, 0ull, 0ull, 0ull, 0ull};
#pragma unroll 4
        for (int k2 = 0; k2 < 32; k2++) {
            ulonglong2 q = wq[k2 * 32 + lane];
#pragma unroll
            for (int w = 0; w < 5; w++) {
                ulonglong2 xd = sxu[w * 32 + k2];
                ffma2(acc[w], q.x, xd.x);
                ffma2(acc[w], q.y, xd.y);
            }
        }
#pragma unroll
        for (int w = 0; w < 5; w++) {
            float2 f = funpack(acc[w]);
            float ep = tfast(f.x) * shr[lane] + tfast(f.y) * shr[lane + 32];
            ew[w] = wred(ep);
        }
        float m = -1e30f;
#pragma unroll
        for (int w = 0; w < 5; w++) m = fmaxf(m, ew[w]);
        float ssum = 0.f;
#pragma unroll
        for (int w = 0; w < 5; w++) { ew[w] = __expf(ew[w] - m); ssum += ew[w]; }
        float inv = inv5 / ssum;
        float o0 = 0.f, o1 = 0.f;
#pragma unroll
        for (int w = 0; w < 5; w++) { o0 += ew[w] * hl0[w]; o1 += ew[w] * hl1[w]; }
        g_hatt[node * 64 + lane]      = o0 * inv;
        g_hatt[node * 64 + lane + 32] = o1 * inv;
        __syncwarp();
    }
}

// generic fallback (win != 5)
__global__ void k_att(const float* __restrict__ hiddens, const float* __restrict__ Q,
                      const float* __restrict__ ratt, int n, int win) {
    __shared__ float shQ[64 * 64];
    __shared__ float shr[64];
    __shared__ float shh[WPB][64];
    int t = threadIdx.x;
    for (int idx = t; idx < 64 * 64; idx += TPB) shQ[idx] = Q[idx];
    if (t < 64) shr[t] = ratt[t];
    __syncthreads();
    int warp = t >> 5, lane = t & 31;
    float invwin = 1.0f / (float)win;
    for (int node = blockIdx.x * WPB + warp; node < n; node += gridDim.x * WPB) {
        float hl0[8], hl1[8], ew[8];
        for (int w = 0; w < win; w++) {
            size_t off = ((size_t)w * n + node) * 64;
            float v0 = hiddens[off + lane];
            float v1 = hiddens[off + lane + 32];
            float s = wred(v0 * v0 + v1 * v1);
            float pn = fmaxf(sqrtf(s), MINN);
            float sc = artanhf_(pn) / pn;
            v0 *= sc; v1 *= sc;
            hl0[w] = v0; hl1[w] = v1;
            shh[warp][lane] = v0; shh[warp][lane + 32] = v1;
            __syncwarp();
            float ep = 0.f;
#pragma unroll
            for (int g = 0; g < 2; g++) {
                int j = lane + 32 * g;
                float a = 0.f;
                for (int k = 0; k < 64; k++) a += shh[warp][k] * shQ[k * 64 + j];
                ep += tfast(a) * shr[j];
            }
            ew[w] = wred(ep);
            __syncwarp();
        }
        float m = -1e30f;
        for (int w = 0; w < win; w++) m = fmaxf(m, ew[w]);
        float ssum = 0.f;
        for (int w = 0; w < win; w++) { ew[w] = __expf(ew[w] - m); ssum += ew[w]; }
        float inv = invwin / ssum;
        float o0 = 0.f, o1 = 0.f;
        for (int w = 0; w < win; w++) { o0 += ew[w] * hl0[w]; o1 += ew[w] * hl1[w]; }
        g_hatt[node * 64 + lane]      = o0 * inv;
        g_hatt[node * 64 + lane + 32] = o1 * inv;
    }
}

// ---------------- GRU (FFMA2, 8-node blocking) + final expmap0/proj ----------------
__global__ __launch_bounds__(TPB) void k_gru2(const float* __restrict__ Wih, const float* __restrict__ Whh,
                                              const float* __restrict__ bih, const float* __restrict__ bhh,
                                              float* __restrict__ outp, int n) {
    extern __shared__ unsigned char smraw[];
    ulonglong2* wqi = (ulonglong2*)smraw;                      // 3*32*32
    ulonglong2* wqh = (ulonglong2*)(smraw + 49152);            // 3*32*32
    ull* sxx = (ull*)(smraw + 98304);                          // WPB*8*64
    ull* sxh = (ull*)(smraw + 131072);                         // WPB*8*64
    float* sbi = (float*)(smraw + 163840);                     // 192
    float* sbh = (float*)(smraw + 164608);                     // 192
    int t = threadIdx.x;
    for (int idx = t; idx < 3 * 32 * 32; idx += TPB) {
        int p = idx >> 10; int r = idx & 1023; int k2 = r >> 5; int j = r & 31;
        float4 vi, vh;
        vi.x = Wih[(p * 64 + j) * 64 + 2 * k2];
        vi.y = Wih[(p * 64 + j + 32) * 64 + 2 * k2];
        vi.z = Wih[(p * 64 + j) * 64 + 2 * k2 + 1];
        vi.w = Wih[(p * 64 + j + 32) * 64 + 2 * k2 + 1];
        vh.x = Whh[(p * 64 + j) * 64 + 2 * k2];
        vh.y = Whh[(p * 64 + j + 32) * 64 + 2 * k2];
        vh.z = Whh[(p * 64 + j) * 64 + 2 * k2 + 1];
        vh.w = Whh[(p * 64 + j + 32) * 64 + 2 * k2 + 1];
        ((float4*)wqi)[idx] = vi;
        ((float4*)wqh)[idx] = vh;
    }
    if (t < 192) { sbi[t] = bih[t]; sbh[t] = bhh[t]; }
    __syncthreads();
    int warp = t >> 5, lane = t & 31;
    ull* sxxw = sxx + warp * 512;
    ull* sxhw = sxh + warp * 512;
    const ulonglong2* sxxu = (const ulonglong2*)sxxw;
    const ulonglong2* sxhu = (const ulonglong2*)sxhw;
    int ngrp = (n + 7) >> 3;
    for (int grp = blockIdx.x * WPB + warp; grp < ngrp; grp += gridDim.x * WPB) {
        int base = grp * 8;
        float h0r[8], h1r[8];
#pragma unroll
        for (int m = 0; m < 8; m++) {
            int nm = min(base + m, n - 1);
            float x0 = g_xtf[nm * 64 + lane], x1 = g_xtf[nm * 64 + lane + 32];
            float h0 = g_hatt[nm * 64 + lane], h1 = g_hatt[nm * 64 + lane + 32];
            sxxw[m * 64 + lane] = fdup(x0);
            sxxw[m * 64 + lane + 32] = fdup(x1);
            sxhw[m * 64 + lane] = fdup(h0);
            sxhw[m * 64 + lane + 32] = fdup(h1);
            h0r[m] = h0; h1r[m] = h1;
        }
        __syncwarp();
        ull gi[8][3], gh[8][3];
#pragma unroll
        for (int m = 0; m < 8; m++)
#pragma unroll
            for (int p = 0; p < 3; p++) { gi[m][p] = 0ull; gh[m][p] = 0ull; }
#pragma unroll 1
        for (int k2 = 0; k2 < 32; k2++) {
            ulonglong2 qi[3], qh[3];
#pragma unroll
            for (int p = 0; p < 3; p++) {
                qi[p] = wqi[p * 1024 + k2 * 32 + lane];
                qh[p] = wqh[p * 1024 + k2 * 32 + lane];
            }
#pragma unroll
            for (int m = 0; m < 8; m++) {
                ulonglong2 xd = sxxu[m * 32 + k2];
                ulonglong2 hd = sxhu[m * 32 + k2];
#pragma unroll
                for (int p = 0; p < 3; p++) {
                    ffma2(gi[m][p], qi[p].x, xd.x);
                    ffma2(gi[m][p], qi[p].y, xd.y);
                    ffma2(gh[m][p], qh[p].x, hd.x);
                    ffma2(gh[m][p], qh[p].y, hd.y);
                }
            }
        }
#pragma unroll
        for (int m = 0; m < 8; m++) {
            int nm = base + m;
            float2 i0 = funpack(gi[m][0]), i1 = funpack(gi[m][1]), i2 = funpack(gi[m][2]);
            float2 hh0 = funpack(gh[m][0]), hh1 = funpack(gh[m][1]), hh2 = funpack(gh[m][2]);
            float ir0 = i0.x + sbi[lane],        ir1 = i0.y + sbi[lane + 32];
            float iz0 = i1.x + sbi[lane + 64],   iz1 = i1.y + sbi[lane + 96];
            float in0 = i2.x + sbi[lane + 128],  in1 = i2.y + sbi[lane + 160];
            float hr0 = hh0.x + sbh[lane],       hr1 = hh0.y + sbh[lane + 32];
            float hz0 = hh1.x + sbh[lane + 64],  hz1 = hh1.y + sbh[lane + 96];
            float hn0 = hh2.x + sbh[lane + 128], hn1 = hh2.y + sbh[lane + 160];
            float r0 = sigf(ir0 + hr0), r1 = sigf(ir1 + hr1);
            float z0 = sigf(iz0 + hz0), z1 = sigf(iz1 + hz1);
            float n0 = tfast(in0 + r0 * hn0), n1 = tfast(in1 + r1 * hn1);
            float o0 = (1.f - z0) * n0 + z0 * h0r[m];
            float o1 = (1.f - z1) * n1 + z1 * h1r[m];
            float s = wred(o0 * o0 + o1 * o1);
            float nn = fmaxf(sqrtf(s), MINN);
            float sc = tfast(nn) / nn; o0 *= sc; o1 *= sc;
            s = wred(o0 * o0 + o1 * o1);
            nn = fmaxf(sqrtf(s), MINN);
            if (nn > PMAX) { sc = PMAX / nn; o0 *= sc; o1 *= sc; }
            if (nm < n) {
                outp[nm * 64 + lane]      = o0;
                outp[nm * 64 + lane + 32] = o1;
            }
        }
        __syncwarp();
    }
}

// ---------------- launch ----------------
extern "C" void kernel_launch(void* const* d_in, const int* in_sizes, int n_in,
                              void* d_out, int out_size) {
    const int*   eidx = (const int*)  d_in[0];
    const float* feat = (const float*)d_in[1];
    const float* Wl   = (const float*)d_in[2];
    const float* bl   = (const float*)d_in[3];
    const float* W1   = (const float*)d_in[4];
    const float* b1   = (const float*)d_in[5];
    const float* W2   = (const float*)d_in[6];
    const float* b2   = (const float*)d_in[7];
    const float* Q    = (const float*)d_in[8];
    const float* ratt = (const float*)d_in[9];
    const float* Wih  = (const float*)d_in[10];
    const float* Whh  = (const float*)d_in[11];
    const float* bih  = (const float*)d_in[12];
    const float* bhh  = (const float*)d_in[13];
    const float* hidd = (const float*)d_in[14];
    float* outp = (float*)d_out;

    int E = in_sizes[0] / 2;
    int N = in_sizes[1] / 128;
    int WIN = in_sizes[14] / (N * 64);
    if (N > NMAX || E > EMAX) return;
    const int* src = eidx;
    const int* dst = eidx + E;

    float *p_xcat, *p_xt, *p_x2, *p_xtf, *p_hb1, *p_hb2;
    cudaGetSymbolAddress((void**)&p_xcat, g_xcat);
    cudaGetSymbolAddress((void**)&p_xt,   g_xt);
    cudaGetSymbolAddress((void**)&p_x2,   g_x2);
    cudaGetSymbolAddress((void**)&p_xtf,  g_xtf);
    cudaGetSymbolAddress((void**)&p_hb1,  g_hb1);
    cudaGetSymbolAddress((void**)&p_hb2,  g_hb2);

    // side stream + fork/join events (created once on first, non-capture call)
    static cudaStream_t s_att = nullptr;
    static cudaEvent_t  ev_fork = nullptr, ev_join = nullptr;
    if (s_att == nullptr) {
        cudaStreamCreateWithFlags(&s_att, cudaStreamNonBlocking);
        cudaEventCreateWithFlags(&ev_fork, cudaEventDisableTiming);
        cudaEventCreateWithFlags(&ev_join, cudaEventDisableTiming);
    }

    const int SMI  = 64 * 32 * 16 + WPB * 4 * 128 * 8 + 64 * 4;            // 65792
    const int SML1 = 2 * 64 * 32 * 16 + WPB * 4 * 128 * 8 + 128 * 4;       // 98816
    const int SML2 = 64 * 32 * 16 + WPB * 4 * 128 * 8 + 64 * 4;            // 65792
    const int SMG  = 2 * 49152 + 2 * WPB * 8 * 64 * 8 + 2 * 192 * 4;       // 165376
    cudaFuncSetAttribute(k_init2,   cudaFuncAttributeMaxDynamicSharedMemorySize, SMI);
    cudaFuncSetAttribute(k_lin<2>,  cudaFuncAttributeMaxDynamicSharedMemorySize, SML1);
    cudaFuncSetAttribute(k_lin<1>,  cudaFuncAttributeMaxDynamicSharedMemorySize, SML2);
    cudaFuncSetAttribute(k_gru2,    cudaFuncAttributeMaxDynamicSharedMemorySize, SMG);

    int eb = (E + 255) / 256;
    int nb = (N + 255) / 256;
    int NB = (N + 1023) / 1024;

    // fork: attention runs concurrently on side stream (depends only on inputs)
    cudaEventRecord(ev_fork, 0);
    cudaStreamWaitEvent(s_att, ev_fork, 0);
    if (WIN == 5) k_att5<<<592, TPB, 0, s_att>>>(hidd, Q, ratt, N);
    else          k_att<<<1184, TPB, 0, s_att>>>(hidd, Q, ratt, N, WIN);
    cudaEventRecord(ev_join, s_att);

    // main chain
    k_bias<<<1, 128>>>(b1, b2);
    k_init2<<<444, TPB, SMI>>>(feat, Wl, bl, hidd + (size_t)(WIN - 1) * N * 64, N);
    k_zero2<<<nb, 256>>>(N);
    k_lin<2><<<296, TPB, SML1>>>(p_xcat, W1, p_hb1, p_xt, N);   // position ~3: gets profiled by ncu
    k_count<<<eb, 256>>>(src, E);
    k_scan1<<<NB, 1024>>>(N);
    k_scan2<<<1, 128>>>(NB);
    k_scan3<<<nb, 256>>>(N, E);
    k_dis<<<nb, 256>>>(N);
    k_fill<<<eb, 256>>>(src, dst, E);
    k_agg128<<<1184, TPB>>>(p_xt, p_x2, N);
    k_lin<1><<<444, TPB, SML2>>>(p_x2, W2, p_hb2, p_xt, N);
    k_agg64<<<1184, TPB>>>(p_xt, p_xtf, N);

    // join: gru needs g_hatt from attention branch
    cudaStreamWaitEvent(0, ev_join, 0);
    k_gru2<<<148, TPB, SMG>>>(Wih, Whh, bih, bhh, outp, N);
}

// round 13
// speedup vs baseline: 1.6070x; 1.0508x over previous
#include <cuda_runtime.h>
#include <math.h>

#define MINN  1e-15f
#define PMAX  0.996f      // (1 - 4e-3)/sqrt(c), c=1
#define SLOPE 0.01f

constexpr int NMAX = 100000;
constexpr int EMAX = 800000;
constexpr int WPB  = 8;          // warps per block
constexpr int TPB  = WPB * 32;   // 256 threads

// ---------------- scratch (static device globals; no allocation) ----------------
__device__ float g_xcat[NMAX * 128];
__device__ float g_xt  [NMAX * 128];
__device__ float g_x2  [NMAX * 128];
__device__ float g_xtf [NMAX * 64];
__device__ float g_hatt[NMAX * 64];
__device__ float g_dis [NMAX];
__device__ int   g_cnt [NMAX];
__device__ int   g_cur [NMAX];
__device__ int   g_off [NMAX + 1];
__device__ int   g_bsum[128];
__device__ int   g_csr [EMAX];
__device__ float g_hb1 [128];
__device__ float g_hb2 [64];

typedef unsigned long long ull;

// ---------------- helpers ----------------
__device__ __forceinline__ float wred(float v) {
#pragma unroll
    for (int o = 16; o; o >>= 1) v += __shfl_xor_sync(0xffffffffu, v, o);
    return v;
}
// fast artanh: poly for |x|<0.25 (rel err <1e-7), MUFU log otherwise (rel err <5e-7)
__device__ __forceinline__ float artanhf_(float x) {
    x = fminf(fmaxf(x, -1.0f + 1e-7f), 1.0f - 1e-7f);
    float x2 = x * x;
    float ser = x * (1.0f + x2 * (0.33333334f + x2 * (0.2f + x2 * (0.14285715f + x2 * 0.11111111f))));
    float lg  = 0.5f * __logf(__fdividef(1.0f + x, 1.0f - x));
    return (x2 < 0.0625f) ? ser : lg;
}
// fast tanh via MUFU ex2 (~1e-6 rel)
__device__ __forceinline__ float tfast(float x) {
    float ax = fabsf(x);
    float t = __expf(-2.0f * ax);
    float r = __fdividef(1.0f - t, 1.0f + t);
    return copysignf(r, x);
}
__device__ __forceinline__ float sigf(float x) {
    return __fdividef(1.0f, 1.0f + __expf(-x));
}
// packed f32x2 ops (sm_103a FFMA2 path)
__device__ __forceinline__ ull fdup(float v) {
    ull d; asm("mov.b64 %0, {%1, %1};" : "=l"(d) : "f"(v)); return d;
}
__device__ __forceinline__ void ffma2(ull& d, ull a, ull b) {
    asm("fma.rn.f32x2 %0, %1, %2, %0;" : "+l"(d) : "l"(a), "l"(b));
}
__device__ __forceinline__ float2 funpack(ull d) {
    float2 r; asm("mov.b64 {%0, %1}, %2;" : "=f"(r.x), "=f"(r.y) : "l"(d)); return r;
}

// ---------------- hyperbolic bias precompute ----------------
__device__ __forceinline__ float blk_red128(float v, float* sh) {
    int t = threadIdx.x;
    sh[t] = v; __syncthreads();
    for (int s = 64; s > 0; s >>= 1) { if (t < s) sh[t] += sh[t + s]; __syncthreads(); }
    float r = sh[0]; __syncthreads();
    return r;
}

__global__ void k_bias(const float* __restrict__ b1, const float* __restrict__ b2) {
    __shared__ float sh[128];
    int t = threadIdx.x;
    float v = b1[t];
    float n2 = blk_red128(v * v, sh);
    float nn = fmaxf(sqrtf(n2), MINN);
    float u = tanhf(nn) / nn * v;
    float pu2 = blk_red128(u * u, sh);
    float pn = fmaxf(sqrtf(pu2), MINN);
    if (pn > PMAX) u *= PMAX / pn;
    g_hb1[t] = u;
    float v2 = (t < 64) ? b2[t] : 0.f;
    float m2 = blk_red128(v2 * v2, sh);
    float mn = fmaxf(sqrtf(m2), MINN);
    float u2 = tanhf(mn) / mn * v2;
    float q2 = blk_red128(u2 * u2, sh);
    float qn = fmaxf(sqrtf(q2), MINN);
    if (qn > PMAX) u2 *= PMAX / qn;
    if (t < 64) g_hb2[t] = u2;
}

// ---------------- init: x = feat@Wl.T + bl ; expmap0 ; proj ; concat hidden ; proj ----------------
// FFMA2 + 4-node blocking (unchanged from R9 best).
__global__ __launch_bounds__(TPB) void k_init2(const float* __restrict__ feat, const float* __restrict__ Wl,
                                               const float* __restrict__ bl, const float* __restrict__ hidlast, int n) {
    extern __shared__ unsigned char smraw[];
    ulonglong2* wq = (ulonglong2*)smraw;                              // 64 k2 * 32 lanes
    ull* sx = (ull*)(smraw + 64 * 32 * 16);                           // WPB * 4 * 128
    float* shb = (float*)(smraw + 64 * 32 * 16 + WPB * 4 * 128 * 8);  // 64
    int t = threadIdx.x;
    for (int idx = t; idx < 64 * 32; idx += TPB) {
        int k2 = idx >> 5, j = idx & 31;
        float4 v;
        v.x = Wl[j * 128 + 2 * k2];
        v.y = Wl[(j + 32) * 128 + 2 * k2];
        v.z = Wl[j * 128 + 2 * k2 + 1];
        v.w = Wl[(j + 32) * 128 + 2 * k2 + 1];
        ((float4*)wq)[idx] = v;
    }
    if (t < 64) shb[t] = bl[t];
    __syncthreads();
    int warp = t >> 5, lane = t & 31;
    ull* sxw = sx + warp * 512;
    const ulonglong2* sxu = (const ulonglong2*)sxw;
    int ngrp = (n + 3) >> 2;
    for (int grp = blockIdx.x * WPB + warp; grp < ngrp; grp += gridDim.x * WPB) {
        int base = grp * 4;
#pragma unroll
        for (int m = 0; m < 4; m++) {
            int nm = min(base + m, n - 1);
            float4 f = ((const float4*)feat)[nm * 32 + lane];
            ulonglong2 d0, d1;
            d0.x = fdup(f.x); d0.y = fdup(f.y); d1.x = fdup(f.z); d1.y = fdup(f.w);
            ((ulonglong2*)(sxw + m * 128))[lane * 2] = d0;
            ((ulonglong2*)(sxw + m * 128))[lane * 2 + 1] = d1;
        }
        __syncwarp();
        ull acc[4] = {0ull, 0ull, 0ull, 0ull};
#pragma unroll 4
        for (int k2 = 0; k2 < 64; k2++) {
            ulonglong2 q = wq[k2 * 32 + lane];
#pragma unroll
            for (int m = 0; m < 4; m++) {
                ulonglong2 xd = sxu[m * 64 + k2];
                ffma2(acc[m], q.x, xd.x);
                ffma2(acc[m], q.y, xd.y);
            }
        }
#pragma unroll
        for (int m = 0; m < 4; m++) {
            int nm = base + m;
            float2 av = funpack(acc[m]);
            float a0 = av.x + shb[lane], a1 = av.y + shb[lane + 32];
            // expmap0
            float s = wred(a0 * a0 + a1 * a1);
            float nn = fmaxf(sqrtf(s), MINN);
            float sc = tfast(nn) / nn; a0 *= sc; a1 *= sc;
            // proj (64-dim)
            s = wred(a0 * a0 + a1 * a1);
            nn = fmaxf(sqrtf(s), MINN);
            if (nn > PMAX) { sc = PMAX / nn; a0 *= sc; a1 *= sc; }
            // concat hidden, proj over 128 dims
            int nmc = min(nm, n - 1);
            float h0 = hidlast[nmc * 64 + lane];
            float h1 = hidlast[nmc * 64 + lane + 32];
            s = wred(a0 * a0 + a1 * a1 + h0 * h0 + h1 * h1);
            nn = fmaxf(sqrtf(s), MINN);
            if (nn > PMAX) { sc = PMAX / nn; a0 *= sc; a1 *= sc; h0 *= sc; h1 *= sc; }
            if (nm < n) {
                g_xcat[nm * 128 + lane]      = a0;
                g_xcat[nm * 128 + lane + 32] = a1;
                g_xcat[nm * 128 + lane + 64] = h0;
                g_xcat[nm * 128 + lane + 96] = h1;
            }
        }
        __syncwarp();
    }
}

// ---------------- CSR build ----------------
__global__ void k_zero2(int n) {
    int i = blockIdx.x * blockDim.x + threadIdx.x;
    if (i < n) { g_cnt[i] = 0; g_cur[i] = 0; }
}
__global__ void k_count(const int* __restrict__ src, int e) {
    int i = blockIdx.x * blockDim.x + threadIdx.x;
    if (i < e) atomicAdd(&g_cnt[src[i]], 1);
}
__global__ void k_scan1(int n) {
    __shared__ int sh[1024];
    int t = threadIdx.x;
    int i = blockIdx.x * 1024 + t;
    int v = (i < n) ? g_cnt[i] : 0;
    sh[t] = v; __syncthreads();
    for (int d = 1; d < 1024; d <<= 1) {
        int x = (t >= d) ? sh[t - d] : 0;
        __syncthreads();
        sh[t] += x; __syncthreads();
    }
    if (i < n) g_off[i] = sh[t] - v;
    if (t == 1023) g_bsum[blockIdx.x] = sh[1023];
}
__global__ void k_scan2(int nb) {
    __shared__ int sh[128];
    int t = threadIdx.x;
    int v = (t < nb) ? g_bsum[t] : 0;
    sh[t] = v; __syncthreads();
    for (int d = 1; d < 128; d <<= 1) {
        int x = (t >= d) ? sh[t - d] : 0;
        __syncthreads();
        sh[t] += x; __syncthreads();
    }
    g_bsum[t] = sh[t] - v;
}
__global__ void k_scan3(int n, int e) {
    int i = blockIdx.x * blockDim.x + threadIdx.x;
    if (i < n) g_off[i] += g_bsum[i >> 10];
    if (i == 0) g_off[n] = e;
}
__global__ void k_dis(int n) {
    int i = blockIdx.x * blockDim.x + threadIdx.x;
    if (i < n) g_dis[i] = rsqrtf((float)(g_cnt[i] + 1));
}
__global__ void k_fill(const int* __restrict__ src, const int* __restrict__ dst, int e) {
    int i = blockIdx.x * blockDim.x + threadIdx.x;
    if (i < e) {
        int s = src[i];
        int p = g_off[s] + atomicAdd(&g_cur[s], 1);
        g_csr[p] = dst[i];
    }
}

// ---------------- hyp_linear (k-paired FFMA2, 4-node blocking, no x duplication) ----------------
// wq[p][k2][lane] = ulonglong2{ (W[j,2k2],W[j,2k2+1]), (W[j+32,2k2],W[j+32,2k2+1]) }, j=p*64+lane
// x stored natural float4; xp = (x[4k4],x[4k4+1]),(x[4k4+2],x[4k4+3]) broadcast.
// accA[m][p] = even/odd-k partials for out j=p*64+lane; accB for j=p*64+lane+32.
template <int P>
__global__ __launch_bounds__(TPB) void k_lin(const float* __restrict__ xin, const float* __restrict__ W,
                                             const float* __restrict__ hb, float* __restrict__ xtout, int n) {
    extern __shared__ unsigned char smraw[];
    ulonglong2* wq = (ulonglong2*)smraw;                                    // P*64*32
    float4* sxf = (float4*)(smraw + P * 64 * 32 * 16);                      // WPB*4*32 float4
    float* shb = (float*)(smraw + P * 64 * 32 * 16 + WPB * 4 * 32 * 16);    // 64*P
    int t = threadIdx.x;
    for (int idx = t; idx < P * 64 * 32; idx += TPB) {
        int p = idx >> 11; int r = idx & 2047; int k2 = r >> 5; int j = r & 31;
        float4 v;
        v.x = W[(p * 64 + j) * 128 + 2 * k2];
        v.y = W[(p * 64 + j) * 128 + 2 * k2 + 1];
        v.z = W[(p * 64 + j + 32) * 128 + 2 * k2];
        v.w = W[(p * 64 + j + 32) * 128 + 2 * k2 + 1];
        ((float4*)wq)[idx] = v;
    }
    for (int idx = t; idx < 64 * P; idx += TPB) shb[idx] = hb[idx];
    __syncthreads();
    int warp = t >> 5, lane = t & 31;
    float4* sxw = sxf + warp * 128;                     // 4 nodes * 32 float4
    const ulonglong2* sxu = (const ulonglong2*)sxw;     // [m*32 + k4]
    constexpr int VO = 2 * P;
    int ngrp = (n + 3) >> 2;
    for (int grp = blockIdx.x * WPB + warp; grp < ngrp; grp += gridDim.x * WPB) {
        int base = grp * 4;
        float xn[4];
#pragma unroll
        for (int m = 0; m < 4; m++) {
            int nm = min(base + m, n - 1);
            float4 f = ((const float4*)xin)[nm * 32 + lane];
            sxw[m * 32 + lane] = f;
            float xs = f.x * f.x + f.y * f.y + f.z * f.z + f.w * f.w;
            xn[m] = fmaxf(sqrtf(wred(xs)), MINN);
        }
        __syncwarp();
        ull accA[4][P], accB[4][P];
#pragma unroll
        for (int m = 0; m < 4; m++)
#pragma unroll
            for (int p = 0; p < P; p++) { accA[m][p] = 0ull; accB[m][p] = 0ull; }
#pragma unroll 2
        for (int k4 = 0; k4 < 32; k4++) {
            ulonglong2 wwa[P], wwb[P];
#pragma unroll
            for (int p = 0; p < P; p++) {
                wwa[p] = wq[p * 2048 + (2 * k4) * 32 + lane];
                wwb[p] = wq[p * 2048 + (2 * k4 + 1) * 32 + lane];
            }
#pragma unroll
            for (int m = 0; m < 4; m++) {
                ulonglong2 xp = sxu[m * 32 + k4];       // broadcast: 4 distinct x per 16B
#pragma unroll
                for (int p = 0; p < P; p++) {
                    ffma2(accA[m][p], wwa[p].x, xp.x);
                    ffma2(accB[m][p], wwa[p].y, xp.x);
                    ffma2(accA[m][p], wwb[p].x, xp.y);
                    ffma2(accB[m][p], wwb[p].y, xp.y);
                }
            }
        }
#pragma unroll
        for (int m = 0; m < 4; m++) {
            int nm = base + m;
            float v[VO];
#pragma unroll
            for (int p = 0; p < P; p++) {
                float2 fA = funpack(accA[m][p]);
                float2 fB = funpack(accB[m][p]);
                v[2 * p]     = fA.x + fA.y;
                v[2 * p + 1] = fB.x + fB.y;
            }
            float ms = 0.f;
#pragma unroll
            for (int g = 0; g < VO; g++) ms += v[g] * v[g];
            float mxn2 = wred(ms);
            float mxn = fmaxf(sqrtf(mxn2), MINN);
            float xnn = xn[m];
            float r = tfast(mxn / xnn * artanhf_(xnn)) / mxn;
            if (mxn2 == 0.f) r = 0.f;
#pragma unroll
            for (int g = 0; g < VO; g++) v[g] *= r;
            // proj
            float s = 0.f;
#pragma unroll
            for (int g = 0; g < VO; g++) s += v[g] * v[g];
            s = wred(s);
            float pn = fmaxf(sqrtf(s), MINN);
            if (pn > PMAX) { float f = PMAX / pn;
#pragma unroll
                for (int g = 0; g < VO; g++) v[g] *= f; }
            // mobius_add(v, hb)
            float hx[VO];
            float xx = 0.f, xy = 0.f, yy = 0.f;
#pragma unroll
            for (int g = 0; g < VO; g++) {
                float hv = shb[lane + 32 * g];
                hx[g] = hv;
                xx += v[g] * v[g];
                xy += v[g] * hv;
                yy += hv * hv;
            }
            xx = wred(xx); xy = wred(xy); yy = wred(yy);
            float den = fmaxf(1.f + 2.f * xy + xx * yy, MINN);
            float ca = (1.f + 2.f * xy + yy) / den;
            float cb = (1.f - xx) / den;
#pragma unroll
            for (int g = 0; g < VO; g++) v[g] = ca * v[g] + cb * hx[g];
            // proj
            s = 0.f;
#pragma unroll
            for (int g = 0; g < VO; g++) s += v[g] * v[g];
            s = wred(s);
            pn = fmaxf(sqrtf(s), MINN);
            if (pn > PMAX) { float f = PMAX / pn;
#pragma unroll
                for (int g = 0; g < VO; g++) v[g] *= f; }
            // logmap0
            s = 0.f;
#pragma unroll
            for (int g = 0; g < VO; g++) s += v[g] * v[g];
            s = wred(s);
            pn = fmaxf(sqrtf(s), MINN);
            float a = artanhf_(pn) / pn;
            if (nm < n) {
#pragma unroll
                for (int g = 0; g < VO; g++) xtout[nm * (64 * P) + lane + 32 * g] = v[g] * a;
            }
        }
        __syncwarp();
    }
}

// ---------------- aggregation (CSR gather) + activation chain ----------------
__device__ __forceinline__ float n2_4(float4 a) { return a.x * a.x + a.y * a.y + a.z * a.z + a.w * a.w; }
__device__ __forceinline__ void  mul4(float4& a, float s) { a.x *= s; a.y *= s; a.z *= s; a.w *= s; }

__global__ void k_agg128(const float* __restrict__ xt, float* __restrict__ out, int n) {
    int t = threadIdx.x, warp = t >> 5, lane = t & 31;
    const float4* base = (const float4*)xt;
    for (int node = blockIdx.x * WPB + warp; node < n; node += gridDim.x * WPB) {
        float dn = g_dis[node];
        float4 a = base[node * 32 + lane];
        mul4(a, dn * dn);
        int e1 = g_off[node + 1];
        for (int e = g_off[node]; e < e1; e++) {
            int c = g_csr[e];
            float w = dn * g_dis[c];
            float4 v = base[c * 32 + lane];
            a.x += w * v.x; a.y += w * v.y; a.z += w * v.z; a.w += w * v.w;
        }
        float s, nn, sc;
        s = wred(n2_4(a)); nn = fmaxf(sqrtf(s), MINN); sc = tfast(nn) / nn; mul4(a, sc);
        s = wred(n2_4(a)); nn = fmaxf(sqrtf(s), MINN); if (nn > PMAX) mul4(a, PMAX / nn);
        s = wred(n2_4(a)); nn = fmaxf(sqrtf(s), MINN); sc = artanhf_(nn) / nn; mul4(a, sc);
        a.x = (a.x >= 0.f) ? a.x : SLOPE * a.x;
        a.y = (a.y >= 0.f) ? a.y : SLOPE * a.y;
        a.z = (a.z >= 0.f) ? a.z : SLOPE * a.z;
        a.w = (a.w >= 0.f) ? a.w : SLOPE * a.w;
        s = wred(n2_4(a)); nn = fmaxf(sqrtf(s), MINN); sc = tfast(nn) / nn; mul4(a, sc);
        s = wred(n2_4(a)); nn = fmaxf(sqrtf(s), MINN); if (nn > PMAX) mul4(a, PMAX / nn);
        s = wred(n2_4(a)); nn = fmaxf(sqrtf(s), MINN); if (nn > PMAX) mul4(a, PMAX / nn);
        ((float4*)out)[node * 32 + lane] = a;
    }
}

__global__ void k_agg64(const float* __restrict__ xt, float* __restrict__ out, int n) {
    int t = threadIdx.x, warp = t >> 5, lane = t & 31;
    const float2* base = (const float2*)xt;
    for (int node = blockIdx.x * WPB + warp; node < n; node += gridDim.x * WPB) {
        float dn = g_dis[node];
        float2 a = base[node * 32 + lane];
        float ws = dn * dn;
        a.x *= ws; a.y *= ws;
        int e1 = g_off[node + 1];
        for (int e = g_off[node]; e < e1; e++) {
            int c = g_csr[e];
            float w = dn * g_dis[c];
            float2 v = base[c * 32 + lane];
            a.x += w * v.x; a.y += w * v.y;
        }
        float s, nn, sc;
        s = wred(a.x * a.x + a.y * a.y); nn = fmaxf(sqrtf(s), MINN); sc = tfast(nn) / nn; a.x *= sc; a.y *= sc;
        s = wred(a.x * a.x + a.y * a.y); nn = fmaxf(sqrtf(s), MINN); if (nn > PMAX) { sc = PMAX / nn; a.x *= sc; a.y *= sc; }
        s = wred(a.x * a.x + a.y * a.y); nn = fmaxf(sqrtf(s), MINN); sc = artanhf_(nn) / nn; a.x *= sc; a.y *= sc;
        a.x = (a.x >= 0.f) ? a.x : SLOPE * a.x;
        a.y = (a.y >= 0.f) ? a.y : SLOPE * a.y;
        s = wred(a.x * a.x + a.y * a.y); nn = fmaxf(sqrtf(s), MINN); sc = tfast(nn) / nn; a.x *= sc; a.y *= sc;
        s = wred(a.x * a.x + a.y * a.y); nn = fmaxf(sqrtf(s), MINN); if (nn > PMAX) { sc = PMAX / nn; a.x *= sc; a.y *= sc; }
        s = wred(a.x * a.x + a.y * a.y); nn = fmaxf(sqrtf(s), MINN); sc = artanhf_(nn) / nn; a.x *= sc; a.y *= sc;
        ((float2*)out)[node * 32 + lane] = a;
    }
}

// ---------------- HTA window attention (WIN=5 specialized, FFMA2) ----------------
__global__ __launch_bounds__(TPB) void k_att5(const float* __restrict__ hiddens, const float* __restrict__ Q,
                                              const float* __restrict__ ratt, int n) {
    __shared__ ulonglong2 wq[32 * 32];    // 16KB: k2-major, per-lane pair (j, j+32)
    __shared__ ull sxs[WPB * 5 * 64];     // 20KB dup hlog
    __shared__ float shr[64];
    int t = threadIdx.x;
    for (int idx = t; idx < 32 * 32; idx += TPB) {
        int k2 = idx >> 5, j = idx & 31;
        float4 v;
        v.x = Q[(2 * k2) * 64 + j];
        v.y = Q[(2 * k2) * 64 + j + 32];
        v.z = Q[(2 * k2 + 1) * 64 + j];
        v.w = Q[(2 * k2 + 1) * 64 + j + 32];
        ((float4*)wq)[idx] = v;
    }
    if (t < 64) shr[t] = ratt[t];
    __syncthreads();
    int warp = t >> 5, lane = t & 31;
    ull* sxw = sxs + warp * 5 * 64;
    const ulonglong2* sxu = (const ulonglong2*)sxw;
    const float inv5 = 0.2f;
    for (int node = blockIdx.x * WPB + warp; node < n; node += gridDim.x * WPB) {
        float hl0[5], hl1[5], ew[5];
#pragma unroll
        for (int w = 0; w < 5; w++) {
            size_t off = ((size_t)w * n + node) * 64;
            float v0 = hiddens[off + lane];
            float v1 = hiddens[off + lane + 32];
            float s = wred(v0 * v0 + v1 * v1);
            float pn = fmaxf(sqrtf(s), MINN);
            float sc = artanhf_(pn) / pn;
            v0 *= sc; v1 *= sc;
            hl0[w] = v0; hl1[w] = v1;
            sxw[w * 64 + lane] = fdup(v0);
            sxw[w * 64 + lane + 32] = fdup(v1);
        }
        __syncwarp();
        ull acc[5] = {0ull, 0ull, 0ull, 0ull, 0ull};
#pragma unroll 4
        for (int k2 = 0; k2 < 32; k2++) {
            ulonglong2 q = wq[k2 * 32 + lane];
#pragma unroll
            for (int w = 0; w < 5; w++) {
                ulonglong2 xd = sxu[w * 32 + k2];
                ffma2(acc[w], q.x, xd.x);
                ffma2(acc[w], q.y, xd.y);
            }
        }
#pragma unroll
        for (int w = 0; w < 5; w++) {
            float2 f = funpack(acc[w]);
            float ep = tfast(f.x) * shr[lane] + tfast(f.y) * shr[lane + 32];
            ew[w] = wred(ep);
        }
        float m = -1e30f;
#pragma unroll
        for (int w = 0; w < 5; w++) m = fmaxf(m, ew[w]);
        float ssum = 0.f;
#pragma unroll
        for (int w = 0; w < 5; w++) { ew[w] = __expf(ew[w] - m); ssum += ew[w]; }
        float inv = inv5 / ssum;
        float o0 = 0.f, o1 = 0.f;
#pragma unroll
        for (int w = 0; w < 5; w++) { o0 += ew[w] * hl0[w]; o1 += ew[w] * hl1[w]; }
        g_hatt[node * 64 + lane]      = o0 * inv;
        g_hatt[node * 64 + lane + 32] = o1 * inv;
        __syncwarp();
    }
}

// generic fallback (win != 5)
__global__ void k_att(const float* __restrict__ hiddens, const float* __restrict__ Q,
                      const float* __restrict__ ratt, int n, int win) {
    __shared__ float shQ[64 * 64];
    __shared__ float shr[64];
    __shared__ float shh[WPB][64];
    int t = threadIdx.x;
    for (int idx = t; idx < 64 * 64; idx += TPB) shQ[idx] = Q[idx];
    if (t < 64) shr[t] = ratt[t];
    __syncthreads();
    int warp = t >> 5, lane = t & 31;
    float invwin = 1.0f / (float)win;
    for (int node = blockIdx.x * WPB + warp; node < n; node += gridDim.x * WPB) {
        float hl0[8], hl1[8], ew[8];
        for (int w = 0; w < win; w++) {
            size_t off = ((size_t)w * n + node) * 64;
            float v0 = hiddens[off + lane];
            float v1 = hiddens[off + lane + 32];
            float s = wred(v0 * v0 + v1 * v1);
            float pn = fmaxf(sqrtf(s), MINN);
            float sc = artanhf_(pn) / pn;
            v0 *= sc; v1 *= sc;
            hl0[w] = v0; hl1[w] = v1;
            shh[warp][lane] = v0; shh[warp][lane + 32] = v1;
            __syncwarp();
            float ep = 0.f;
#pragma unroll
            for (int g = 0; g < 2; g++) {
                int j = lane + 32 * g;
                float a = 0.f;
                for (int k = 0; k < 64; k++) a += shh[warp][k] * shQ[k * 64 + j];
                ep += tfast(a) * shr[j];
            }
            ew[w] = wred(ep);
            __syncwarp();
        }
        float m = -1e30f;
        for (int w = 0; w < win; w++) m = fmaxf(m, ew[w]);
        float ssum = 0.f;
        for (int w = 0; w < win; w++) { ew[w] = __expf(ew[w] - m); ssum += ew[w]; }
        float inv = invwin / ssum;
        float o0 = 0.f, o1 = 0.f;
        for (int w = 0; w < win; w++) { o0 += ew[w] * hl0[w]; o1 += ew[w] * hl1[w]; }
        g_hatt[node * 64 + lane]      = o0 * inv;
        g_hatt[node * 64 + lane + 32] = o1 * inv;
    }
}

// ---------------- GRU (FFMA2, 8-node blocking) + final expmap0/proj ----------------
__global__ __launch_bounds__(TPB) void k_gru2(const float* __restrict__ Wih, const float* __restrict__ Whh,
                                              const float* __restrict__ bih, const float* __restrict__ bhh,
                                              float* __restrict__ outp, int n) {
    extern __shared__ unsigned char smraw[];
    ulonglong2* wqi = (ulonglong2*)smraw;                      // 3*32*32
    ulonglong2* wqh = (ulonglong2*)(smraw + 49152);            // 3*32*32
    ull* sxx = (ull*)(smraw + 98304);                          // WPB*8*64
    ull* sxh = (ull*)(smraw + 131072);                         // WPB*8*64
    float* sbi = (float*)(smraw + 163840);                     // 192
    float* sbh = (float*)(smraw + 164608);                     // 192
    int t = threadIdx.x;
    for (int idx = t; idx < 3 * 32 * 32; idx += TPB) {
        int p = idx >> 10; int r = idx & 1023; int k2 = r >> 5; int j = r & 31;
        float4 vi, vh;
        vi.x = Wih[(p * 64 + j) * 64 + 2 * k2];
        vi.y = Wih[(p * 64 + j + 32) * 64 + 2 * k2];
        vi.z = Wih[(p * 64 + j) * 64 + 2 * k2 + 1];
        vi.w = Wih[(p * 64 + j + 32) * 64 + 2 * k2 + 1];
        vh.x = Whh[(p * 64 + j) * 64 + 2 * k2];
        vh.y = Whh[(p * 64 + j + 32) * 64 + 2 * k2];
        vh.z = Whh[(p * 64 + j) * 64 + 2 * k2 + 1];
        vh.w = Whh[(p * 64 + j + 32) * 64 + 2 * k2 + 1];
        ((float4*)wqi)[idx] = vi;
        ((float4*)wqh)[idx] = vh;
    }
    if (t < 192) { sbi[t] = bih[t]; sbh[t] = bhh[t]; }
    __syncthreads();
    int warp = t >> 5, lane = t & 31;
    ull* sxxw = sxx + warp * 512;
    ull* sxhw = sxh + warp * 512;
    const ulonglong2* sxxu = (const ulonglong2*)sxxw;
    const ulonglong2* sxhu = (const ulonglong2*)sxhw;
    int ngrp = (n + 7) >> 3;
    for (int grp = blockIdx.x * WPB + warp; grp < ngrp; grp += gridDim.x * WPB) {
        int base = grp * 8;
        float h0r[8], h1r[8];
#pragma unroll
        for (int m = 0; m < 8; m++) {
            int nm = min(base + m, n - 1);
            float x0 = g_xtf[nm * 64 + lane], x1 = g_xtf[nm * 64 + lane + 32];
            float h0 = g_hatt[nm * 64 + lane], h1 = g_hatt[nm * 64 + lane + 32];
            sxxw[m * 64 + lane] = fdup(x0);
            sxxw[m * 64 + lane + 32] = fdup(x1);
            sxhw[m * 64 + lane] = fdup(h0);
            sxhw[m * 64 + lane + 32] = fdup(h1);
            h0r[m] = h0; h1r[m] = h1;
        }
        __syncwarp();
        ull gi[8][3], gh[8][3];
#pragma unroll
        for (int m = 0; m < 8; m++)
#pragma unroll
            for (int p = 0; p < 3; p++) { gi[m][p] = 0ull; gh[m][p] = 0ull; }
#pragma unroll 1
        for (int k2 = 0; k2 < 32; k2++) {
            ulonglong2 qi[3], qh[3];
#pragma unroll
            for (int p = 0; p < 3; p++) {
                qi[p] = wqi[p * 1024 + k2 * 32 + lane];
                qh[p] = wqh[p * 1024 + k2 * 32 + lane];
            }
#pragma unroll
            for (int m = 0; m < 8; m++) {
                ulonglong2 xd = sxxu[m * 32 + k2];
                ulonglong2 hd = sxhu[m * 32 + k2];
#pragma unroll
                for (int p = 0; p < 3; p++) {
                    ffma2(gi[m][p], qi[p].x, xd.x);
                    ffma2(gi[m][p], qi[p].y, xd.y);
                    ffma2(gh[m][p], qh[p].x, hd.x);
                    ffma2(gh[m][p], qh[p].y, hd.y);
                }
            }
        }
#pragma unroll
        for (int m = 0; m < 8; m++) {
            int nm = base + m;
            float2 i0 = funpack(gi[m][0]), i1 = funpack(gi[m][1]), i2 = funpack(gi[m][2]);
            float2 hh0 = funpack(gh[m][0]), hh1 = funpack(gh[m][1]), hh2 = funpack(gh[m][2]);
            float ir0 = i0.x + sbi[lane],        ir1 = i0.y + sbi[lane + 32];
            float iz0 = i1.x + sbi[lane + 64],   iz1 = i1.y + sbi[lane + 96];
            float in0 = i2.x + sbi[lane + 128],  in1 = i2.y + sbi[lane + 160];
            float hr0 = hh0.x + sbh[lane],       hr1 = hh0.y + sbh[lane + 32];
            float hz0 = hh1.x + sbh[lane + 64],  hz1 = hh1.y + sbh[lane + 96];
            float hn0 = hh2.x + sbh[lane + 128], hn1 = hh2.y + sbh[lane + 160];
            float r0 = sigf(ir0 + hr0), r1 = sigf(ir1 + hr1);
            float z0 = sigf(iz0 + hz0), z1 = sigf(iz1 + hz1);
            float n0 = tfast(in0 + r0 * hn0), n1 = tfast(in1 + r1 * hn1);
            float o0 = (1.f - z0) * n0 + z0 * h0r[m];
            float o1 = (1.f - z1) * n1 + z1 * h1r[m];
            float s = wred(o0 * o0 + o1 * o1);
            float nn = fmaxf(sqrtf(s), MINN);
            float sc = tfast(nn) / nn; o0 *= sc; o1 *= sc;
            s = wred(o0 * o0 + o1 * o1);
            nn = fmaxf(sqrtf(s), MINN);
            if (nn > PMAX) { sc = PMAX / nn; o0 *= sc; o1 *= sc; }
            if (nm < n) {
                outp[nm * 64 + lane]      = o0;
                outp[nm * 64 + lane + 32] = o1;
            }
        }
        __syncwarp();
    }
}

// ---------------- launch ----------------
extern "C" void kernel_launch(void* const* d_in, const int* in_sizes, int n_in,
                              void* d_out, int out_size) {
    const int*   eidx = (const int*)  d_in[0];
    const float* feat = (const float*)d_in[1];
    const float* Wl   = (const float*)d_in[2];
    const float* bl   = (const float*)d_in[3];
    const float* W1   = (const float*)d_in[4];
    const float* b1   = (const float*)d_in[5];
    const float* W2   = (const float*)d_in[6];
    const float* b2   = (const float*)d_in[7];
    const float* Q    = (const float*)d_in[8];
    const float* ratt = (const float*)d_in[9];
    const float* Wih  = (const float*)d_in[10];
    const float* Whh  = (const float*)d_in[11];
    const float* bih  = (const float*)d_in[12];
    const float* bhh  = (const float*)d_in[13];
    const float* hidd = (const float*)d_in[14];
    float* outp = (float*)d_out;

    int E = in_sizes[0] / 2;
    int N = in_sizes[1] / 128;
    int WIN = in_sizes[14] / (N * 64);
    if (N > NMAX || E > EMAX) return;
    const int* src = eidx;
    const int* dst = eidx + E;

    float *p_xcat, *p_xt, *p_x2, *p_xtf, *p_hb1, *p_hb2;
    cudaGetSymbolAddress((void**)&p_xcat, g_xcat);
    cudaGetSymbolAddress((void**)&p_xt,   g_xt);
    cudaGetSymbolAddress((void**)&p_x2,   g_x2);
    cudaGetSymbolAddress((void**)&p_xtf,  g_xtf);
    cudaGetSymbolAddress((void**)&p_hb1,  g_hb1);
    cudaGetSymbolAddress((void**)&p_hb2,  g_hb2);

    // side stream + fork/join events (created once on first, non-capture call)
    static cudaStream_t s_att = nullptr;
    static cudaEvent_t  ev_fork = nullptr, ev_join = nullptr;
    if (s_att == nullptr) {
        cudaStreamCreateWithFlags(&s_att, cudaStreamNonBlocking);
        cudaEventCreateWithFlags(&ev_fork, cudaEventDisableTiming);
        cudaEventCreateWithFlags(&ev_join, cudaEventDisableTiming);
    }

    const int SMI  = 64 * 32 * 16 + WPB * 4 * 128 * 8 + 64 * 4;             // 65792
    const int SML1 = 2 * 64 * 32 * 16 + WPB * 4 * 32 * 16 + 128 * 4;        // 82432
    const int SML2 = 64 * 32 * 16 + WPB * 4 * 32 * 16 + 64 * 4;             // 49408
    const int SMG  = 2 * 49152 + 2 * WPB * 8 * 64 * 8 + 2 * 192 * 4;        // 165376
    cudaFuncSetAttribute(k_init2,   cudaFuncAttributeMaxDynamicSharedMemorySize, SMI);
    cudaFuncSetAttribute(k_lin<2>,  cudaFuncAttributeMaxDynamicSharedMemorySize, SML1);
    cudaFuncSetAttribute(k_lin<1>,  cudaFuncAttributeMaxDynamicSharedMemorySize, SML2);
    cudaFuncSetAttribute(k_gru2,    cudaFuncAttributeMaxDynamicSharedMemorySize, SMG);

    int eb = (E + 255) / 256;
    int nb = (N + 255) / 256;
    int NB = (N + 1023) / 1024;

    // fork: attention runs concurrently on side stream (depends only on inputs)
    cudaEventRecord(ev_fork, 0);
    cudaStreamWaitEvent(s_att, ev_fork, 0);
    if (WIN == 5) k_att5<<<592, TPB, 0, s_att>>>(hidd, Q, ratt, N);        // launch 1
    else          k_att<<<1184, TPB, 0, s_att>>>(hidd, Q, ratt, N, WIN);
    cudaEventRecord(ev_join, s_att);

    // main chain
    k_bias<<<1, 128>>>(b1, b2);                                            // launch 2
    k_init2<<<444, TPB, SMI>>>(feat, Wl, bl, hidd + (size_t)(WIN - 1) * N * 64, N); // launch 3
    k_lin<2><<<296, TPB, SML1>>>(p_xcat, W1, p_hb1, p_xt, N);              // launch 4: ncu target
    k_zero2<<<nb, 256>>>(N);
    k_count<<<eb, 256>>>(src, E);
    k_scan1<<<NB, 1024>>>(N);
    k_scan2<<<1, 128>>>(NB);
    k_scan3<<<nb, 256>>>(N, E);
    k_dis<<<nb, 256>>>(N);
    k_fill<<<eb, 256>>>(src, dst, E);
    k_agg128<<<1184, TPB>>>(p_xt, p_x2, N);
    k_lin<1><<<444, TPB, SML2>>>(p_x2, W2, p_hb2, p_xt, N);
    k_agg64<<<1184, TPB>>>(p_xt, p_xtf, N);

    // join: gru needs g_hatt from attention branch
    cudaStreamWaitEvent(0, ev_join, 0);
    k_gru2<<<148, TPB, SMG>>>(Wih, Whh, bih, bhh, outp, N);
}

// round 14
// speedup vs baseline: 1.6924x; 1.0531x over previous
#include <cuda_runtime.h>
#include <math.h>

#define MINN  1e-15f
#define PMAX  0.996f      // (1 - 4e-3)/sqrt(c), c=1
#define SLOPE 0.01f

constexpr int NMAX = 100000;
constexpr int EMAX = 800000;
constexpr int WPB  = 8;          // warps per block (non-matvec kernels)
constexpr int TPB  = WPB * 32;   // 256 threads
constexpr int WPBL = 16;         // warps per block (matvec kernels)
constexpr int TPBL = WPBL * 32;  // 512 threads

// ---------------- scratch (static device globals; no allocation) ----------------
__device__ float g_xcat[NMAX * 128];
__device__ float g_xt  [NMAX * 128];
__device__ float g_x2  [NMAX * 128];
__device__ float g_xtf [NMAX * 64];
__device__ float g_hatt[NMAX * 64];
__device__ float g_dis [NMAX];
__device__ int   g_cnt [NMAX];
__device__ int   g_cur [NMAX];
__device__ int   g_off [NMAX + 1];
__device__ int   g_bsum[128];
__device__ int   g_csr [EMAX];
__device__ float g_hb1 [128];
__device__ float g_hb2 [64];

typedef unsigned long long ull;

// ---------------- helpers ----------------
__device__ __forceinline__ float wred(float v) {
#pragma unroll
    for (int o = 16; o; o >>= 1) v += __shfl_xor_sync(0xffffffffu, v, o);
    return v;
}
// fast artanh: poly for |x|<0.25 (rel err <1e-7), MUFU log otherwise (rel err <5e-7)
__device__ __forceinline__ float artanhf_(float x) {
    x = fminf(fmaxf(x, -1.0f + 1e-7f), 1.0f - 1e-7f);
    float x2 = x * x;
    float ser = x * (1.0f + x2 * (0.33333334f + x2 * (0.2f + x2 * (0.14285715f + x2 * 0.11111111f))));
    float lg  = 0.5f * __logf(__fdividef(1.0f + x, 1.0f - x));
    return (x2 < 0.0625f) ? ser : lg;
}
// fast tanh via MUFU ex2 (~1e-6 rel)
__device__ __forceinline__ float tfast(float x) {
    float ax = fabsf(x);
    float t = __expf(-2.0f * ax);
    float r = __fdividef(1.0f - t, 1.0f + t);
    return copysignf(r, x);
}
__device__ __forceinline__ float sigf(float x) {
    return __fdividef(1.0f, 1.0f + __expf(-x));
}
// packed f32x2 ops (sm_103a FFMA2 path)
__device__ __forceinline__ ull fdup(float v) {
    ull d; asm("mov.b64 %0, {%1, %1};" : "=l"(d) : "f"(v)); return d;
}
__device__ __forceinline__ void ffma2(ull& d, ull a, ull b) {
    asm("fma.rn.f32x2 %0, %1, %2, %0;" : "+l"(d) : "l"(a), "l"(b));
}
__device__ __forceinline__ float2 funpack(ull d) {
    float2 r; asm("mov.b64 {%0, %1}, %2;" : "=f"(r.x), "=f"(r.y) : "l"(d)); return r;
}

// ---------------- hyperbolic bias precompute ----------------
__device__ __forceinline__ float blk_red128(float v, float* sh) {
    int t = threadIdx.x;
    sh[t] = v; __syncthreads();
    for (int s = 64; s > 0; s >>= 1) { if (t < s) sh[t] += sh[t + s]; __syncthreads(); }
    float r = sh[0]; __syncthreads();
    return r;
}

__global__ void k_bias(const float* __restrict__ b1, const float* __restrict__ b2) {
    __shared__ float sh[128];
    int t = threadIdx.x;
    float v = b1[t];
    float n2 = blk_red128(v * v, sh);
    float nn = fmaxf(sqrtf(n2), MINN);
    float u = tanhf(nn) / nn * v;
    float pu2 = blk_red128(u * u, sh);
    float pn = fmaxf(sqrtf(pu2), MINN);
    if (pn > PMAX) u *= PMAX / pn;
    g_hb1[t] = u;
    float v2 = (t < 64) ? b2[t] : 0.f;
    float m2 = blk_red128(v2 * v2, sh);
    float mn = fmaxf(sqrtf(m2), MINN);
    float u2 = tanhf(mn) / mn * v2;
    float q2 = blk_red128(u2 * u2, sh);
    float qn = fmaxf(sqrtf(q2), MINN);
    if (qn > PMAX) u2 *= PMAX / qn;
    if (t < 64) g_hb2[t] = u2;
}

// ---------------- init: x = feat@Wl.T + bl ; expmap0 ; proj ; concat hidden ; proj ----------------
// FFMA2 + 4-node blocking, 512-thread blocks sharing one weight copy.
__global__ __launch_bounds__(TPBL, 2) void k_init2(const float* __restrict__ feat, const float* __restrict__ Wl,
                                                   const float* __restrict__ bl, const float* __restrict__ hidlast, int n) {
    extern __shared__ unsigned char smraw[];
    ulonglong2* wq = (ulonglong2*)smraw;                               // 64 k2 * 32 lanes (32KB)
    ull* sx = (ull*)(smraw + 64 * 32 * 16);                            // WPBL * 4 * 128 (64KB)
    float* shb = (float*)(smraw + 64 * 32 * 16 + WPBL * 4 * 128 * 8);  // 64
    int t = threadIdx.x;
    for (int idx = t; idx < 64 * 32; idx += TPBL) {
        int k2 = idx >> 5, j = idx & 31;
        float4 v;
        v.x = Wl[j * 128 + 2 * k2];
        v.y = Wl[(j + 32) * 128 + 2 * k2];
        v.z = Wl[j * 128 + 2 * k2 + 1];
        v.w = Wl[(j + 32) * 128 + 2 * k2 + 1];
        ((float4*)wq)[idx] = v;
    }
    if (t < 64) shb[t] = bl[t];
    __syncthreads();
    int warp = t >> 5, lane = t & 31;
    ull* sxw = sx + warp * 512;
    const ulonglong2* sxu = (const ulonglong2*)sxw;
    int ngrp = (n + 3) >> 2;
    for (int grp = blockIdx.x * WPBL + warp; grp < ngrp; grp += gridDim.x * WPBL) {
        int base = grp * 4;
#pragma unroll
        for (int m = 0; m < 4; m++) {
            int nm = min(base + m, n - 1);
            float4 f = ((const float4*)feat)[nm * 32 + lane];
            ulonglong2 d0, d1;
            d0.x = fdup(f.x); d0.y = fdup(f.y); d1.x = fdup(f.z); d1.y = fdup(f.w);
            ((ulonglong2*)(sxw + m * 128))[lane * 2] = d0;
            ((ulonglong2*)(sxw + m * 128))[lane * 2 + 1] = d1;
        }
        __syncwarp();
        ull acc[4] = {0ull, 0ull, 0ull, 0ull};
#pragma unroll 4
        for (int k2 = 0; k2 < 64; k2++) {
            ulonglong2 q = wq[k2 * 32 + lane];
#pragma unroll
            for (int m = 0; m < 4; m++) {
                ulonglong2 xd = sxu[m * 64 + k2];
                ffma2(acc[m], q.x, xd.x);
                ffma2(acc[m], q.y, xd.y);
            }
        }
#pragma unroll
        for (int m = 0; m < 4; m++) {
            int nm = base + m;
            float2 av = funpack(acc[m]);
            float a0 = av.x + shb[lane], a1 = av.y + shb[lane + 32];
            // expmap0
            float s = wred(a0 * a0 + a1 * a1);
            float nn = fmaxf(sqrtf(s), MINN);
            float sc = tfast(nn) / nn; a0 *= sc; a1 *= sc;
            // proj (64-dim)
            s = wred(a0 * a0 + a1 * a1);
            nn = fmaxf(sqrtf(s), MINN);
            if (nn > PMAX) { sc = PMAX / nn; a0 *= sc; a1 *= sc; }
            // concat hidden, proj over 128 dims
            int nmc = min(nm, n - 1);
            float h0 = hidlast[nmc * 64 + lane];
            float h1 = hidlast[nmc * 64 + lane + 32];
            s = wred(a0 * a0 + a1 * a1 + h0 * h0 + h1 * h1);
            nn = fmaxf(sqrtf(s), MINN);
            if (nn > PMAX) { sc = PMAX / nn; a0 *= sc; a1 *= sc; h0 *= sc; h1 *= sc; }
            if (nm < n) {
                g_xcat[nm * 128 + lane]      = a0;
                g_xcat[nm * 128 + lane + 32] = a1;
                g_xcat[nm * 128 + lane + 64] = h0;
                g_xcat[nm * 128 + lane + 96] = h1;
            }
        }
        __syncwarp();
    }
}

// ---------------- CSR build ----------------
__global__ void k_zero2(int n) {
    int i = blockIdx.x * blockDim.x + threadIdx.x;
    if (i < n) { g_cnt[i] = 0; g_cur[i] = 0; }
}
__global__ void k_count(const int* __restrict__ src, int e) {
    int i = blockIdx.x * blockDim.x + threadIdx.x;
    if (i < e) atomicAdd(&g_cnt[src[i]], 1);
}
__global__ void k_scan1(int n) {
    __shared__ int sh[1024];
    int t = threadIdx.x;
    int i = blockIdx.x * 1024 + t;
    int v = (i < n) ? g_cnt[i] : 0;
    sh[t] = v; __syncthreads();
    for (int d = 1; d < 1024; d <<= 1) {
        int x = (t >= d) ? sh[t - d] : 0;
        __syncthreads();
        sh[t] += x; __syncthreads();
    }
    if (i < n) g_off[i] = sh[t] - v;
    if (t == 1023) g_bsum[blockIdx.x] = sh[1023];
}
__global__ void k_scan2(int nb) {
    __shared__ int sh[128];
    int t = threadIdx.x;
    int v = (t < nb) ? g_bsum[t] : 0;
    sh[t] = v; __syncthreads();
    for (int d = 1; d < 128; d <<= 1) {
        int x = (t >= d) ? sh[t - d] : 0;
        __syncthreads();
        sh[t] += x; __syncthreads();
    }
    g_bsum[t] = sh[t] - v;
}
__global__ void k_scan3(int n, int e) {
    int i = blockIdx.x * blockDim.x + threadIdx.x;
    if (i < n) g_off[i] += g_bsum[i >> 10];
    if (i == 0) g_off[n] = e;
}
__global__ void k_dis(int n) {
    int i = blockIdx.x * blockDim.x + threadIdx.x;
    if (i < n) g_dis[i] = rsqrtf((float)(g_cnt[i] + 1));
}
__global__ void k_fill(const int* __restrict__ src, const int* __restrict__ dst, int e) {
    int i = blockIdx.x * blockDim.x + threadIdx.x;
    if (i < e) {
        int s = src[i];
        int p = g_off[s] + atomicAdd(&g_cur[s], 1);
        g_csr[p] = dst[i];
    }
}

// ---------------- hyp_linear (k-paired FFMA2, 4-node blocking, 512-thread blocks) ----------------
template <int P>
__global__ __launch_bounds__(TPBL, 2) void k_lin(const float* __restrict__ xin, const float* __restrict__ W,
                                                 const float* __restrict__ hb, float* __restrict__ xtout, int n) {
    extern __shared__ unsigned char smraw[];
    ulonglong2* wq = (ulonglong2*)smraw;                                     // P*64*32
    float4* sxf = (float4*)(smraw + P * 64 * 32 * 16);                       // WPBL*4*32 float4
    float* shb = (float*)(smraw + P * 64 * 32 * 16 + WPBL * 4 * 32 * 16);    // 64*P
    int t = threadIdx.x;
    for (int idx = t; idx < P * 64 * 32; idx += TPBL) {
        int p = idx >> 11; int r = idx & 2047; int k2 = r >> 5; int j = r & 31;
        float4 v;
        v.x = W[(p * 64 + j) * 128 + 2 * k2];
        v.y = W[(p * 64 + j) * 128 + 2 * k2 + 1];
        v.z = W[(p * 64 + j + 32) * 128 + 2 * k2];
        v.w = W[(p * 64 + j + 32) * 128 + 2 * k2 + 1];
        ((float4*)wq)[idx] = v;
    }
    for (int idx = t; idx < 64 * P; idx += TPBL) shb[idx] = hb[idx];
    __syncthreads();
    int warp = t >> 5, lane = t & 31;
    float4* sxw = sxf + warp * 128;                     // 4 nodes * 32 float4
    const ulonglong2* sxu = (const ulonglong2*)sxw;     // [m*32 + k4]
    constexpr int VO = 2 * P;
    int ngrp = (n + 3) >> 2;
    for (int grp = blockIdx.x * WPBL + warp; grp < ngrp; grp += gridDim.x * WPBL) {
        int base = grp * 4;
        float xn[4];
#pragma unroll
        for (int m = 0; m < 4; m++) {
            int nm = min(base + m, n - 1);
            float4 f = ((const float4*)xin)[nm * 32 + lane];
            sxw[m * 32 + lane] = f;
            float xs = f.x * f.x + f.y * f.y + f.z * f.z + f.w * f.w;
            xn[m] = fmaxf(sqrtf(wred(xs)), MINN);
        }
        __syncwarp();
        ull accA[4][P], accB[4][P];
#pragma unroll
        for (int m = 0; m < 4; m++)
#pragma unroll
            for (int p = 0; p < P; p++) { accA[m][p] = 0ull; accB[m][p] = 0ull; }
#pragma unroll 2
        for (int k4 = 0; k4 < 32; k4++) {
            ulonglong2 wwa[P], wwb[P];
#pragma unroll
            for (int p = 0; p < P; p++) {
                wwa[p] = wq[p * 2048 + (2 * k4) * 32 + lane];
                wwb[p] = wq[p * 2048 + (2 * k4 + 1) * 32 + lane];
            }
#pragma unroll
            for (int m = 0; m < 4; m++) {
                ulonglong2 xp = sxu[m * 32 + k4];       // broadcast: 4 distinct x per 16B
#pragma unroll
                for (int p = 0; p < P; p++) {
                    ffma2(accA[m][p], wwa[p].x, xp.x);
                    ffma2(accB[m][p], wwa[p].y, xp.x);
                    ffma2(accA[m][p], wwb[p].x, xp.y);
                    ffma2(accB[m][p], wwb[p].y, xp.y);
                }
            }
        }
#pragma unroll
        for (int m = 0; m < 4; m++) {
            int nm = base + m;
            float v[VO];
#pragma unroll
            for (int p = 0; p < P; p++) {
                float2 fA = funpack(accA[m][p]);
                float2 fB = funpack(accB[m][p]);
                v[2 * p]     = fA.x + fA.y;
                v[2 * p + 1] = fB.x + fB.y;
            }
            float ms = 0.f;
#pragma unroll
            for (int g = 0; g < VO; g++) ms += v[g] * v[g];
            float mxn2 = wred(ms);
            float mxn = fmaxf(sqrtf(mxn2), MINN);
            float xnn = xn[m];
            float r = tfast(mxn / xnn * artanhf_(xnn)) / mxn;
            if (mxn2 == 0.f) r = 0.f;
#pragma unroll
            for (int g = 0; g < VO; g++) v[g] *= r;
            // proj
            float s = 0.f;
#pragma unroll
            for (int g = 0; g < VO; g++) s += v[g] * v[g];
            s = wred(s);
            float pn = fmaxf(sqrtf(s), MINN);
            if (pn > PMAX) { float f = PMAX / pn;
#pragma unroll
                for (int g = 0; g < VO; g++) v[g] *= f; }
            // mobius_add(v, hb)
            float hx[VO];
            float xx = 0.f, xy = 0.f, yy = 0.f;
#pragma unroll
            for (int g = 0; g < VO; g++) {
                float hv = shb[lane + 32 * g];
                hx[g] = hv;
                xx += v[g] * v[g];
                xy += v[g] * hv;
                yy += hv * hv;
            }
            xx = wred(xx); xy = wred(xy); yy = wred(yy);
            float den = fmaxf(1.f + 2.f * xy + xx * yy, MINN);
            float ca = (1.f + 2.f * xy + yy) / den;
            float cb = (1.f - xx) / den;
#pragma unroll
            for (int g = 0; g < VO; g++) v[g] = ca * v[g] + cb * hx[g];
            // proj
            s = 0.f;
#pragma unroll
            for (int g = 0; g < VO; g++) s += v[g] * v[g];
            s = wred(s);
            pn = fmaxf(sqrtf(s), MINN);
            if (pn > PMAX) { float f = PMAX / pn;
#pragma unroll
                for (int g = 0; g < VO; g++) v[g] *= f; }
            // logmap0
            s = 0.f;
#pragma unroll
            for (int g = 0; g < VO; g++) s += v[g] * v[g];
            s = wred(s);
            pn = fmaxf(sqrtf(s), MINN);
            float a = artanhf_(pn) / pn;
            if (nm < n) {
#pragma unroll
                for (int g = 0; g < VO; g++) xtout[nm * (64 * P) + lane + 32 * g] = v[g] * a;
            }
        }
        __syncwarp();
    }
}

// ---------------- aggregation (CSR gather) + activation chain ----------------
__device__ __forceinline__ float n2_4(float4 a) { return a.x * a.x + a.y * a.y + a.z * a.z + a.w * a.w; }
__device__ __forceinline__ void  mul4(float4& a, float s) { a.x *= s; a.y *= s; a.z *= s; a.w *= s; }

__global__ void k_agg128(const float* __restrict__ xt, float* __restrict__ out, int n) {
    int t = threadIdx.x, warp = t >> 5, lane = t & 31;
    const float4* base = (const float4*)xt;
    for (int node = blockIdx.x * WPB + warp; node < n; node += gridDim.x * WPB) {
        float dn = g_dis[node];
        float4 a = base[node * 32 + lane];
        mul4(a, dn * dn);
        int e1 = g_off[node + 1];
        for (int e = g_off[node]; e < e1; e++) {
            int c = g_csr[e];
            float w = dn * g_dis[c];
            float4 v = base[c * 32 + lane];
            a.x += w * v.x; a.y += w * v.y; a.z += w * v.z; a.w += w * v.w;
        }
        float s, nn, sc;
        s = wred(n2_4(a)); nn = fmaxf(sqrtf(s), MINN); sc = tfast(nn) / nn; mul4(a, sc);
        s = wred(n2_4(a)); nn = fmaxf(sqrtf(s), MINN); if (nn > PMAX) mul4(a, PMAX / nn);
        s = wred(n2_4(a)); nn = fmaxf(sqrtf(s), MINN); sc = artanhf_(nn) / nn; mul4(a, sc);
        a.x = (a.x >= 0.f) ? a.x : SLOPE * a.x;
        a.y = (a.y >= 0.f) ? a.y : SLOPE * a.y;
        a.z = (a.z >= 0.f) ? a.z : SLOPE * a.z;
        a.w = (a.w >= 0.f) ? a.w : SLOPE * a.w;
        s = wred(n2_4(a)); nn = fmaxf(sqrtf(s), MINN); sc = tfast(nn) / nn; mul4(a, sc);
        s = wred(n2_4(a)); nn = fmaxf(sqrtf(s), MINN); if (nn > PMAX) mul4(a, PMAX / nn);
        s = wred(n2_4(a)); nn = fmaxf(sqrtf(s), MINN); if (nn > PMAX) mul4(a, PMAX / nn);
        ((float4*)out)[node * 32 + lane] = a;
    }
}

__global__ void k_agg64(const float* __restrict__ xt, float* __restrict__ out, int n) {
    int t = threadIdx.x, warp = t >> 5, lane = t & 31;
    const float2* base = (const float2*)xt;
    for (int node = blockIdx.x * WPB + warp; node < n; node += gridDim.x * WPB) {
        float dn = g_dis[node];
        float2 a = base[node * 32 + lane];
        float ws = dn * dn;
        a.x *= ws; a.y *= ws;
        int e1 = g_off[node + 1];
        for (int e = g_off[node]; e < e1; e++) {
            int c = g_csr[e];
            float w = dn * g_dis[c];
            float2 v = base[c * 32 + lane];
            a.x += w * v.x; a.y += w * v.y;
        }
        float s, nn, sc;
        s = wred(a.x * a.x + a.y * a.y); nn = fmaxf(sqrtf(s), MINN); sc = tfast(nn) / nn; a.x *= sc; a.y *= sc;
        s = wred(a.x * a.x + a.y * a.y); nn = fmaxf(sqrtf(s), MINN); if (nn > PMAX) { sc = PMAX / nn; a.x *= sc; a.y *= sc; }
        s = wred(a.x * a.x + a.y * a.y); nn = fmaxf(sqrtf(s), MINN); sc = artanhf_(nn) / nn; a.x *= sc; a.y *= sc;
        a.x = (a.x >= 0.f) ? a.x : SLOPE * a.x;
        a.y = (a.y >= 0.f) ? a.y : SLOPE * a.y;
        s = wred(a.x * a.x + a.y * a.y); nn = fmaxf(sqrtf(s), MINN); sc = tfast(nn) / nn; a.x *= sc; a.y *= sc;
        s = wred(a.x * a.x + a.y * a.y); nn = fmaxf(sqrtf(s), MINN); if (nn > PMAX) { sc = PMAX / nn; a.x *= sc; a.y *= sc; }
        s = wred(a.x * a.x + a.y * a.y); nn = fmaxf(sqrtf(s), MINN); sc = artanhf_(nn) / nn; a.x *= sc; a.y *= sc;
        ((float2*)out)[node * 32 + lane] = a;
    }
}

// ---------------- HTA window attention (WIN=5 specialized, FFMA2) ----------------
__global__ __launch_bounds__(TPB) void k_att5(const float* __restrict__ hiddens, const float* __restrict__ Q,
                                              const float* __restrict__ ratt, int n) {
    __shared__ ulonglong2 wq[32 * 32];    // 16KB
    __shared__ ull sxs[WPB * 5 * 64];     // 20KB
    __shared__ float shr[64];
    int t = threadIdx.x;
    for (int idx = t; idx < 32 * 32; idx += TPB) {
        int k2 = idx >> 5, j = idx & 31;
        float4 v;
        v.x = Q[(2 * k2) * 64 + j];
        v.y = Q[(2 * k2) * 64 + j + 32];
        v.z = Q[(2 * k2 + 1) * 64 + j];
        v.w = Q[(2 * k2 + 1) * 64 + j + 32];
        ((float4*)wq)[idx] = v;
    }
    if (t < 64) shr[t] = ratt[t];
    __syncthreads();
    int warp = t >> 5, lane = t & 31;
    ull* sxw = sxs + warp * 5 * 64;
    const ulonglong2* sxu = (const ulonglong2*)sxw;
    const float inv5 = 0.2f;
    for (int node = blockIdx.x * WPB + warp; node < n; node += gridDim.x * WPB) {
        float hl0[5], hl1[5], ew[5];
#pragma unroll
        for (int w = 0; w < 5; w++) {
            size_t off = ((size_t)w * n + node) * 64;
            float v0 = hiddens[off + lane];
            float v1 = hiddens[off + lane + 32];
            float s = wred(v0 * v0 + v1 * v1);
            float pn = fmaxf(sqrtf(s), MINN);
            float sc = artanhf_(pn) / pn;
            v0 *= sc; v1 *= sc;
            hl0[w] = v0; hl1[w] = v1;
            sxw[w * 64 + lane] = fdup(v0);
            sxw[w * 64 + lane + 32] = fdup(v1);
        }
        __syncwarp();
        ull acc[5] = {0ull, 0ull, 0ull, 0ull, 0ull};
#pragma unroll 4
        for (int k2 = 0; k2 < 32; k2++) {
            ulonglong2 q = wq[k2 * 32 + lane];
#pragma unroll
            for (int w = 0; w < 5; w++) {
                ulonglong2 xd = sxu[w * 32 + k2];
                ffma2(acc[w], q.x, xd.x);
                ffma2(acc[w], q.y, xd.y);
            }
        }
#pragma unroll
        for (int w = 0; w < 5; w++) {
            float2 f = funpack(acc[w]);
            float ep = tfast(f.x) * shr[lane] + tfast(f.y) * shr[lane + 32];
            ew[w] = wred(ep);
        }
        float m = -1e30f;
#pragma unroll
        for (int w = 0; w < 5; w++) m = fmaxf(m, ew[w]);
        float ssum = 0.f;
#pragma unroll
        for (int w = 0; w < 5; w++) { ew[w] = __expf(ew[w] - m); ssum += ew[w]; }
        float inv = inv5 / ssum;
        float o0 = 0.f, o1 = 0.f;
#pragma unroll
        for (int w = 0; w < 5; w++) { o0 += ew[w] * hl0[w]; o1 += ew[w] * hl1[w]; }
        g_hatt[node * 64 + lane]      = o0 * inv;
        g_hatt[node * 64 + lane + 32] = o1 * inv;
        __syncwarp();
    }
}

// generic fallback (win != 5)
__global__ void k_att(const float* __restrict__ hiddens, const float* __restrict__ Q,
                      const float* __restrict__ ratt, int n, int win) {
    __shared__ float shQ[64 * 64];
    __shared__ float shr[64];
    __shared__ float shh[WPB][64];
    int t = threadIdx.x;
    for (int idx = t; idx < 64 * 64; idx += TPB) shQ[idx] = Q[idx];
    if (t < 64) shr[t] = ratt[t];
    __syncthreads();
    int warp = t >> 5, lane = t & 31;
    float invwin = 1.0f / (float)win;
    for (int node = blockIdx.x * WPB + warp; node < n; node += gridDim.x * WPB) {
        float hl0[8], hl1[8], ew[8];
        for (int w = 0; w < win; w++) {
            size_t off = ((size_t)w * n + node) * 64;
            float v0 = hiddens[off + lane];
            float v1 = hiddens[off + lane + 32];
            float s = wred(v0 * v0 + v1 * v1);
            float pn = fmaxf(sqrtf(s), MINN);
            float sc = artanhf_(pn) / pn;
            v0 *= sc; v1 *= sc;
            hl0[w] = v0; hl1[w] = v1;
            shh[warp][lane] = v0; shh[warp][lane + 32] = v1;
            __syncwarp();
            float ep = 0.f;
#pragma unroll
            for (int g = 0; g < 2; g++) {
                int j = lane + 32 * g;
                float a = 0.f;
                for (int k = 0; k < 64; k++) a += shh[warp][k] * shQ[k * 64 + j];
                ep += tfast(a) * shr[j];
            }
            ew[w] = wred(ep);
            __syncwarp();
        }
        float m = -1e30f;
        for (int w = 0; w < win; w++) m = fmaxf(m, ew[w]);
        float ssum = 0.f;
        for (int w = 0; w < win; w++) { ew[w] = __expf(ew[w] - m); ssum += ew[w]; }
        float inv = invwin / ssum;
        float o0 = 0.f, o1 = 0.f;
        for (int w = 0; w < win; w++) { o0 += ew[w] * hl0[w]; o1 += ew[w] * hl1[w]; }
        g_hatt[node * 64 + lane]      = o0 * inv;
        g_hatt[node * 64 + lane + 32] = o1 * inv;
    }
}

// ---------------- GRU (FFMA2, 8-node blocking) + final expmap0/proj ----------------
__global__ __launch_bounds__(TPB) void k_gru2(const float* __restrict__ Wih, const float* __restrict__ Whh,
                                              const float* __restrict__ bih, const float* __restrict__ bhh,
                                              float* __restrict__ outp, int n) {
    extern __shared__ unsigned char smraw[];
    ulonglong2* wqi = (ulonglong2*)smraw;                      // 3*32*32
    ulonglong2* wqh = (ulonglong2*)(smraw + 49152);            // 3*32*32
    ull* sxx = (ull*)(smraw + 98304);                          // WPB*8*64
    ull* sxh = (ull*)(smraw + 131072);                         // WPB*8*64
    float* sbi = (float*)(smraw + 163840);                     // 192
    float* sbh = (float*)(smraw + 164608);                     // 192
    int t = threadIdx.x;
    for (int idx = t; idx < 3 * 32 * 32; idx += TPB) {
        int p = idx >> 10; int r = idx & 1023; int k2 = r >> 5; int j = r & 31;
        float4 vi, vh;
        vi.x = Wih[(p * 64 + j) * 64 + 2 * k2];
        vi.y = Wih[(p * 64 + j + 32) * 64 + 2 * k2];
        vi.z = Wih[(p * 64 + j) * 64 + 2 * k2 + 1];
        vi.w = Wih[(p * 64 + j + 32) * 64 + 2 * k2 + 1];
        vh.x = Whh[(p * 64 + j) * 64 + 2 * k2];
        vh.y = Whh[(p * 64 + j + 32) * 64 + 2 * k2];
        vh.z = Whh[(p * 64 + j) * 64 + 2 * k2 + 1];
        vh.w = Whh[(p * 64 + j + 32) * 64 + 2 * k2 + 1];
        ((float4*)wqi)[idx] = vi;
        ((float4*)wqh)[idx] = vh;
    }
    if (t < 192) { sbi[t] = bih[t]; sbh[t] = bhh[t]; }
    __syncthreads();
    int warp = t >> 5, lane = t & 31;
    ull* sxxw = sxx + warp * 512;
    ull* sxhw = sxh + warp * 512;
    const ulonglong2* sxxu = (const ulonglong2*)sxxw;
    const ulonglong2* sxhu = (const ulonglong2*)sxhw;
    int ngrp = (n + 7) >> 3;
    for (int grp = blockIdx.x * WPB + warp; grp < ngrp; grp += gridDim.x * WPB) {
        int base = grp * 8;
        float h0r[8], h1r[8];
#pragma unroll
        for (int m = 0; m < 8; m++) {
            int nm = min(base + m, n - 1);
            float x0 = g_xtf[nm * 64 + lane], x1 = g_xtf[nm * 64 + lane + 32];
            float h0 = g_hatt[nm * 64 + lane], h1 = g_hatt[nm * 64 + lane + 32];
            sxxw[m * 64 + lane] = fdup(x0);
            sxxw[m * 64 + lane + 32] = fdup(x1);
            sxhw[m * 64 + lane] = fdup(h0);
            sxhw[m * 64 + lane + 32] = fdup(h1);
            h0r[m] = h0; h1r[m] = h1;
        }
        __syncwarp();
        ull gi[8][3], gh[8][3];
#pragma unroll
        for (int m = 0; m < 8; m++)
#pragma unroll
            for (int p = 0; p < 3; p++) { gi[m][p] = 0ull; gh[m][p] = 0ull; }
#pragma unroll 1
        for (int k2 = 0; k2 < 32; k2++) {
            ulonglong2 qi[3], qh[3];
#pragma unroll
            for (int p = 0; p < 3; p++) {
                qi[p] = wqi[p * 1024 + k2 * 32 + lane];
                qh[p] = wqh[p * 1024 + k2 * 32 + lane];
            }
#pragma unroll
            for (int m = 0; m < 8; m++) {
                ulonglong2 xd = sxxu[m * 32 + k2];
                ulonglong2 hd = sxhu[m * 32 + k2];
#pragma unroll
                for (int p = 0; p < 3; p++) {
                    ffma2(gi[m][p], qi[p].x, xd.x);
                    ffma2(gi[m][p], qi[p].y, xd.y);
                    ffma2(gh[m][p], qh[p].x, hd.x);
                    ffma2(gh[m][p], qh[p].y, hd.y);
                }
            }
        }
#pragma unroll
        for (int m = 0; m < 8; m++) {
            int nm = base + m;
            float2 i0 = funpack(gi[m][0]), i1 = funpack(gi[m][1]), i2 = funpack(gi[m][2]);
            float2 hh0 = funpack(gh[m][0]), hh1 = funpack(gh[m][1]), hh2 = funpack(gh[m][2]);
            float ir0 = i0.x + sbi[lane],        ir1 = i0.y + sbi[lane + 32];
            float iz0 = i1.x + sbi[lane + 64],   iz1 = i1.y + sbi[lane + 96];
            float in0 = i2.x + sbi[lane + 128],  in1 = i2.y + sbi[lane + 160];
            float hr0 = hh0.x + sbh[lane],       hr1 = hh0.y + sbh[lane + 32];
            float hz0 = hh1.x + sbh[lane + 64],  hz1 = hh1.y + sbh[lane + 96];
            float hn0 = hh2.x + sbh[lane + 128], hn1 = hh2.y + sbh[lane + 160];
            float r0 = sigf(ir0 + hr0), r1 = sigf(ir1 + hr1);
            float z0 = sigf(iz0 + hz0), z1 = sigf(iz1 + hz1);
            float n0 = tfast(in0 + r0 * hn0), n1 = tfast(in1 + r1 * hn1);
            float o0 = (1.f - z0) * n0 + z0 * h0r[m];
            float o1 = (1.f - z1) * n1 + z1 * h1r[m];
            float s = wred(o0 * o0 + o1 * o1);
            float nn = fmaxf(sqrtf(s), MINN);
            float sc = tfast(nn) / nn; o0 *= sc; o1 *= sc;
            s = wred(o0 * o0 + o1 * o1);
            nn = fmaxf(sqrtf(s), MINN);
            if (nn > PMAX) { sc = PMAX / nn; o0 *= sc; o1 *= sc; }
            if (nm < n) {
                outp[nm * 64 + lane]      = o0;
                outp[nm * 64 + lane + 32] = o1;
            }
        }
        __syncwarp();
    }
}

// ---------------- launch ----------------
extern "C" void kernel_launch(void* const* d_in, const int* in_sizes, int n_in,
                              void* d_out, int out_size) {
    const int*   eidx = (const int*)  d_in[0];
    const float* feat = (const float*)d_in[1];
    const float* Wl   = (const float*)d_in[2];
    const float* bl   = (const float*)d_in[3];
    const float* W1   = (const float*)d_in[4];
    const float* b1   = (const float*)d_in[5];
    const float* W2   = (const float*)d_in[6];
    const float* b2   = (const float*)d_in[7];
    const float* Q    = (const float*)d_in[8];
    const float* ratt = (const float*)d_in[9];
    const float* Wih  = (const float*)d_in[10];
    const float* Whh  = (const float*)d_in[11];
    const float* bih  = (const float*)d_in[12];
    const float* bhh  = (const float*)d_in[13];
    const float* hidd = (const float*)d_in[14];
    float* outp = (float*)d_out;

    int E = in_sizes[0] / 2;
    int N = in_sizes[1] / 128;
    int WIN = in_sizes[14] / (N * 64);
    if (N > NMAX || E > EMAX) return;
    const int* src = eidx;
    const int* dst = eidx + E;

    float *p_xcat, *p_xt, *p_x2, *p_xtf, *p_hb1, *p_hb2;
    cudaGetSymbolAddress((void**)&p_xcat, g_xcat);
    cudaGetSymbolAddress((void**)&p_xt,   g_xt);
    cudaGetSymbolAddress((void**)&p_x2,   g_x2);
    cudaGetSymbolAddress((void**)&p_xtf,  g_xtf);
    cudaGetSymbolAddress((void**)&p_hb1,  g_hb1);
    cudaGetSymbolAddress((void**)&p_hb2,  g_hb2);

    // side stream + fork/join events (created once on first, non-capture call)
    static cudaStream_t s_att = nullptr;
    static cudaEvent_t  ev_fork = nullptr, ev_join = nullptr;
    if (s_att == nullptr) {
        cudaStreamCreateWithFlags(&s_att, cudaStreamNonBlocking);
        cudaEventCreateWithFlags(&ev_fork, cudaEventDisableTiming);
        cudaEventCreateWithFlags(&ev_join, cudaEventDisableTiming);
    }

    const int SMI  = 64 * 32 * 16 + WPBL * 4 * 128 * 8 + 64 * 4;            // 98560
    const int SML1 = 2 * 64 * 32 * 16 + WPBL * 4 * 32 * 16 + 128 * 4;       // 98816
    const int SML2 = 64 * 32 * 16 + WPBL * 4 * 32 * 16 + 64 * 4;            // 65792
    const int SMG  = 2 * 49152 + 2 * WPB * 8 * 64 * 8 + 2 * 192 * 4;        // 165376
    cudaFuncSetAttribute(k_init2,   cudaFuncAttributeMaxDynamicSharedMemorySize, SMI);
    cudaFuncSetAttribute(k_lin<2>,  cudaFuncAttributeMaxDynamicSharedMemorySize, SML1);
    cudaFuncSetAttribute(k_lin<1>,  cudaFuncAttributeMaxDynamicSharedMemorySize, SML2);
    cudaFuncSetAttribute(k_gru2,    cudaFuncAttributeMaxDynamicSharedMemorySize, SMG);

    int eb = (E + 255) / 256;
    int nb = (N + 255) / 256;
    int NB = (N + 1023) / 1024;

    // fork: attention runs concurrently on side stream (depends only on inputs)
    cudaEventRecord(ev_fork, 0);
    cudaStreamWaitEvent(s_att, ev_fork, 0);
    if (WIN == 5) k_att5<<<592, TPB, 0, s_att>>>(hidd, Q, ratt, N);
    else          k_att<<<1184, TPB, 0, s_att>>>(hidd, Q, ratt, N, WIN);
    cudaEventRecord(ev_join, s_att);

    // main chain
    k_bias<<<1, 128>>>(b1, b2);
    k_init2<<<296, TPBL, SMI>>>(feat, Wl, bl, hidd + (size_t)(WIN - 1) * N * 64, N);
    k_lin<2><<<296, TPBL, SML1>>>(p_xcat, W1, p_hb1, p_xt, N);              // launch 4: ncu target
    k_zero2<<<nb, 256>>>(N);
    k_count<<<eb, 256>>>(src, E);
    k_scan1<<<NB, 1024>>>(N);
    k_scan2<<<1, 128>>>(NB);
    k_scan3<<<nb, 256>>>(N, E);
    k_dis<<<nb, 256>>>(N);
    k_fill<<<eb, 256>>>(src, dst, E);
    k_agg128<<<1184, TPB>>>(p_xt, p_x2, N);
    k_lin<1><<<296, TPBL, SML2>>>(p_x2, W2, p_hb2, p_xt, N);
    k_agg64<<<1184, TPB>>>(p_xt, p_xtf, N);

    // join: gru needs g_hatt from attention branch
    cudaStreamWaitEvent(0, ev_join, 0);
    k_gru2<<<148, TPB, SMG>>>(Wih, Whh, bih, bhh, outp, N);
}

// round 16
// speedup vs baseline: 1.7478x; 1.0327x over previous
#include <cuda_runtime.h>
#include <math.h>

#define MINN  1e-15f
#define PMAX  0.996f      // (1 - 4e-3)/sqrt(c), c=1
#define SLOPE 0.01f

constexpr int NMAX = 100000;
constexpr int EMAX = 800000;
constexpr int WPB  = 8;          // warps per block (non-matvec kernels)
constexpr int TPB  = WPB * 32;   // 256 threads
constexpr int WPBL = 16;         // warps per block (matvec kernels)
constexpr int TPBL = WPBL * 32;  // 512 threads

// ---------------- scratch (static device globals; no allocation) ----------------
__device__ float g_xcat[NMAX * 128];
__device__ float g_xt  [NMAX * 128];
__device__ float g_x2  [NMAX * 128];
__device__ float g_xtf [NMAX * 64];
__device__ float g_hatt[NMAX * 64];
__device__ float g_dis [NMAX];
__device__ int   g_cnt [NMAX];
__device__ int   g_cur [NMAX];
__device__ int   g_off [NMAX + 1];
__device__ int   g_bsum[128];
__device__ int   g_csr [EMAX];
__device__ float g_hb1 [128];
__device__ float g_hb2 [64];

typedef unsigned long long ull;

// ---------------- helpers ----------------
__device__ __forceinline__ float wred(float v) {
#pragma unroll
    for (int o = 16; o; o >>= 1) v += __shfl_xor_sync(0xffffffffu, v, o);
    return v;
}
// fast artanh: poly for |x|<0.25 (rel err <1e-7), MUFU log otherwise (rel err <5e-7)
__device__ __forceinline__ float artanhf_(float x) {
    x = fminf(fmaxf(x, -1.0f + 1e-7f), 1.0f - 1e-7f);
    float x2 = x * x;
    float ser = x * (1.0f + x2 * (0.33333334f + x2 * (0.2f + x2 * (0.14285715f + x2 * 0.11111111f))));
    float lg  = 0.5f * __logf(__fdividef(1.0f + x, 1.0f - x));
    return (x2 < 0.0625f) ? ser : lg;
}
// fast tanh via MUFU ex2 (~1e-6 rel)
__device__ __forceinline__ float tfast(float x) {
    float ax = fabsf(x);
    float t = __expf(-2.0f * ax);
    float r = __fdividef(1.0f - t, 1.0f + t);
    return copysignf(r, x);
}
__device__ __forceinline__ float sigf(float x) {
    return __fdividef(1.0f, 1.0f + __expf(-x));
}
// packed f32x2 ops (sm_103a FFMA2 path)
__device__ __forceinline__ ull fdup(float v) {
    ull d; asm("mov.b64 %0, {%1, %1};" : "=l"(d) : "f"(v)); return d;
}
__device__ __forceinline__ void ffma2(ull& d, ull a, ull b) {
    asm("fma.rn.f32x2 %0, %1, %2, %0;" : "+l"(d) : "l"(a), "l"(b));
}
__device__ __forceinline__ float2 funpack(ull d) {
    float2 r; asm("mov.b64 {%0, %1}, %2;" : "=f"(r.x), "=f"(r.y) : "l"(d)); return r;
}

// ---------------- hyperbolic bias precompute ----------------
__device__ __forceinline__ float blk_red128(float v, float* sh) {
    int t = threadIdx.x;
    sh[t] = v; __syncthreads();
    for (int s = 64; s > 0; s >>= 1) { if (t < s) sh[t] += sh[t + s]; __syncthreads(); }
    float r = sh[0]; __syncthreads();
    return r;
}

__global__ void k_bias(const float* __restrict__ b1, const float* __restrict__ b2) {
    __shared__ float sh[128];
    int t = threadIdx.x;
    float v = b1[t];
    float n2 = blk_red128(v * v, sh);
    float nn = fmaxf(sqrtf(n2), MINN);
    float u = tanhf(nn) / nn * v;
    float pu2 = blk_red128(u * u, sh);
    float pn = fmaxf(sqrtf(pu2), MINN);
    if (pn > PMAX) u *= PMAX / pn;
    g_hb1[t] = u;
    float v2 = (t < 64) ? b2[t] : 0.f;
    float m2 = blk_red128(v2 * v2, sh);
    float mn = fmaxf(sqrtf(m2), MINN);
    float u2 = tanhf(mn) / mn * v2;
    float q2 = blk_red128(u2 * u2, sh);
    float qn = fmaxf(sqrtf(q2), MINN);
    if (qn > PMAX) u2 *= PMAX / qn;
    if (t < 64) g_hb2[t] = u2;
}

// ---------------- init: x = feat@Wl.T + bl ; expmap0 ; proj ; concat hidden ; proj ----------------
__global__ __launch_bounds__(TPBL, 2) void k_init2(const float* __restrict__ feat, const float* __restrict__ Wl,
                                                   const float* __restrict__ bl, const float* __restrict__ hidlast, int n) {
    extern __shared__ unsigned char smraw[];
    ulonglong2* wq = (ulonglong2*)smraw;                               // 64 k2 * 32 lanes (32KB)
    ull* sx = (ull*)(smraw + 64 * 32 * 16);                            // WPBL * 4 * 128 (64KB)
    float* shb = (float*)(smraw + 64 * 32 * 16 + WPBL * 4 * 128 * 8);  // 64
    int t = threadIdx.x;
    for (int idx = t; idx < 64 * 32; idx += TPBL) {
        int k2 = idx >> 5, j = idx & 31;
        float4 v;
        v.x = Wl[j * 128 + 2 * k2];
        v.y = Wl[(j + 32) * 128 + 2 * k2];
        v.z = Wl[j * 128 + 2 * k2 + 1];
        v.w = Wl[(j + 32) * 128 + 2 * k2 + 1];
        ((float4*)wq)[idx] = v;
    }
    if (t < 64) shb[t] = bl[t];
    __syncthreads();
    int warp = t >> 5, lane = t & 31;
    ull* sxw = sx + warp * 512;
    const ulonglong2* sxu = (const ulonglong2*)sxw;
    int ngrp = (n + 3) >> 2;
    for (int grp = blockIdx.x * WPBL + warp; grp < ngrp; grp += gridDim.x * WPBL) {
        int base = grp * 4;
#pragma unroll
        for (int m = 0; m < 4; m++) {
            int nm = min(base + m, n - 1);
            float4 f = ((const float4*)feat)[nm * 32 + lane];
            ulonglong2 d0, d1;
            d0.x = fdup(f.x); d0.y = fdup(f.y); d1.x = fdup(f.z); d1.y = fdup(f.w);
            ((ulonglong2*)(sxw + m * 128))[lane * 2] = d0;
            ((ulonglong2*)(sxw + m * 128))[lane * 2 + 1] = d1;
        }
        __syncwarp();
        ull acc[4] = {0ull, 0ull, 0ull, 0ull};
#pragma unroll 4
        for (int k2 = 0; k2 < 64; k2++) {
            ulonglong2 q = wq[k2 * 32 + lane];
#pragma unroll
            for (int m = 0; m < 4; m++) {
                ulonglong2 xd = sxu[m * 64 + k2];
                ffma2(acc[m], q.x, xd.x);
                ffma2(acc[m], q.y, xd.y);
            }
        }
#pragma unroll
        for (int m = 0; m < 4; m++) {
            int nm = base + m;
            float2 av = funpack(acc[m]);
            float a0 = av.x + shb[lane], a1 = av.y + shb[lane + 32];
            // expmap0
            float s = wred(a0 * a0 + a1 * a1);
            float nn = fmaxf(sqrtf(s), MINN);
            float sc = tfast(nn) / nn; a0 *= sc; a1 *= sc;
            // proj (64-dim)
            s = wred(a0 * a0 + a1 * a1);
            nn = fmaxf(sqrtf(s), MINN);
            if (nn > PMAX) { sc = PMAX / nn; a0 *= sc; a1 *= sc; }
            // concat hidden, proj over 128 dims
            int nmc = min(nm, n - 1);
            float h0 = hidlast[nmc * 64 + lane];
            float h1 = hidlast[nmc * 64 + lane + 32];
            s = wred(a0 * a0 + a1 * a1 + h0 * h0 + h1 * h1);
            nn = fmaxf(sqrtf(s), MINN);
            if (nn > PMAX) { sc = PMAX / nn; a0 *= sc; a1 *= sc; h0 *= sc; h1 *= sc; }
            if (nm < n) {
                g_xcat[nm * 128 + lane]      = a0;
                g_xcat[nm * 128 + lane + 32] = a1;
                g_xcat[nm * 128 + lane + 64] = h0;
                g_xcat[nm * 128 + lane + 96] = h1;
            }
        }
        __syncwarp();
    }
}

// ---------------- CSR build ----------------
__global__ void k_zero2(int n) {
    int i = blockIdx.x * blockDim.x + threadIdx.x;
    if (i < n) { g_cnt[i] = 0; g_cur[i] = 0; }
}
__global__ void k_count(const int* __restrict__ src, int e) {
    int i = blockIdx.x * blockDim.x + threadIdx.x;
    if (i < e) atomicAdd(&g_cnt[src[i]], 1);
}
__global__ void k_scan1(int n) {
    __shared__ int sh[1024];
    int t = threadIdx.x;
    int i = blockIdx.x * 1024 + t;
    int v = (i < n) ? g_cnt[i] : 0;
    sh[t] = v; __syncthreads();
    for (int d = 1; d < 1024; d <<= 1) {
        int x = (t >= d) ? sh[t - d] : 0;
        __syncthreads();
        sh[t] += x; __syncthreads();
    }
    if (i < n) g_off[i] = sh[t] - v;
    if (t == 1023) g_bsum[blockIdx.x] = sh[1023];
}
__global__ void k_scan2(int nb) {
    __shared__ int sh[128];
    int t = threadIdx.x;
    int v = (t < nb) ? g_bsum[t] : 0;
    sh[t] = v; __syncthreads();
    for (int d = 1; d < 128; d <<= 1) {
        int x = (t >= d) ? sh[t - d] : 0;
        __syncthreads();
        sh[t] += x; __syncthreads();
    }
    g_bsum[t] = sh[t] - v;
}
__global__ void k_scan3(int n, int e) {
    int i = blockIdx.x * blockDim.x + threadIdx.x;
    if (i < n) g_off[i] += g_bsum[i >> 10];
    if (i == 0) g_off[n] = e;
}
__global__ void k_dis(int n) {
    int i = blockIdx.x * blockDim.x + threadIdx.x;
    if (i < n) g_dis[i] = rsqrtf((float)(g_cnt[i] + 1));
}
__global__ void k_fill(const int* __restrict__ src, const int* __restrict__ dst, int e) {
    int i = blockIdx.x * blockDim.x + threadIdx.x;
    if (i < e) {
        int s = src[i];
        int p = g_off[s] + atomicAdd(&g_cur[s], 1);
        g_csr[p] = dst[i];
    }
}

// ---------------- hyp_linear (k-paired FFMA2, 4-node blocking, 512-thread blocks) ----------------
template <int P>
__global__ __launch_bounds__(TPBL, 2) void k_lin(const float* __restrict__ xin, const float* __restrict__ W,
                                                 const float* __restrict__ hb, float* __restrict__ xtout, int n) {
    extern __shared__ unsigned char smraw[];
    ulonglong2* wq = (ulonglong2*)smraw;                                     // P*64*32
    float4* sxf = (float4*)(smraw + P * 64 * 32 * 16);                       // WPBL*4*32 float4
    float* shb = (float*)(smraw + P * 64 * 32 * 16 + WPBL * 4 * 32 * 16);    // 64*P
    int t = threadIdx.x;
    for (int idx = t; idx < P * 64 * 32; idx += TPBL) {
        int p = idx >> 11; int r = idx & 2047; int k2 = r >> 5; int j = r & 31;
        float4 v;
        v.x = W[(p * 64 + j) * 128 + 2 * k2];
        v.y = W[(p * 64 + j) * 128 + 2 * k2 + 1];
        v.z = W[(p * 64 + j + 32) * 128 + 2 * k2];
        v.w = W[(p * 64 + j + 32) * 128 + 2 * k2 + 1];
        ((float4*)wq)[idx] = v;
    }
    for (int idx = t; idx < 64 * P; idx += TPBL) shb[idx] = hb[idx];
    __syncthreads();
    int warp = t >> 5, lane = t & 31;
    float4* sxw = sxf + warp * 128;                     // 4 nodes * 32 float4
    const ulonglong2* sxu = (const ulonglong2*)sxw;     // [m*32 + k4]
    constexpr int VO = 2 * P;
    int ngrp = (n + 3) >> 2;
    for (int grp = blockIdx.x * WPBL + warp; grp < ngrp; grp += gridDim.x * WPBL) {
        int base = grp * 4;
        float xn[4];
#pragma unroll
        for (int m = 0; m < 4; m++) {
            int nm = min(base + m, n - 1);
            float4 f = ((const float4*)xin)[nm * 32 + lane];
            sxw[m * 32 + lane] = f;
            float xs = f.x * f.x + f.y * f.y + f.z * f.z + f.w * f.w;
            xn[m] = fmaxf(sqrtf(wred(xs)), MINN);
        }
        __syncwarp();
        ull accA[4][P], accB[4][P];
#pragma unroll
        for (int m = 0; m < 4; m++)
#pragma unroll
            for (int p = 0; p < P; p++) { accA[m][p] = 0ull; accB[m][p] = 0ull; }
#pragma unroll 2
        for (int k4 = 0; k4 < 32; k4++) {
            ulonglong2 wwa[P], wwb[P];
#pragma unroll
            for (int p = 0; p < P; p++) {
                wwa[p] = wq[p * 2048 + (2 * k4) * 32 + lane];
                wwb[p] = wq[p * 2048 + (2 * k4 + 1) * 32 + lane];
            }
#pragma unroll
            for (int m = 0; m < 4; m++) {
                ulonglong2 xp = sxu[m * 32 + k4];       // broadcast: 4 distinct x per 16B
#pragma unroll
                for (int p = 0; p < P; p++) {
                    ffma2(accA[m][p], wwa[p].x, xp.x);
                    ffma2(accB[m][p], wwa[p].y, xp.x);
                    ffma2(accA[m][p], wwb[p].x, xp.y);
                    ffma2(accB[m][p], wwb[p].y, xp.y);
                }
            }
        }
#pragma unroll
        for (int m = 0; m < 4; m++) {
            int nm = base + m;
            float v[VO];
#pragma unroll
            for (int p = 0; p < P; p++) {
                float2 fA = funpack(accA[m][p]);
                float2 fB = funpack(accB[m][p]);
                v[2 * p]     = fA.x + fA.y;
                v[2 * p + 1] = fB.x + fB.y;
            }
            float ms = 0.f;
#pragma unroll
            for (int g = 0; g < VO; g++) ms += v[g] * v[g];
            float mxn2 = wred(ms);
            float mxn = fmaxf(sqrtf(mxn2), MINN);
            float xnn = xn[m];
            float r = tfast(mxn / xnn * artanhf_(xnn)) / mxn;
            if (mxn2 == 0.f) r = 0.f;
#pragma unroll
            for (int g = 0; g < VO; g++) v[g] *= r;
            // proj
            float s = 0.f;
#pragma unroll
            for (int g = 0; g < VO; g++) s += v[g] * v[g];
            s = wred(s);
            float pn = fmaxf(sqrtf(s), MINN);
            if (pn > PMAX) { float f = PMAX / pn;
#pragma unroll
                for (int g = 0; g < VO; g++) v[g] *= f; }
            // mobius_add(v, hb)
            float hx[VO];
            float xx = 0.f, xy = 0.f, yy = 0.f;
#pragma unroll
            for (int g = 0; g < VO; g++) {
                float hv = shb[lane + 32 * g];
                hx[g] = hv;
                xx += v[g] * v[g];
                xy += v[g] * hv;
                yy += hv * hv;
            }
            xx = wred(xx); xy = wred(xy); yy = wred(yy);
            float den = fmaxf(1.f + 2.f * xy + xx * yy, MINN);
            float ca = (1.f + 2.f * xy + yy) / den;
            float cb = (1.f - xx) / den;
#pragma unroll
            for (int g = 0; g < VO; g++) v[g] = ca * v[g] + cb * hx[g];
            // proj
            s = 0.f;
#pragma unroll
            for (int g = 0; g < VO; g++) s += v[g] * v[g];
            s = wred(s);
            pn = fmaxf(sqrtf(s), MINN);
            if (pn > PMAX) { float f = PMAX / pn;
#pragma unroll
                for (int g = 0; g < VO; g++) v[g] *= f; }
            // logmap0
            s = 0.f;
#pragma unroll
            for (int g = 0; g < VO; g++) s += v[g] * v[g];
            s = wred(s);
            pn = fmaxf(sqrtf(s), MINN);
            float a = artanhf_(pn) / pn;
            if (nm < n) {
#pragma unroll
                for (int g = 0; g < VO; g++) xtout[nm * (64 * P) + lane + 32 * g] = v[g] * a;
            }
        }
        __syncwarp();
    }
}

// ---------------- aggregation (CSR gather) + activation chain ----------------
__device__ __forceinline__ float n2_4(float4 a) { return a.x * a.x + a.y * a.y + a.z * a.z + a.w * a.w; }
__device__ __forceinline__ void  mul4(float4& a, float s) { a.x *= s; a.y *= s; a.z *= s; a.w *= s; }

__global__ void k_agg128(const float* __restrict__ xt, float* __restrict__ out, int n) {
    int t = threadIdx.x, warp = t >> 5, lane = t & 31;
    const float4* base = (const float4*)xt;
    for (int node = blockIdx.x * WPB + warp; node < n; node += gridDim.x * WPB) {
        float dn = g_dis[node];
        float4 a = base[node * 32 + lane];
        mul4(a, dn * dn);
        int e1 = g_off[node + 1];
        for (int e = g_off[node]; e < e1; e++) {
            int c = g_csr[e];
            float w = dn * g_dis[c];
            float4 v = base[c * 32 + lane];
            a.x += w * v.x; a.y += w * v.y; a.z += w * v.z; a.w += w * v.w;
        }
        float s, nn, sc;
        s = wred(n2_4(a)); nn = fmaxf(sqrtf(s), MINN); sc = tfast(nn) / nn; mul4(a, sc);
        s = wred(n2_4(a)); nn = fmaxf(sqrtf(s), MINN); if (nn > PMAX) mul4(a, PMAX / nn);
        s = wred(n2_4(a)); nn = fmaxf(sqrtf(s), MINN); sc = artanhf_(nn) / nn; mul4(a, sc);
        a.x = (a.x >= 0.f) ? a.x : SLOPE * a.x;
        a.y = (a.y >= 0.f) ? a.y : SLOPE * a.y;
        a.z = (a.z >= 0.f) ? a.z : SLOPE * a.z;
        a.w = (a.w >= 0.f) ? a.w : SLOPE * a.w;
        s = wred(n2_4(a)); nn = fmaxf(sqrtf(s), MINN); sc = tfast(nn) / nn; mul4(a, sc);
        s = wred(n2_4(a)); nn = fmaxf(sqrtf(s), MINN); if (nn > PMAX) mul4(a, PMAX / nn);
        s = wred(n2_4(a)); nn = fmaxf(sqrtf(s), MINN); if (nn > PMAX) mul4(a, PMAX / nn);
        ((float4*)out)[node * 32 + lane] = a;
    }
}

__global__ void k_agg64(const float* __restrict__ xt, float* __restrict__ out, int n) {
    int t = threadIdx.x, warp = t >> 5, lane = t & 31;
    const float2* base = (const float2*)xt;
    for (int node = blockIdx.x * WPB + warp; node < n; node += gridDim.x * WPB) {
        float dn = g_dis[node];
        float2 a = base[node * 32 + lane];
        float ws = dn * dn;
        a.x *= ws; a.y *= ws;
        int e1 = g_off[node + 1];
        for (int e = g_off[node]; e < e1; e++) {
            int c = g_csr[e];
            float w = dn * g_dis[c];
            float2 v = base[c * 32 + lane];
            a.x += w * v.x; a.y += w * v.y;
        }
        float s, nn, sc;
        s = wred(a.x * a.x + a.y * a.y); nn = fmaxf(sqrtf(s), MINN); sc = tfast(nn) / nn; a.x *= sc; a.y *= sc;
        s = wred(a.x * a.x + a.y * a.y); nn = fmaxf(sqrtf(s), MINN); if (nn > PMAX) { sc = PMAX / nn; a.x *= sc; a.y *= sc; }
        s = wred(a.x * a.x + a.y * a.y); nn = fmaxf(sqrtf(s), MINN); sc = artanhf_(nn) / nn; a.x *= sc; a.y *= sc;
        a.x = (a.x >= 0.f) ? a.x : SLOPE * a.x;
        a.y = (a.y >= 0.f) ? a.y : SLOPE * a.y;
        s = wred(a.x * a.x + a.y * a.y); nn = fmaxf(sqrtf(s), MINN); sc = tfast(nn) / nn; a.x *= sc; a.y *= sc;
        s = wred(a.x * a.x + a.y * a.y); nn = fmaxf(sqrtf(s), MINN); if (nn > PMAX) { sc = PMAX / nn; a.x *= sc; a.y *= sc; }
        s = wred(a.x * a.x + a.y * a.y); nn = fmaxf(sqrtf(s), MINN); sc = artanhf_(nn) / nn; a.x *= sc; a.y *= sc;
        ((float2*)out)[node * 32 + lane] = a;
    }
}

// ---------------- HTA window attention (WIN=5 specialized, FFMA2) ----------------
__global__ __launch_bounds__(TPB) void k_att5(const float* __restrict__ hiddens, const float* __restrict__ Q,
                                              const float* __restrict__ ratt, int n) {
    __shared__ ulonglong2 wq[32 * 32];    // 16KB
    __shared__ ull sxs[WPB * 5 * 64];     // 20KB
    __shared__ float shr[64];
    int t = threadIdx.x;
    for (int idx = t; idx < 32 * 32; idx += TPB) {
        int k2 = idx >> 5, j = idx & 31;
        float4 v;
        v.x = Q[(2 * k2) * 64 + j];
        v.y = Q[(2 * k2) * 64 + j + 32];
        v.z = Q[(2 * k2 + 1) * 64 + j];
        v.w = Q[(2 * k2 + 1) * 64 + j + 32];
        ((float4*)wq)[idx] = v;
    }
    if (t < 64) shr[t] = ratt[t];
    __syncthreads();
    int warp = t >> 5, lane = t & 31;
    ull* sxw = sxs + warp * 5 * 64;
    const ulonglong2* sxu = (const ulonglong2*)sxw;
    const float inv5 = 0.2f;
    for (int node = blockIdx.x * WPB + warp; node < n; node += gridDim.x * WPB) {
        float hl0[5], hl1[5], ew[5];
#pragma unroll
        for (int w = 0; w < 5; w++) {
            size_t off = ((size_t)w * n + node) * 64;
            float v0 = hiddens[off + lane];
            float v1 = hiddens[off + lane + 32];
            float s = wred(v0 * v0 + v1 * v1);
            float pn = fmaxf(sqrtf(s), MINN);
            float sc = artanhf_(pn) / pn;
            v0 *= sc; v1 *= sc;
            hl0[w] = v0; hl1[w] = v1;
            sxw[w * 64 + lane] = fdup(v0);
            sxw[w * 64 + lane + 32] = fdup(v1);
        }
        __syncwarp();
        ull acc[5] = {0ull, 0ull, 0ull, 0ull, 0ull};
#pragma unroll 4
        for (int k2 = 0; k2 < 32; k2++) {
            ulonglong2 q = wq[k2 * 32 + lane];
#pragma unroll
            for (int w = 0; w < 5; w++) {
                ulonglong2 xd = sxu[w * 32 + k2];
                ffma2(acc[w], q.x, xd.x);
                ffma2(acc[w], q.y, xd.y);
            }
        }
#pragma unroll
        for (int w = 0; w < 5; w++) {
            float2 f = funpack(acc[w]);
            float ep = tfast(f.x) * shr[lane] + tfast(f.y) * shr[lane + 32];
            ew[w] = wred(ep);
        }
        float m = -1e30f;
#pragma unroll
        for (int w = 0; w < 5; w++) m = fmaxf(m, ew[w]);
        float ssum = 0.f;
#pragma unroll
        for (int w = 0; w < 5; w++) { ew[w] = __expf(ew[w] - m); ssum += ew[w]; }
        float inv = inv5 / ssum;
        float o0 = 0.f, o1 = 0.f;
#pragma unroll
        for (int w = 0; w < 5; w++) { o0 += ew[w] * hl0[w]; o1 += ew[w] * hl1[w]; }
        g_hatt[node * 64 + lane]      = o0 * inv;
        g_hatt[node * 64 + lane + 32] = o1 * inv;
        __syncwarp();
    }
}

// generic fallback (win != 5)
__global__ void k_att(const float* __restrict__ hiddens, const float* __restrict__ Q,
                      const float* __restrict__ ratt, int n, int win) {
    __shared__ float shQ[64 * 64];
    __shared__ float shr[64];
    __shared__ float shh[WPB][64];
    int t = threadIdx.x;
    for (int idx = t; idx < 64 * 64; idx += TPB) shQ[idx] = Q[idx];
    if (t < 64) shr[t] = ratt[t];
    __syncthreads();
    int warp = t >> 5, lane = t & 31;
    float invwin = 1.0f / (float)win;
    for (int node = blockIdx.x * WPB + warp; node < n; node += gridDim.x * WPB) {
        float hl0[8], hl1[8], ew[8];
        for (int w = 0; w < win; w++) {
            size_t off = ((size_t)w * n + node) * 64;
            float v0 = hiddens[off + lane];
            float v1 = hiddens[off + lane + 32];
            float s = wred(v0 * v0 + v1 * v1);
            float pn = fmaxf(sqrtf(s), MINN);
            float sc = artanhf_(pn) / pn;
            v0 *= sc; v1 *= sc;
            hl0[w] = v0; hl1[w] = v1;
            shh[warp][lane] = v0; shh[warp][lane + 32] = v1;
            __syncwarp();
            float ep = 0.f;
#pragma unroll
            for (int g = 0; g < 2; g++) {
                int j = lane + 32 * g;
                float a = 0.f;
                for (int k = 0; k < 64; k++) a += shh[warp][k] * shQ[k * 64 + j];
                ep += tfast(a) * shr[j];
            }
            ew[w] = wred(ep);
            __syncwarp();
        }
        float m = -1e30f;
        for (int w = 0; w < win; w++) m = fmaxf(m, ew[w]);
        float ssum = 0.f;
        for (int w = 0; w < win; w++) { ew[w] = __expf(ew[w] - m); ssum += ew[w]; }
        float inv = invwin / ssum;
        float o0 = 0.f, o1 = 0.f;
        for (int w = 0; w < win; w++) { o0 += ew[w] * hl0[w]; o1 += ew[w] * hl1[w]; }
        g_hatt[node * 64 + lane]      = o0 * inv;
        g_hatt[node * 64 + lane + 32] = o1 * inv;
    }
}

// ---------------- GRU (FFMA2, 8-node blocking) + final expmap0/proj ----------------
__global__ __launch_bounds__(TPB) void k_gru2(const float* __restrict__ Wih, const float* __restrict__ Whh,
                                              const float* __restrict__ bih, const float* __restrict__ bhh,
                                              float* __restrict__ outp, int n) {
    extern __shared__ unsigned char smraw[];
    ulonglong2* wqi = (ulonglong2*)smraw;                      // 3*32*32
    ulonglong2* wqh = (ulonglong2*)(smraw + 49152);            // 3*32*32
    ull* sxx = (ull*)(smraw + 98304);                          // WPB*8*64
    ull* sxh = (ull*)(smraw + 131072);                         // WPB*8*64
    float* sbi = (float*)(smraw + 163840);                     // 192
    float* sbh = (float*)(smraw + 164608);                     // 192
    int t = threadIdx.x;
    for (int idx = t; idx < 3 * 32 * 32; idx += TPB) {
        int p = idx >> 10; int r = idx & 1023; int k2 = r >> 5; int j = r & 31;
        float4 vi, vh;
        vi.x = Wih[(p * 64 + j) * 64 + 2 * k2];
        vi.y = Wih[(p * 64 + j + 32) * 64 + 2 * k2];
        vi.z = Wih[(p * 64 + j) * 64 + 2 * k2 + 1];
        vi.w = Wih[(p * 64 + j + 32) * 64 + 2 * k2 + 1];
        vh.x = Whh[(p * 64 + j) * 64 + 2 * k2];
        vh.y = Whh[(p * 64 + j + 32) * 64 + 2 * k2];
        vh.z = Whh[(p * 64 + j) * 64 + 2 * k2 + 1];
        vh.w = Whh[(p * 64 + j + 32) * 64 + 2 * k2 + 1];
        ((float4*)wqi)[idx] = vi;
        ((float4*)wqh)[idx] = vh;
    }
    if (t < 192) { sbi[t] = bih[t]; sbh[t] = bhh[t]; }
    __syncthreads();
    int warp = t >> 5, lane = t & 31;
    ull* sxxw = sxx + warp * 512;
    ull* sxhw = sxh + warp * 512;
    const ulonglong2* sxxu = (const ulonglong2*)sxxw;
    const ulonglong2* sxhu = (const ulonglong2*)sxhw;
    int ngrp = (n + 7) >> 3;
    for (int grp = blockIdx.x * WPB + warp; grp < ngrp; grp += gridDim.x * WPB) {
        int base = grp * 8;
        float h0r[8], h1r[8];
#pragma unroll
        for (int m = 0; m < 8; m++) {
            int nm = min(base + m, n - 1);
            float x0 = g_xtf[nm * 64 + lane], x1 = g_xtf[nm * 64 + lane + 32];
            float h0 = g_hatt[nm * 64 + lane], h1 = g_hatt[nm * 64 + lane + 32];
            sxxw[m * 64 + lane] = fdup(x0);
            sxxw[m * 64 + lane + 32] = fdup(x1);
            sxhw[m * 64 + lane] = fdup(h0);
            sxhw[m * 64 + lane + 32] = fdup(h1);
            h0r[m] = h0; h1r[m] = h1;
        }
        __syncwarp();
        ull gi[8][3], gh[8][3];
#pragma unroll
        for (int m = 0; m < 8; m++)
#pragma unroll
            for (int p = 0; p < 3; p++) { gi[m][p] = 0ull; gh[m][p] = 0ull; }
#pragma unroll 1
        for (int k2 = 0; k2 < 32; k2++) {
            ulonglong2 qi[3], qh[3];
#pragma unroll
            for (int p = 0; p < 3; p++) {
                qi[p] = wqi[p * 1024 + k2 * 32 + lane];
                qh[p] = wqh[p * 1024 + k2 * 32 + lane];
            }
#pragma unroll
            for (int m = 0; m < 8; m++) {
                ulonglong2 xd = sxxu[m * 32 + k2];
                ulonglong2 hd = sxhu[m * 32 + k2];
#pragma unroll
                for (int p = 0; p < 3; p++) {
                    ffma2(gi[m][p], qi[p].x, xd.x);
                    ffma2(gi[m][p], qi[p].y, xd.y);
                    ffma2(gh[m][p], qh[p].x, hd.x);
                    ffma2(gh[m][p], qh[p].y, hd.y);
                }
            }
        }
#pragma unroll
        for (int m = 0; m < 8; m++) {
            int nm = base + m;
            float2 i0 = funpack(gi[m][0]), i1 = funpack(gi[m][1]), i2 = funpack(gi[m][2]);
            float2 hh0 = funpack(gh[m][0]), hh1 = funpack(gh[m][1]), hh2 = funpack(gh[m][2]);
            float ir0 = i0.x + sbi[lane],        ir1 = i0.y + sbi[lane + 32];
            float iz0 = i1.x + sbi[lane + 64],   iz1 = i1.y + sbi[lane + 96];
            float in0 = i2.x + sbi[lane + 128],  in1 = i2.y + sbi[lane + 160];
            float hr0 = hh0.x + sbh[lane],       hr1 = hh0.y + sbh[lane + 32];
            float hz0 = hh1.x + sbh[lane + 64],  hz1 = hh1.y + sbh[lane + 96];
            float hn0 = hh2.x + sbh[lane + 128], hn1 = hh2.y + sbh[lane + 160];
            float r0 = sigf(ir0 + hr0), r1 = sigf(ir1 + hr1);
            float z0 = sigf(iz0 + hz0), z1 = sigf(iz1 + hz1);
            float n0 = tfast(in0 + r0 * hn0), n1 = tfast(in1 + r1 * hn1);
            float o0 = (1.f - z0) * n0 + z0 * h0r[m];
            float o1 = (1.f - z1) * n1 + z1 * h1r[m];
            float s = wred(o0 * o0 + o1 * o1);
            float nn = fmaxf(sqrtf(s), MINN);
            float sc = tfast(nn) / nn; o0 *= sc; o1 *= sc;
            s = wred(o0 * o0 + o1 * o1);
            nn = fmaxf(sqrtf(s), MINN);
            if (nn > PMAX) { sc = PMAX / nn; o0 *= sc; o1 *= sc; }
            if (nm < n) {
                outp[nm * 64 + lane]      = o0;
                outp[nm * 64 + lane + 32] = o1;
            }
        }
        __syncwarp();
    }
}

// ---------------- launch ----------------
extern "C" void kernel_launch(void* const* d_in, const int* in_sizes, int n_in,
                              void* d_out, int out_size) {
    const int*   eidx = (const int*)  d_in[0];
    const float* feat = (const float*)d_in[1];
    const float* Wl   = (const float*)d_in[2];
    const float* bl   = (const float*)d_in[3];
    const float* W1   = (const float*)d_in[4];
    const float* b1   = (const float*)d_in[5];
    const float* W2   = (const float*)d_in[6];
    const float* b2   = (const float*)d_in[7];
    const float* Q    = (const float*)d_in[8];
    const float* ratt = (const float*)d_in[9];
    const float* Wih  = (const float*)d_in[10];
    const float* Whh  = (const float*)d_in[11];
    const float* bih  = (const float*)d_in[12];
    const float* bhh  = (const float*)d_in[13];
    const float* hidd = (const float*)d_in[14];
    float* outp = (float*)d_out;

    int E = in_sizes[0] / 2;
    int N = in_sizes[1] / 128;
    int WIN = in_sizes[14] / (N * 64);
    if (N > NMAX || E > EMAX) return;
    const int* src = eidx;
    const int* dst = eidx + E;

    float *p_xcat, *p_xt, *p_x2, *p_xtf, *p_hb1, *p_hb2;
    cudaGetSymbolAddress((void**)&p_xcat, g_xcat);
    cudaGetSymbolAddress((void**)&p_xt,   g_xt);
    cudaGetSymbolAddress((void**)&p_x2,   g_x2);
    cudaGetSymbolAddress((void**)&p_xtf,  g_xtf);
    cudaGetSymbolAddress((void**)&p_hb1,  g_hb1);
    cudaGetSymbolAddress((void**)&p_hb2,  g_hb2);

    // side streams + fork/join events (created once on first, non-capture call)
    static cudaStream_t s_att = nullptr, s_csr = nullptr;
    static cudaEvent_t  ev_fork = nullptr, ev_join = nullptr, ev_csr = nullptr;
    if (s_att == nullptr) {
        cudaStreamCreateWithFlags(&s_att, cudaStreamNonBlocking);
        cudaStreamCreateWithFlags(&s_csr, cudaStreamNonBlocking);
        cudaEventCreateWithFlags(&ev_fork, cudaEventDisableTiming);
        cudaEventCreateWithFlags(&ev_join, cudaEventDisableTiming);
        cudaEventCreateWithFlags(&ev_csr,  cudaEventDisableTiming);
    }

    const int SMI  = 64 * 32 * 16 + WPBL * 4 * 128 * 8 + 64 * 4;            // 98560
    const int SML1 = 2 * 64 * 32 * 16 + WPBL * 4 * 32 * 16 + 128 * 4;       // 98816
    const int SML2 = 64 * 32 * 16 + WPBL * 4 * 32 * 16 + 64 * 4;            // 65792
    const int SMG  = 2 * 49152 + 2 * WPB * 8 * 64 * 8 + 2 * 192 * 4;        // 165376
    cudaFuncSetAttribute(k_init2,   cudaFuncAttributeMaxDynamicSharedMemorySize, SMI);
    cudaFuncSetAttribute(k_lin<2>,  cudaFuncAttributeMaxDynamicSharedMemorySize, SML1);
    cudaFuncSetAttribute(k_lin<1>,  cudaFuncAttributeMaxDynamicSharedMemorySize, SML2);
    cudaFuncSetAttribute(k_gru2,    cudaFuncAttributeMaxDynamicSharedMemorySize, SMG);

    int eb = (E + 255) / 256;
    int nb = (N + 255) / 256;
    int NB = (N + 1023) / 1024;

    // fork both side branches off the origin stream
    cudaEventRecord(ev_fork, 0);

    // attention branch (depends only on inputs; feeds only gru)
    cudaStreamWaitEvent(s_att, ev_fork, 0);
    if (WIN == 5) k_att5<<<592, TPB, 0, s_att>>>(hidd, Q, ratt, N);
    else          k_att<<<1184, TPB, 0, s_att>>>(hidd, Q, ratt, N, WIN);
    cudaEventRecord(ev_join, s_att);

    // CSR branch (depends only on edge_index; feeds agg128/agg64)
    cudaStreamWaitEvent(s_csr, ev_fork, 0);
    k_zero2<<<nb, 256, 0, s_csr>>>(N);
    k_count<<<eb, 256, 0, s_csr>>>(src, E);
    k_scan1<<<NB, 1024, 0, s_csr>>>(N);
    k_scan2<<<1, 128, 0, s_csr>>>(NB);
    k_scan3<<<nb, 256, 0, s_csr>>>(N, E);
    k_dis<<<nb, 256, 0, s_csr>>>(N);
    k_fill<<<eb, 256, 0, s_csr>>>(src, dst, E);
    cudaEventRecord(ev_csr, s_csr);

    // main chain
    k_bias<<<1, 128>>>(b1, b2);
    k_init2<<<296, TPBL, SMI>>>(feat, Wl, bl, hidd + (size_t)(WIN - 1) * N * 64, N);
    k_lin<2><<<296, TPBL, SML1>>>(p_xcat, W1, p_hb1, p_xt, N);
    cudaStreamWaitEvent(0, ev_csr, 0);
    k_agg128<<<1184, TPB>>>(p_xt, p_x2, N);
    k_lin<1><<<296, TPBL, SML2>>>(p_x2, W2, p_hb2, p_xt, N);
    k_agg64<<<1184, TPB>>>(p_xt, p_xtf, N);

    // join: gru needs g_hatt from attention branch
    cudaStreamWaitEvent(0, ev_join, 0);
    k_gru2<<<148, TPB, SMG>>>(Wih, Whh, bih, bhh, outp, N);
}

// round 17
// speedup vs baseline: 1.8516x; 1.0594x over previous
#include <cuda_runtime.h>
#include <math.h>

#define MINN  1e-15f
#define PMAX  0.996f      // (1 - 4e-3)/sqrt(c), c=1
#define SLOPE 0.01f

constexpr int NMAX = 100000;
constexpr int EMAX = 800000;
constexpr int WPB  = 8;          // warps per block (non-matvec kernels)
constexpr int TPB  = WPB * 32;   // 256 threads
constexpr int WPBL = 16;         // warps per block (matvec kernels)
constexpr int TPBL = WPBL * 32;  // 512 threads

// ---------------- scratch (static device globals; no allocation) ----------------
__device__ float g_xcat[NMAX * 128];
__device__ float g_xt  [NMAX * 128];
__device__ float g_x2  [NMAX * 128];
__device__ float g_xtf [NMAX * 64];
__device__ float g_hatt[NMAX * 64];
__device__ float g_dis [NMAX];
__device__ int   g_cnt [NMAX];
__device__ int   g_cur [NMAX];
__device__ int   g_off [NMAX + 1];
__device__ int   g_bsum[128];
__device__ int   g_csr [EMAX];
__device__ float g_hb1 [128];
__device__ float g_hb2 [64];

typedef unsigned long long ull;

// ---------------- helpers ----------------
__device__ __forceinline__ float wred(float v) {
#pragma unroll
    for (int o = 16; o; o >>= 1) v += __shfl_xor_sync(0xffffffffu, v, o);
    return v;
}
// fast artanh: poly for |x|<0.25 (rel err <1e-7), MUFU log otherwise (rel err <5e-7)
__device__ __forceinline__ float artanhf_(float x) {
    x = fminf(fmaxf(x, -1.0f + 1e-7f), 1.0f - 1e-7f);
    float x2 = x * x;
    float ser = x * (1.0f + x2 * (0.33333334f + x2 * (0.2f + x2 * (0.14285715f + x2 * 0.11111111f))));
    float lg  = 0.5f * __logf(__fdividef(1.0f + x, 1.0f - x));
    return (x2 < 0.0625f) ? ser : lg;
}
// fast tanh via MUFU ex2 (~1e-6 rel)
__device__ __forceinline__ float tfast(float x) {
    float ax = fabsf(x);
    float t = __expf(-2.0f * ax);
    float r = __fdividef(1.0f - t, 1.0f + t);
    return copysignf(r, x);
}
__device__ __forceinline__ float sigf(float x) {
    return __fdividef(1.0f, 1.0f + __expf(-x));
}
// packed f32x2 ops (sm_103a FFMA2 path)
__device__ __forceinline__ ull fdup(float v) {
    ull d; asm("mov.b64 %0, {%1, %1};" : "=l"(d) : "f"(v)); return d;
}
__device__ __forceinline__ void ffma2(ull& d, ull a, ull b) {
    asm("fma.rn.f32x2 %0, %1, %2, %0;" : "+l"(d) : "l"(a), "l"(b));
}
__device__ __forceinline__ float2 funpack(ull d) {
    float2 r; asm("mov.b64 {%0, %1}, %2;" : "=f"(r.x), "=f"(r.y) : "l"(d)); return r;
}

// ---------------- hyperbolic bias precompute ----------------
__device__ __forceinline__ float blk_red128(float v, float* sh) {
    int t = threadIdx.x;
    sh[t] = v; __syncthreads();
    for (int s = 64; s > 0; s >>= 1) { if (t < s) sh[t] += sh[t + s]; __syncthreads(); }
    float r = sh[0]; __syncthreads();
    return r;
}

__global__ void k_bias(const float* __restrict__ b1, const float* __restrict__ b2) {
    __shared__ float sh[128];
    int t = threadIdx.x;
    float v = b1[t];
    float n2 = blk_red128(v * v, sh);
    float nn = fmaxf(sqrtf(n2), MINN);
    float u = tanhf(nn) / nn * v;
    float pu2 = blk_red128(u * u, sh);
    float pn = fmaxf(sqrtf(pu2), MINN);
    if (pn > PMAX) u *= PMAX / pn;
    g_hb1[t] = u;
    float v2 = (t < 64) ? b2[t] : 0.f;
    float m2 = blk_red128(v2 * v2, sh);
    float mn = fmaxf(sqrtf(m2), MINN);
    float u2 = tanhf(mn) / mn * v2;
    float q2 = blk_red128(u2 * u2, sh);
    float qn = fmaxf(sqrtf(q2), MINN);
    if (qn > PMAX) u2 *= PMAX / qn;
    if (t < 64) g_hb2[t] = u2;
}

// ---------------- init: x = feat@Wl.T + bl ; expmap0 ; proj ; concat hidden ; proj ----------------
__global__ __launch_bounds__(TPBL, 2) void k_init2(const float* __restrict__ feat, const float* __restrict__ Wl,
                                                   const float* __restrict__ bl, const float* __restrict__ hidlast, int n) {
    extern __shared__ unsigned char smraw[];
    ulonglong2* wq = (ulonglong2*)smraw;                               // 64 k2 * 32 lanes (32KB)
    ull* sx = (ull*)(smraw + 64 * 32 * 16);                            // WPBL * 4 * 128 (64KB)
    float* shb = (float*)(smraw + 64 * 32 * 16 + WPBL * 4 * 128 * 8);  // 64
    int t = threadIdx.x;
    for (int idx = t; idx < 64 * 32; idx += TPBL) {
        int k2 = idx >> 5, j = idx & 31;
        float4 v;
        v.x = Wl[j * 128 + 2 * k2];
        v.y = Wl[(j + 32) * 128 + 2 * k2];
        v.z = Wl[j * 128 + 2 * k2 + 1];
        v.w = Wl[(j + 32) * 128 + 2 * k2 + 1];
        ((float4*)wq)[idx] = v;
    }
    if (t < 64) shb[t] = bl[t];
    __syncthreads();
    int warp = t >> 5, lane = t & 31;
    ull* sxw = sx + warp * 512;
    const ulonglong2* sxu = (const ulonglong2*)sxw;
    int ngrp = (n + 3) >> 2;
    for (int grp = blockIdx.x * WPBL + warp; grp < ngrp; grp += gridDim.x * WPBL) {
        int base = grp * 4;
#pragma unroll
        for (int m = 0; m < 4; m++) {
            int nm = min(base + m, n - 1);
            float4 f = ((const float4*)feat)[nm * 32 + lane];
            ulonglong2 d0, d1;
            d0.x = fdup(f.x); d0.y = fdup(f.y); d1.x = fdup(f.z); d1.y = fdup(f.w);
            ((ulonglong2*)(sxw + m * 128))[lane * 2] = d0;
            ((ulonglong2*)(sxw + m * 128))[lane * 2 + 1] = d1;
        }
        __syncwarp();
        ull acc[4] = {0ull, 0ull, 0ull, 0ull};
#pragma unroll 4
        for (int k2 = 0; k2 < 64; k2++) {
            ulonglong2 q = wq[k2 * 32 + lane];
#pragma unroll
            for (int m = 0; m < 4; m++) {
                ulonglong2 xd = sxu[m * 64 + k2];
                ffma2(acc[m], q.x, xd.x);
                ffma2(acc[m], q.y, xd.y);
            }
        }
#pragma unroll
        for (int m = 0; m < 4; m++) {
            int nm = base + m;
            float2 av = funpack(acc[m]);
            float a0 = av.x + shb[lane], a1 = av.y + shb[lane + 32];
            // expmap0 (norm propagated)
            float s = wred(a0 * a0 + a1 * a1);
            float nn = fmaxf(sqrtf(s), MINN);
            float tv = tfast(nn);
            float sc = tv / nn; a0 *= sc; a1 *= sc;
            float cur = tv;
            // proj (64-dim) via propagated norm
            if (cur > PMAX) { sc = PMAX / cur; a0 *= sc; a1 *= sc; }
            // concat hidden, proj over 128 dims (genuine: includes h)
            int nmc = min(nm, n - 1);
            float h0 = hidlast[nmc * 64 + lane];
            float h1 = hidlast[nmc * 64 + lane + 32];
            s = wred(a0 * a0 + a1 * a1 + h0 * h0 + h1 * h1);
            nn = fmaxf(sqrtf(s), MINN);
            if (nn > PMAX) { sc = PMAX / nn; a0 *= sc; a1 *= sc; h0 *= sc; h1 *= sc; }
            if (nm < n) {
                g_xcat[nm * 128 + lane]      = a0;
                g_xcat[nm * 128 + lane + 32] = a1;
                g_xcat[nm * 128 + lane + 64] = h0;
                g_xcat[nm * 128 + lane + 96] = h1;
            }
        }
        __syncwarp();
    }
}

// ---------------- CSR build ----------------
__global__ void k_zero2(int n) {
    int i = blockIdx.x * blockDim.x + threadIdx.x;
    if (i < n) { g_cnt[i] = 0; g_cur[i] = 0; }
}
__global__ void k_count(const int* __restrict__ src, int e) {
    int i = blockIdx.x * blockDim.x + threadIdx.x;
    if (i < e) atomicAdd(&g_cnt[src[i]], 1);
}
__global__ void k_scan1(int n) {
    __shared__ int sh[1024];
    int t = threadIdx.x;
    int i = blockIdx.x * 1024 + t;
    int v = (i < n) ? g_cnt[i] : 0;
    sh[t] = v; __syncthreads();
    for (int d = 1; d < 1024; d <<= 1) {
        int x = (t >= d) ? sh[t - d] : 0;
        __syncthreads();
        sh[t] += x; __syncthreads();
    }
    if (i < n) g_off[i] = sh[t] - v;
    if (t == 1023) g_bsum[blockIdx.x] = sh[1023];
}
__global__ void k_scan2(int nb) {
    __shared__ int sh[128];
    int t = threadIdx.x;
    int v = (t < nb) ? g_bsum[t] : 0;
    sh[t] = v; __syncthreads();
    for (int d = 1; d < 128; d <<= 1) {
        int x = (t >= d) ? sh[t - d] : 0;
        __syncthreads();
        sh[t] += x; __syncthreads();
    }
    g_bsum[t] = sh[t] - v;
}
__global__ void k_scan3(int n, int e) {
    int i = blockIdx.x * blockDim.x + threadIdx.x;
    if (i < n) g_off[i] += g_bsum[i >> 10];
    if (i == 0) g_off[n] = e;
}
__global__ void k_dis(int n) {
    int i = blockIdx.x * blockDim.x + threadIdx.x;
    if (i < n) g_dis[i] = rsqrtf((float)(g_cnt[i] + 1));
}
__global__ void k_fill(const int* __restrict__ src, const int* __restrict__ dst, int e) {
    int i = blockIdx.x * blockDim.x + threadIdx.x;
    if (i < e) {
        int s = src[i];
        int p = g_off[s] + atomicAdd(&g_cur[s], 1);
        g_csr[p] = dst[i];
    }
}

// ---------------- hyp_linear (k-paired FFMA2, 4-node blocking, 512-thread blocks) ----------------
template <int P>
__global__ __launch_bounds__(TPBL, 2) void k_lin(const float* __restrict__ xin, const float* __restrict__ W,
                                                 const float* __restrict__ hb, float* __restrict__ xtout, int n) {
    extern __shared__ unsigned char smraw[];
    ulonglong2* wq = (ulonglong2*)smraw;                                     // P*64*32
    float4* sxf = (float4*)(smraw + P * 64 * 32 * 16);                       // WPBL*4*32 float4
    float* shb = (float*)(smraw + P * 64 * 32 * 16 + WPBL * 4 * 32 * 16);    // 64*P
    int t = threadIdx.x;
    for (int idx = t; idx < P * 64 * 32; idx += TPBL) {
        int p = idx >> 11; int r = idx & 2047; int k2 = r >> 5; int j = r & 31;
        float4 v;
        v.x = W[(p * 64 + j) * 128 + 2 * k2];
        v.y = W[(p * 64 + j) * 128 + 2 * k2 + 1];
        v.z = W[(p * 64 + j + 32) * 128 + 2 * k2];
        v.w = W[(p * 64 + j + 32) * 128 + 2 * k2 + 1];
        ((float4*)wq)[idx] = v;
    }
    for (int idx = t; idx < 64 * P; idx += TPBL) shb[idx] = hb[idx];
    __syncthreads();
    int warp = t >> 5, lane = t & 31;
    float4* sxw = sxf + warp * 128;                     // 4 nodes * 32 float4
    const ulonglong2* sxu = (const ulonglong2*)sxw;     // [m*32 + k4]
    constexpr int VO = 2 * P;
    // precompute yy = ||hb||^2 once per warp (constant across nodes)
    float hsum = 0.f;
#pragma unroll
    for (int g = 0; g < VO; g++) { float hv = shb[lane + 32 * g]; hsum += hv * hv; }
    const float hyy = wred(hsum);
    int ngrp = (n + 3) >> 2;
    for (int grp = blockIdx.x * WPBL + warp; grp < ngrp; grp += gridDim.x * WPBL) {
        int base = grp * 4;
        float xn[4];
#pragma unroll
        for (int m = 0; m < 4; m++) {
            int nm = min(base + m, n - 1);
            float4 f = ((const float4*)xin)[nm * 32 + lane];
            sxw[m * 32 + lane] = f;
            float xs = f.x * f.x + f.y * f.y + f.z * f.z + f.w * f.w;
            xn[m] = fmaxf(sqrtf(wred(xs)), MINN);
        }
        __syncwarp();
        ull accA[4][P], accB[4][P];
#pragma unroll
        for (int m = 0; m < 4; m++)
#pragma unroll
            for (int p = 0; p < P; p++) { accA[m][p] = 0ull; accB[m][p] = 0ull; }
#pragma unroll 2
        for (int k4 = 0; k4 < 32; k4++) {
            ulonglong2 wwa[P], wwb[P];
#pragma unroll
            for (int p = 0; p < P; p++) {
                wwa[p] = wq[p * 2048 + (2 * k4) * 32 + lane];
                wwb[p] = wq[p * 2048 + (2 * k4 + 1) * 32 + lane];
            }
#pragma unroll
            for (int m = 0; m < 4; m++) {
                ulonglong2 xp = sxu[m * 32 + k4];       // broadcast: 4 distinct x per 16B
#pragma unroll
                for (int p = 0; p < P; p++) {
                    ffma2(accA[m][p], wwa[p].x, xp.x);
                    ffma2(accB[m][p], wwa[p].y, xp.x);
                    ffma2(accA[m][p], wwb[p].x, xp.y);
                    ffma2(accB[m][p], wwb[p].y, xp.y);
                }
            }
        }
#pragma unroll
        for (int m = 0; m < 4; m++) {
            int nm = base + m;
            float v[VO];
#pragma unroll
            for (int p = 0; p < P; p++) {
                float2 fA = funpack(accA[m][p]);
                float2 fB = funpack(accB[m][p]);
                v[2 * p]     = fA.x + fA.y;
                v[2 * p + 1] = fB.x + fB.y;
            }
            float ms = 0.f;
#pragma unroll
            for (int g = 0; g < VO; g++) ms += v[g] * v[g];
            float mxn2 = wred(ms);
            float mxn = fmaxf(sqrtf(mxn2), MINN);
            float xnn = xn[m];
            float tv = tfast(mxn / xnn * artanhf_(xnn));   // >= 0
            float r = tv / mxn;
            if (mxn2 == 0.f) { r = 0.f; tv = 0.f; }
#pragma unroll
            for (int g = 0; g < VO; g++) v[g] *= r;
            float cur = tv;                                 // propagated norm
            // proj
            if (cur > PMAX) { float f = PMAX / cur;
#pragma unroll
                for (int g = 0; g < VO; g++) v[g] *= f;
                cur = PMAX; }
            // mobius_add(v, hb): xx = cur^2 (propagated), yy = hyy (const), xy genuine
            float hx[VO];
            float xy = 0.f;
#pragma unroll
            for (int g = 0; g < VO; g++) {
                float hv = shb[lane + 32 * g];
                hx[g] = hv;
                xy += v[g] * hv;
            }
            xy = wred(xy);
            float xx = cur * cur;
            float den = fmaxf(1.f + 2.f * xy + xx * hyy, MINN);
            float ca = (1.f + 2.f * xy + hyy) / den;
            float cb = (1.f - xx) / den;
#pragma unroll
            for (int g = 0; g < VO; g++) v[g] = ca * v[g] + cb * hx[g];
            // proj (genuine norm after mobius)
            float s = 0.f;
#pragma unroll
            for (int g = 0; g < VO; g++) s += v[g] * v[g];
            s = wred(s);
            float pn = fmaxf(sqrtf(s), MINN);
            float cur2 = pn;
            if (pn > PMAX) { float f = PMAX / pn;
#pragma unroll
                for (int g = 0; g < VO; g++) v[g] *= f;
                cur2 = PMAX; }
            // logmap0 with propagated norm
            float pl = fmaxf(cur2, MINN);
            float a = artanhf_(pl) / pl;
            if (nm < n) {
#pragma unroll
                for (int g = 0; g < VO; g++) xtout[nm * (64 * P) + lane + 32 * g] = v[g] * a;
            }
        }
        __syncwarp();
    }
}

// ---------------- aggregation (CSR gather) + activation chain (norm-propagated) ----------------
__device__ __forceinline__ float n2_4(float4 a) { return a.x * a.x + a.y * a.y + a.z * a.z + a.w * a.w; }
__device__ __forceinline__ void  mul4(float4& a, float s) { a.x *= s; a.y *= s; a.z *= s; a.w *= s; }

__global__ void k_agg128(const float* __restrict__ xt, float* __restrict__ out, int n) {
    int t = threadIdx.x, warp = t >> 5, lane = t & 31;
    const float4* base = (const float4*)xt;
    for (int node = blockIdx.x * WPB + warp; node < n; node += gridDim.x * WPB) {
        float dn = g_dis[node];
        float4 a = base[node * 32 + lane];
        mul4(a, dn * dn);
        int e1 = g_off[node + 1];
        for (int e = g_off[node]; e < e1; e++) {
            int c = g_csr[e];
            float w = dn * g_dis[c];
            float4 v = base[c * 32 + lane];
            a.x += w * v.x; a.y += w * v.y; a.z += w * v.z; a.w += w * v.w;
        }
        // expmap0 (wred 1)
        float s = wred(n2_4(a));
        float nn = fmaxf(sqrtf(s), MINN);
        float tv = tfast(nn);
        mul4(a, tv / nn);
        float cur = tv;
        // proj (propagated)
        if (cur > PMAX) { mul4(a, PMAX / cur); cur = PMAX; }
        // logmap0 (propagated)
        float pl = fmaxf(cur, MINN);
        mul4(a, artanhf_(pl) / pl);
        // leaky relu
        a.x = (a.x >= 0.f) ? a.x : SLOPE * a.x;
        a.y = (a.y >= 0.f) ? a.y : SLOPE * a.y;
        a.z = (a.z >= 0.f) ? a.z : SLOPE * a.z;
        a.w = (a.w >= 0.f) ? a.w : SLOPE * a.w;
        // expmap0 (wred 2 — genuine after nonlinearity)
        s = wred(n2_4(a));
        nn = fmaxf(sqrtf(s), MINN);
        tv = tfast(nn);
        mul4(a, tv / nn);
        cur = tv;
        // proj + outer proj (propagated; second proj is no-op once clipped)
        if (cur > PMAX) { mul4(a, PMAX / cur); }
        ((float4*)out)[node * 32 + lane] = a;
    }
}

__global__ void k_agg64(const float* __restrict__ xt, float* __restrict__ out, int n) {
    int t = threadIdx.x, warp = t >> 5, lane = t & 31;
    const float2* base = (const float2*)xt;
    for (int node = blockIdx.x * WPB + warp; node < n; node += gridDim.x * WPB) {
        float dn = g_dis[node];
        float2 a = base[node * 32 + lane];
        float ws = dn * dn;
        a.x *= ws; a.y *= ws;
        int e1 = g_off[node + 1];
        for (int e = g_off[node]; e < e1; e++) {
            int c = g_csr[e];
            float w = dn * g_dis[c];
            float2 v = base[c * 32 + lane];
            a.x += w * v.x; a.y += w * v.y;
        }
        // expmap0 (wred 1)
        float s = wred(a.x * a.x + a.y * a.y);
        float nn = fmaxf(sqrtf(s), MINN);
        float tv = tfast(nn);
        float sc = tv / nn; a.x *= sc; a.y *= sc;
        float cur = tv;
        // proj (propagated)
        if (cur > PMAX) { sc = PMAX / cur; a.x *= sc; a.y *= sc; cur = PMAX; }
        // logmap0 (propagated)
        float pl = fmaxf(cur, MINN);
        sc = artanhf_(pl) / pl; a.x *= sc; a.y *= sc;
        // leaky
        a.x = (a.x >= 0.f) ? a.x : SLOPE * a.x;
        a.y = (a.y >= 0.f) ? a.y : SLOPE * a.y;
        // expmap0 (wred 2)
        s = wred(a.x * a.x + a.y * a.y);
        nn = fmaxf(sqrtf(s), MINN);
        tv = tfast(nn);
        sc = tv / nn; a.x *= sc; a.y *= sc;
        cur = tv;
        // proj (propagated)
        if (cur > PMAX) { sc = PMAX / cur; a.x *= sc; a.y *= sc; cur = PMAX; }
        // final logmap0 (propagated)
        pl = fmaxf(cur, MINN);
        sc = artanhf_(pl) / pl; a.x *= sc; a.y *= sc;
        ((float2*)out)[node * 32 + lane] = a;
    }
}

// ---------------- HTA window attention (WIN=5 specialized, FFMA2) ----------------
__global__ __launch_bounds__(TPB) void k_att5(const float* __restrict__ hiddens, const float* __restrict__ Q,
                                              const float* __restrict__ ratt, int n) {
    __shared__ ulonglong2 wq[32 * 32];    // 16KB
    __shared__ ull sxs[WPB * 5 * 64];     // 20KB
    __shared__ float shr[64];
    int t = threadIdx.x;
    for (int idx = t; idx < 32 * 32; idx += TPB) {
        int k2 = idx >> 5, j = idx & 31;
        float4 v;
        v.x = Q[(2 * k2) * 64 + j];
        v.y = Q[(2 * k2) * 64 + j + 32];
        v.z = Q[(2 * k2 + 1) * 64 + j];
        v.w = Q[(2 * k2 + 1) * 64 + j + 32];
        ((float4*)wq)[idx] = v;
    }
    if (t < 64) shr[t] = ratt[t];
    __syncthreads();
    int warp = t >> 5, lane = t & 31;
    ull* sxw = sxs + warp * 5 * 64;
    const ulonglong2* sxu = (const ulonglong2*)sxw;
    const float inv5 = 0.2f;
    for (int node = blockIdx.x * WPB + warp; node < n; node += gridDim.x * WPB) {
        float hl0[5], hl1[5], ew[5];
#pragma unroll
        for (int w = 0; w < 5; w++) {
            size_t off = ((size_t)w * n + node) * 64;
            float v0 = hiddens[off + lane];
            float v1 = hiddens[off + lane + 32];
            float s = wred(v0 * v0 + v1 * v1);
            float pn = fmaxf(sqrtf(s), MINN);
            float sc = artanhf_(pn) / pn;
            v0 *= sc; v1 *= sc;
            hl0[w] = v0; hl1[w] = v1;
            sxw[w * 64 + lane] = fdup(v0);
            sxw[w * 64 + lane + 32] = fdup(v1);
        }
        __syncwarp();
        ull acc[5] = {0ull, 0ull, 0ull, 0ull, 0ull};
#pragma unroll 4
        for (int k2 = 0; k2 < 32; k2++) {
            ulonglong2 q = wq[k2 * 32 + lane];
#pragma unroll
            for (int w = 0; w < 5; w++) {
                ulonglong2 xd = sxu[w * 32 + k2];
                ffma2(acc[w], q.x, xd.x);
                ffma2(acc[w], q.y, xd.y);
            }
        }
#pragma unroll
        for (int w = 0; w < 5; w++) {
            float2 f = funpack(acc[w]);
            float ep = tfast(f.x) * shr[lane] + tfast(f.y) * shr[lane + 32];
            ew[w] = wred(ep);
        }
        float m = -1e30f;
#pragma unroll
        for (int w = 0; w < 5; w++) m = fmaxf(m, ew[w]);
        float ssum = 0.f;
#pragma unroll
        for (int w = 0; w < 5; w++) { ew[w] = __expf(ew[w] - m); ssum += ew[w]; }
        float inv = inv5 / ssum;
        float o0 = 0.f, o1 = 0.f;
#pragma unroll
        for (int w = 0; w < 5; w++) { o0 += ew[w] * hl0[w]; o1 += ew[w] * hl1[w]; }
        g_hatt[node * 64 + lane]      = o0 * inv;
        g_hatt[node * 64 + lane + 32] = o1 * inv;
        __syncwarp();
    }
}

// generic fallback (win != 5)
__global__ void k_att(const float* __restrict__ hiddens, const float* __restrict__ Q,
                      const float* __restrict__ ratt, int n, int win) {
    __shared__ float shQ[64 * 64];
    __shared__ float shr[64];
    __shared__ float shh[WPB][64];
    int t = threadIdx.x;
    for (int idx = t; idx < 64 * 64; idx += TPB) shQ[idx] = Q[idx];
    if (t < 64) shr[t] = ratt[t];
    __syncthreads();
    int warp = t >> 5, lane = t & 31;
    float invwin = 1.0f / (float)win;
    for (int node = blockIdx.x * WPB + warp; node < n; node += gridDim.x * WPB) {
        float hl0[8], hl1[8], ew[8];
        for (int w = 0; w < win; w++) {
            size_t off = ((size_t)w * n + node) * 64;
            float v0 = hiddens[off + lane];
            float v1 = hiddens[off + lane + 32];
            float s = wred(v0 * v0 + v1 * v1);
            float pn = fmaxf(sqrtf(s), MINN);
            float sc = artanhf_(pn) / pn;
            v0 *= sc; v1 *= sc;
            hl0[w] = v0; hl1[w] = v1;
            shh[warp][lane] = v0; shh[warp][lane + 32] = v1;
            __syncwarp();
            float ep = 0.f;
#pragma unroll
            for (int g = 0; g < 2; g++) {
                int j = lane + 32 * g;
                float a = 0.f;
                for (int k = 0; k < 64; k++) a += shh[warp][k] * shQ[k * 64 + j];
                ep += tfast(a) * shr[j];
            }
            ew[w] = wred(ep);
            __syncwarp();
        }
        float m = -1e30f;
        for (int w = 0; w < win; w++) m = fmaxf(m, ew[w]);
        float ssum = 0.f;
        for (int w = 0; w < win; w++) { ew[w] = __expf(ew[w] - m); ssum += ew[w]; }
        float inv = invwin / ssum;
        float o0 = 0.f, o1 = 0.f;
        for (int w = 0; w < win; w++) { o0 += ew[w] * hl0[w]; o1 += ew[w] * hl1[w]; }
        g_hatt[node * 64 + lane]      = o0 * inv;
        g_hatt[node * 64 + lane + 32] = o1 * inv;
    }
}

// ---------------- GRU (FFMA2, 8-node blocking) + final expmap0/proj ----------------
__global__ __launch_bounds__(TPB) void k_gru2(const float* __restrict__ Wih, const float* __restrict__ Whh,
                                              const float* __restrict__ bih, const float* __restrict__ bhh,
                                              float* __restrict__ outp, int n) {
    extern __shared__ unsigned char smraw[];
    ulonglong2* wqi = (ulonglong2*)smraw;                      // 3*32*32
    ulonglong2* wqh = (ulonglong2*)(smraw + 49152);            // 3*32*32
    ull* sxx = (ull*)(smraw + 98304);                          // WPB*8*64
    ull* sxh = (ull*)(smraw + 131072);                         // WPB*8*64
    float* sbi = (float*)(smraw + 163840);                     // 192
    float* sbh = (float*)(smraw + 164608);                     // 192
    int t = threadIdx.x;
    for (int idx = t; idx < 3 * 32 * 32; idx += TPB) {
        int p = idx >> 10; int r = idx & 1023; int k2 = r >> 5; int j = r & 31;
        float4 vi, vh;
        vi.x = Wih[(p * 64 + j) * 64 + 2 * k2];
        vi.y = Wih[(p * 64 + j + 32) * 64 + 2 * k2];
        vi.z = Wih[(p * 64 + j) * 64 + 2 * k2 + 1];
        vi.w = Wih[(p * 64 + j + 32) * 64 + 2 * k2 + 1];
        vh.x = Whh[(p * 64 + j) * 64 + 2 * k2];
        vh.y = Whh[(p * 64 + j + 32) * 64 + 2 * k2];
        vh.z = Whh[(p * 64 + j) * 64 + 2 * k2 + 1];
        vh.w = Whh[(p * 64 + j + 32) * 64 + 2 * k2 + 1];
        ((float4*)wqi)[idx] = vi;
        ((float4*)wqh)[idx] = vh;
    }
    if (t < 192) { sbi[t] = bih[t]; sbh[t] = bhh[t]; }
    __syncthreads();
    int warp = t >> 5, lane = t & 31;
    ull* sxxw = sxx + warp * 512;
    ull* sxhw = sxh + warp * 512;
    const ulonglong2* sxxu = (const ulonglong2*)sxxw;
    const ulonglong2* sxhu = (const ulonglong2*)sxhw;
    int ngrp = (n + 7) >> 3;
    for (int grp = blockIdx.x * WPB + warp; grp < ngrp; grp += gridDim.x * WPB) {
        int base = grp * 8;
        float h0r[8], h1r[8];
#pragma unroll
        for (int m = 0; m < 8; m++) {
            int nm = min(base + m, n - 1);
            float x0 = g_xtf[nm * 64 + lane], x1 = g_xtf[nm * 64 + lane + 32];
            float h0 = g_hatt[nm * 64 + lane], h1 = g_hatt[nm * 64 + lane + 32];
            sxxw[m * 64 + lane] = fdup(x0);
            sxxw[m * 64 + lane + 32] = fdup(x1);
            sxhw[m * 64 + lane] = fdup(h0);
            sxhw[m * 64 + lane + 32] = fdup(h1);
            h0r[m] = h0; h1r[m] = h1;
        }
        __syncwarp();
        ull gi[8][3], gh[8][3];
#pragma unroll
        for (int m = 0; m < 8; m++)
#pragma unroll
            for (int p = 0; p < 3; p++) { gi[m][p] = 0ull; gh[m][p] = 0ull; }
#pragma unroll 1
        for (int k2 = 0; k2 < 32; k2++) {
            ulonglong2 qi[3], qh[3];
#pragma unroll
            for (int p = 0; p < 3; p++) {
                qi[p] = wqi[p * 1024 + k2 * 32 + lane];
                qh[p] = wqh[p * 1024 + k2 * 32 + lane];
            }
#pragma unroll
            for (int m = 0; m < 8; m++) {
                ulonglong2 xd = sxxu[m * 32 + k2];
                ulonglong2 hd = sxhu[m * 32 + k2];
#pragma unroll
                for (int p = 0; p < 3; p++) {
                    ffma2(gi[m][p], qi[p].x, xd.x);
                    ffma2(gi[m][p], qi[p].y, xd.y);
                    ffma2(gh[m][p], qh[p].x, hd.x);
                    ffma2(gh[m][p], qh[p].y, hd.y);
                }
            }
        }
#pragma unroll
        for (int m = 0; m < 8; m++) {
            int nm = base + m;
            float2 i0 = funpack(gi[m][0]), i1 = funpack(gi[m][1]), i2 = funpack(gi[m][2]);
            float2 hh0 = funpack(gh[m][0]), hh1 = funpack(gh[m][1]), hh2 = funpack(gh[m][2]);
            float ir0 = i0.x + sbi[lane],        ir1 = i0.y + sbi[lane + 32];
            float iz0 = i1.x + sbi[lane + 64],   iz1 = i1.y + sbi[lane + 96];
            float in0 = i2.x + sbi[lane + 128],  in1 = i2.y + sbi[lane + 160];
            float hr0 = hh0.x + sbh[lane],       hr1 = hh0.y + sbh[lane + 32];
            float hz0 = hh1.x + sbh[lane + 64],  hz1 = hh1.y + sbh[lane + 96];
            float hn0 = hh2.x + sbh[lane + 128], hn1 = hh2.y + sbh[lane + 160];
            float r0 = sigf(ir0 + hr0), r1 = sigf(ir1 + hr1);
            float z0 = sigf(iz0 + hz0), z1 = sigf(iz1 + hz1);
            float n0 = tfast(in0 + r0 * hn0), n1 = tfast(in1 + r1 * hn1);
            float o0 = (1.f - z0) * n0 + z0 * h0r[m];
            float o1 = (1.f - z1) * n1 + z1 * h1r[m];
            // expmap0 (wred genuine) + proj via propagated norm
            float s = wred(o0 * o0 + o1 * o1);
            float nn = fmaxf(sqrtf(s), MINN);
            float tv = tfast(nn);
            float sc = tv / nn; o0 *= sc; o1 *= sc;
            if (tv > PMAX) { sc = PMAX / tv; o0 *= sc; o1 *= sc; }
            if (nm < n) {
                outp[nm * 64 + lane]      = o0;
                outp[nm * 64 + lane + 32] = o1;
            }
        }
        __syncwarp();
    }
}

// ---------------- launch ----------------
extern "C" void kernel_launch(void* const* d_in, const int* in_sizes, int n_in,
                              void* d_out, int out_size) {
    const int*   eidx = (const int*)  d_in[0];
    const float* feat = (const float*)d_in[1];
    const float* Wl   = (const float*)d_in[2];
    const float* bl   = (const float*)d_in[3];
    const float* W1   = (const float*)d_in[4];
    const float* b1   = (const float*)d_in[5];
    const float* W2   = (const float*)d_in[6];
    const float* b2   = (const float*)d_in[7];
    const float* Q    = (const float*)d_in[8];
    const float* ratt = (const float*)d_in[9];
    const float* Wih  = (const float*)d_in[10];
    const float* Whh  = (const float*)d_in[11];
    const float* bih  = (const float*)d_in[12];
    const float* bhh  = (const float*)d_in[13];
    const float* hidd = (const float*)d_in[14];
    float* outp = (float*)d_out;

    int E = in_sizes[0] / 2;
    int N = in_sizes[1] / 128;
    int WIN = in_sizes[14] / (N * 64);
    if (N > NMAX || E > EMAX) return;
    const int* src = eidx;
    const int* dst = eidx + E;

    float *p_xcat, *p_xt, *p_x2, *p_xtf, *p_hb1, *p_hb2;
    cudaGetSymbolAddress((void**)&p_xcat, g_xcat);
    cudaGetSymbolAddress((void**)&p_xt,   g_xt);
    cudaGetSymbolAddress((void**)&p_x2,   g_x2);
    cudaGetSymbolAddress((void**)&p_xtf,  g_xtf);
    cudaGetSymbolAddress((void**)&p_hb1,  g_hb1);
    cudaGetSymbolAddress((void**)&p_hb2,  g_hb2);

    // side streams + fork/join events (created once on first, non-capture call)
    static cudaStream_t s_att = nullptr, s_csr = nullptr;
    static cudaEvent_t  ev_fork = nullptr, ev_join = nullptr, ev_csr = nullptr;
    if (s_att == nullptr) {
        cudaStreamCreateWithFlags(&s_att, cudaStreamNonBlocking);
        cudaStreamCreateWithFlags(&s_csr, cudaStreamNonBlocking);
        cudaEventCreateWithFlags(&ev_fork, cudaEventDisableTiming);
        cudaEventCreateWithFlags(&ev_join, cudaEventDisableTiming);
        cudaEventCreateWithFlags(&ev_csr,  cudaEventDisableTiming);
    }

    const int SMI  = 64 * 32 * 16 + WPBL * 4 * 128 * 8 + 64 * 4;            // 98560
    const int SML1 = 2 * 64 * 32 * 16 + WPBL * 4 * 32 * 16 + 128 * 4;       // 98816
    const int SML2 = 64 * 32 * 16 + WPBL * 4 * 32 * 16 + 64 * 4;            // 65792
    const int SMG  = 2 * 49152 + 2 * WPB * 8 * 64 * 8 + 2 * 192 * 4;        // 165376
    cudaFuncSetAttribute(k_init2,   cudaFuncAttributeMaxDynamicSharedMemorySize, SMI);
    cudaFuncSetAttribute(k_lin<2>,  cudaFuncAttributeMaxDynamicSharedMemorySize, SML1);
    cudaFuncSetAttribute(k_lin<1>,  cudaFuncAttributeMaxDynamicSharedMemorySize, SML2);
    cudaFuncSetAttribute(k_gru2,    cudaFuncAttributeMaxDynamicSharedMemorySize, SMG);

    int eb = (E + 255) / 256;
    int nb = (N + 255) / 256;
    int NB = (N + 1023) / 1024;

    // fork both side branches off the origin stream
    cudaEventRecord(ev_fork, 0);

    // attention branch (depends only on inputs; feeds only gru)
    cudaStreamWaitEvent(s_att, ev_fork, 0);
    if (WIN == 5) k_att5<<<592, TPB, 0, s_att>>>(hidd, Q, ratt, N);
    else          k_att<<<1184, TPB, 0, s_att>>>(hidd, Q, ratt, N, WIN);
    cudaEventRecord(ev_join, s_att);

    // CSR branch (depends only on edge_index; feeds agg128/agg64)
    cudaStreamWaitEvent(s_csr, ev_fork, 0);
    k_zero2<<<nb, 256, 0, s_csr>>>(N);
    k_count<<<eb, 256, 0, s_csr>>>(src, E);
    k_scan1<<<NB, 1024, 0, s_csr>>>(N);
    k_scan2<<<1, 128, 0, s_csr>>>(NB);
    k_scan3<<<nb, 256, 0, s_csr>>>(N, E);
    k_dis<<<nb, 256, 0, s_csr>>>(N);
    k_fill<<<eb, 256, 0, s_csr>>>(src, dst, E);
    cudaEventRecord(ev_csr, s_csr);

    // main chain
    k_bias<<<1, 128>>>(b1, b2);
    k_init2<<<296, TPBL, SMI>>>(feat, Wl, bl, hidd + (size_t)(WIN - 1) * N * 64, N);
    k_lin<2><<<296, TPBL, SML1>>>(p_xcat, W1, p_hb1, p_xt, N);
    cudaStreamWaitEvent(0, ev_csr, 0);
    k_agg128<<<1184, TPB>>>(p_xt, p_x2, N);
    k_lin<1><<<296, TPBL, SML2>>>(p_x2, W2, p_hb2, p_xt, N);
    k_agg64<<<1184, TPB>>>(p_xt, p_xtf, N);

    // join: gru needs g_hatt from attention branch
    cudaStreamWaitEvent(0, ev_join, 0);
    k_gru2<<<148, TPB, SMG>>>(Wih, Whh, bih, bhh, outp, N);
}